// round 2
// baseline (speedup 1.0000x reference)
#include <cuda_runtime.h>
#include <math.h>

#define HEADS   8
#define DH      64
#define DIM     512
#define NSEQ    2048
#define NB      4
#define MROWS   (NB*NSEQ)          // 8192
#define QSCALE  0.125f             // dh^-0.5

// -------- scratch (device globals; no allocation allowed) --------
__device__ float g_q[NB*HEADS*NSEQ*DH];     // [b,h,n,d]
__device__ float g_k[NB*HEADS*NSEQ*DH];
__device__ float g_v[NB*HEADS*NSEQ*DH];
__device__ float g_ao[MROWS*DIM];           // attn out, rows = b*2048+n
__device__ float g_y[MROWS*DIM];            // out-proj result pre-LN
__device__ float g_cos[NB*NSEQ*DH];
__device__ float g_sin[NB*NSEQ*DH];

// ============================================================
// Kernel 0: precompute cos/sin of rope freqs (524288 elems)
// ============================================================
__global__ void rope_table_kernel(const float* __restrict__ rope)
{
    int i = blockIdx.x * blockDim.x + threadIdx.x;
    int total = NB*NSEQ*DH;
    if (i < total) {
        float f = rope[i];
        g_cos[i] = cosf(f);
        g_sin[i] = sinf(f);
    }
}

// ============================================================
// Kernel 1: QKV projection + RoPE (+ q scale)
// C[m, col] = sum_k x[m,k] * W[col,k]
// grid: (128, 24)   by: mat = by/8 (0=q,1=k,2=v), col0 = (by%8)*64
// block: 256 (16x16 threads, 4x4 microtile)
// ============================================================
__global__ void qkv_rope_kernel(const float* __restrict__ x,
                                const float* __restrict__ Wq,
                                const float* __restrict__ Wk,
                                const float* __restrict__ Wv)
{
    __shared__ __align__(16) float As[64*64];   // [k][row]
    __shared__ __align__(16) float Bs[64*64];   // [k][col]
    const int tid = threadIdx.x;
    const int tx = tid & 15, ty = tid >> 4;
    const int m0   = blockIdx.x * 64;
    const int by   = blockIdx.y;
    const int mat  = by >> 3;
    const int col0 = (by & 7) * 64;
    const float* W = (mat == 0) ? Wq : ((mat == 1) ? Wk : Wv);

    const int lrow = tid >> 4;          // 0..15
    const int lk4  = (tid & 15) * 4;    // 0..60

    float c[4][4];
    #pragma unroll
    for (int i = 0; i < 4; i++)
        #pragma unroll
        for (int j = 0; j < 4; j++) c[i][j] = 0.f;

    for (int kk = 0; kk < DIM; kk += 64) {
        #pragma unroll
        for (int p = 0; p < 4; p++) {
            int r = lrow + p*16;
            // A: x logical row m = b*2048+n -> physical row n*4+b
            int m = m0 + r;
            int n = m & 2047, b = m >> 11;
            float4 a4 = *(const float4*)(x + (n*NB + b)*DIM + kk + lk4);
            As[(lk4+0)*64 + r] = a4.x;
            As[(lk4+1)*64 + r] = a4.y;
            As[(lk4+2)*64 + r] = a4.z;
            As[(lk4+3)*64 + r] = a4.w;
            // B: W[col0+r][kk+lk4..]
            float4 b4 = *(const float4*)(W + (col0 + r)*DIM + kk + lk4);
            Bs[(lk4+0)*64 + r] = b4.x;
            Bs[(lk4+1)*64 + r] = b4.y;
            Bs[(lk4+2)*64 + r] = b4.z;
            Bs[(lk4+3)*64 + r] = b4.w;
        }
        __syncthreads();
        const float4* As4 = (const float4*)As;
        const float4* Bs4 = (const float4*)Bs;
        #pragma unroll
        for (int k = 0; k < 64; k++) {
            float4 a = As4[k*16 + ty];
            float4 b = Bs4[k*16 + tx];
            float av[4] = {a.x, a.y, a.z, a.w};
            float bv[4] = {b.x, b.y, b.z, b.w};
            #pragma unroll
            for (int i = 0; i < 4; i++)
                #pragma unroll
                for (int j = 0; j < 4; j++)
                    c[i][j] = fmaf(av[i], bv[j], c[i][j]);
        }
        __syncthreads();
    }

    // store (with rope for q/k)
    const int h  = col0 >> 6;        // head index (col0 is a multiple of 64)
    const int d0 = tx * 4;           // within-head dim, pairs intact
    #pragma unroll
    for (int i = 0; i < 4; i++) {
        int m = m0 + ty*4 + i;
        int n = m & 2047, b = m >> 11;
        if (mat < 2) {
            int fo = (b*NSEQ + n)*DH + d0;
            float c0 = g_cos[fo+0], c1 = g_cos[fo+1], c2 = g_cos[fo+2], c3 = g_cos[fo+3];
            float s0 = g_sin[fo+0], s1 = g_sin[fo+1], s2 = g_sin[fo+2], s3 = g_sin[fo+3];
            float t0 = c[i][0], t1 = c[i][1], t2 = c[i][2], t3 = c[i][3];
            float o0 = t0*c0 - t1*s0;
            float o1 = t1*c1 + t0*s1;
            float o2 = t2*c2 - t3*s2;
            float o3 = t3*c3 + t2*s3;
            if (mat == 0) { o0 *= QSCALE; o1 *= QSCALE; o2 *= QSCALE; o3 *= QSCALE; }
            float* dst = ((mat == 0) ? g_q : g_k) + ((b*HEADS + h)*NSEQ + n)*DH + d0;
            dst[0] = o0; dst[1] = o1; dst[2] = o2; dst[3] = o3;
        } else {
            float* dst = g_v + ((b*HEADS + h)*NSEQ + n)*DH + d0;
            dst[0] = c[i][0]; dst[1] = c[i][1]; dst[2] = c[i][2]; dst[3] = c[i][3];
        }
    }
}

// ============================================================
// Kernel 2: causal flash attention, fp32
// grid: (32 qtiles, 32 bh), block 256, dyn smem 64KB
// ============================================================
__global__ void attn_kernel(const float* __restrict__ head_scale)
{
    extern __shared__ __align__(16) float sm[];
    float* Qs = sm;           // [d][i]  64x64
    float* Ks = sm + 4096;    // [d][j]
    float* Vs = sm + 8192;    // [j][d]
    float* Ps = sm + 12288;   // [j][i]

    const int tid = threadIdx.x;
    const int tx = tid & 15, ty = tid >> 4;
    const int qt = blockIdx.x;
    const int bh = blockIdx.y;
    const int q0 = qt * 64;
    const float* qb = g_q + bh*NSEQ*DH;
    const float* kb = g_k + bh*NSEQ*DH;
    const float* vb = g_v + bh*NSEQ*DH;

    const int lrow = tid >> 4;
    const int ld4  = (tid & 15) * 4;

    // load Q transposed
    #pragma unroll
    for (int p = 0; p < 4; p++) {
        int r = lrow + p*16;
        float4 v4 = *(const float4*)(qb + (q0 + r)*DH + ld4);
        Qs[(ld4+0)*64 + r] = v4.x;
        Qs[(ld4+1)*64 + r] = v4.y;
        Qs[(ld4+2)*64 + r] = v4.z;
        Qs[(ld4+3)*64 + r] = v4.w;
    }

    float m_i[4], l_i[4], o[4][4];
    #pragma unroll
    for (int i = 0; i < 4; i++) {
        m_i[i] = -1e30f; l_i[i] = 0.f;
        #pragma unroll
        for (int j = 0; j < 4; j++) o[i][j] = 0.f;
    }

    const float4* Qs4 = (const float4*)Qs;
    const float4* Ks4 = (const float4*)Ks;
    const float4* Vs4 = (const float4*)Vs;
    const float4* Ps4 = (const float4*)Ps;

    for (int kt = 0; kt <= qt; kt++) {
        int k0 = kt * 64;
        __syncthreads();   // previous iter consumers done with Ks/Vs (also covers Q store on iter 0)
        #pragma unroll
        for (int p = 0; p < 4; p++) {
            int r = lrow + p*16;
            float4 kv = *(const float4*)(kb + (k0 + r)*DH + ld4);
            Ks[(ld4+0)*64 + r] = kv.x;
            Ks[(ld4+1)*64 + r] = kv.y;
            Ks[(ld4+2)*64 + r] = kv.z;
            Ks[(ld4+3)*64 + r] = kv.w;
            *(float4*)(Vs + r*64 + ld4) = *(const float4*)(vb + (k0 + r)*DH + ld4);
        }
        __syncthreads();

        float s[4][4];
        #pragma unroll
        for (int i = 0; i < 4; i++)
            #pragma unroll
            for (int j = 0; j < 4; j++) s[i][j] = 0.f;

        #pragma unroll
        for (int d = 0; d < 64; d++) {
            float4 a = Qs4[d*16 + ty];
            float4 b = Ks4[d*16 + tx];
            float av[4] = {a.x, a.y, a.z, a.w};
            float bv[4] = {b.x, b.y, b.z, b.w};
            #pragma unroll
            for (int i = 0; i < 4; i++)
                #pragma unroll
                for (int j = 0; j < 4; j++)
                    s[i][j] = fmaf(av[i], bv[j], s[i][j]);
        }

        if (kt == qt) {
            #pragma unroll
            for (int i = 0; i < 4; i++) {
                int qi = q0 + ty*4 + i;
                #pragma unroll
                for (int j = 0; j < 4; j++) {
                    int kj = k0 + tx*4 + j;
                    if (kj > qi) s[i][j] = -1e30f;
                }
            }
        }

        float alpha[4];
        #pragma unroll
        for (int i = 0; i < 4; i++) {
            float rm = fmaxf(fmaxf(s[i][0], s[i][1]), fmaxf(s[i][2], s[i][3]));
            #pragma unroll
            for (int off = 8; off > 0; off >>= 1)
                rm = fmaxf(rm, __shfl_xor_sync(0xffffffffu, rm, off));
            float mnew = fmaxf(m_i[i], rm);
            alpha[i] = __expf(m_i[i] - mnew);
            m_i[i] = mnew;
            float rs = 0.f;
            #pragma unroll
            for (int j = 0; j < 4; j++) {
                float p = __expf(s[i][j] - mnew);
                s[i][j] = p;
                rs += p;
            }
            #pragma unroll
            for (int off = 8; off > 0; off >>= 1)
                rs += __shfl_xor_sync(0xffffffffu, rs, off);
            l_i[i] = l_i[i]*alpha[i] + rs;
        }

        // write P transposed [j][i]
        #pragma unroll
        for (int j = 0; j < 4; j++)
            #pragma unroll
            for (int i = 0; i < 4; i++)
                Ps[(tx*4 + j)*64 + ty*4 + i] = s[i][j];

        #pragma unroll
        for (int i = 0; i < 4; i++)
            #pragma unroll
            for (int jd = 0; jd < 4; jd++)
                o[i][jd] *= alpha[i];

        __syncthreads();
        #pragma unroll
        for (int j = 0; j < 64; j++) {
            float4 a = Ps4[j*16 + ty];
            float4 b = Vs4[j*16 + tx];
            float av[4] = {a.x, a.y, a.z, a.w};
            float bv[4] = {b.x, b.y, b.z, b.w};
            #pragma unroll
            for (int i = 0; i < 4; i++)
                #pragma unroll
                for (int jd = 0; jd < 4; jd++)
                    o[i][jd] = fmaf(av[i], bv[jd], o[i][jd]);
        }
    }

    const int b = bh >> 3, h = bh & 7;
    const float hs = head_scale[h];
    #pragma unroll
    for (int i = 0; i < 4; i++) {
        int n = q0 + ty*4 + i;
        float inv = hs / l_i[i];
        float* dst = g_ao + (b*NSEQ + n)*DIM + h*DH + tx*4;
        #pragma unroll
        for (int jd = 0; jd < 4; jd++) dst[jd] = o[i][jd] * inv;
    }
}

// ============================================================
// Kernel 3: output projection  y = ao @ Wo^T + bo
// grid: (128, 8), block 256
// ============================================================
__global__ void outproj_kernel(const float* __restrict__ Wo,
                               const float* __restrict__ bo)
{
    __shared__ __align__(16) float As[64*64];
    __shared__ __align__(16) float Bs[64*64];
    const int tid = threadIdx.x;
    const int tx = tid & 15, ty = tid >> 4;
    const int m0   = blockIdx.x * 64;
    const int col0 = blockIdx.y * 64;
    const int lrow = tid >> 4;
    const int lk4  = (tid & 15) * 4;

    float c[4][4];
    #pragma unroll
    for (int i = 0; i < 4; i++)
        #pragma unroll
        for (int j = 0; j < 4; j++) c[i][j] = 0.f;

    for (int kk = 0; kk < DIM; kk += 64) {
        #pragma unroll
        for (int p = 0; p < 4; p++) {
            int r = lrow + p*16;
            float4 a4 = *(const float4*)(g_ao + (m0 + r)*DIM + kk + lk4);
            As[(lk4+0)*64 + r] = a4.x;
            As[(lk4+1)*64 + r] = a4.y;
            As[(lk4+2)*64 + r] = a4.z;
            As[(lk4+3)*64 + r] = a4.w;
            float4 b4 = *(const float4*)(Wo + (col0 + r)*DIM + kk + lk4);
            Bs[(lk4+0)*64 + r] = b4.x;
            Bs[(lk4+1)*64 + r] = b4.y;
            Bs[(lk4+2)*64 + r] = b4.z;
            Bs[(lk4+3)*64 + r] = b4.w;
        }
        __syncthreads();
        const float4* As4 = (const float4*)As;
        const float4* Bs4 = (const float4*)Bs;
        #pragma unroll
        for (int k = 0; k < 64; k++) {
            float4 a = As4[k*16 + ty];
            float4 b = Bs4[k*16 + tx];
            float av[4] = {a.x, a.y, a.z, a.w};
            float bv[4] = {b.x, b.y, b.z, b.w};
            #pragma unroll
            for (int i = 0; i < 4; i++)
                #pragma unroll
                for (int j = 0; j < 4; j++)
                    c[i][j] = fmaf(av[i], bv[j], c[i][j]);
        }
        __syncthreads();
    }

    #pragma unroll
    for (int i = 0; i < 4; i++) {
        int m = m0 + ty*4 + i;
        float* dst = g_y + m*DIM + col0 + tx*4;
        #pragma unroll
        for (int j = 0; j < 4; j++)
            dst[j] = c[i][j] + bo[col0 + tx*4 + j];
    }
}

// ============================================================
// Kernel 4: LayerNorm + ls_scale + (b,n,d)->(n,b,d) transpose
// grid: 8192 blocks, 128 threads (each thread: 4 contiguous elems)
// ============================================================
__global__ void ln_kernel(const float* __restrict__ ln_g,
                          const float* __restrict__ ln_b,
                          const float* __restrict__ ls,
                          float* __restrict__ out)
{
    __shared__ float red[8];   // 4 warps x {sum, sumsq}
    const int m = blockIdx.x;
    const int b = m >> 11, n = m & 2047;
    const int tid = threadIdx.x;
    float4 v = ((const float4*)(g_y + m*DIM))[tid];
    float s  = v.x + v.y + v.z + v.w;
    float sq = v.x*v.x + v.y*v.y + v.z*v.z + v.w*v.w;
    #pragma unroll
    for (int off = 16; off > 0; off >>= 1) {
        s  += __shfl_xor_sync(0xffffffffu, s,  off);
        sq += __shfl_xor_sync(0xffffffffu, sq, off);
    }
    const int wid = tid >> 5;
    if ((tid & 31) == 0) { red[wid] = s; red[wid + 4] = sq; }
    __syncthreads();
    s  = red[0] + red[1] + red[2] + red[3];
    sq = red[4] + red[5] + red[6] + red[7];
    float mu  = s * (1.f/DIM);
    float var = sq * (1.f/DIM) - mu*mu;
    float r   = rsqrtf(var + 1e-5f);

    float* dst = out + (n*NB + b)*DIM;
    const int d0 = tid * 4;
    float vv[4] = {v.x, v.y, v.z, v.w};
    #pragma unroll
    for (int q = 0; q < 4; q++) {
        int d = d0 + q;
        dst[d] = ls[d] * ((vv[q] - mu) * r * ln_g[d] + ln_b[d]);
    }
}

// ============================================================
extern "C" void kernel_launch(void* const* d_in, const int* in_sizes, int n_in,
                              void* d_out, int out_size)
{
    const float* x    = (const float*)d_in[0];
    const float* rope = (const float*)d_in[1];
    const float* Wq   = (const float*)d_in[2];
    const float* Wk   = (const float*)d_in[3];
    const float* Wv   = (const float*)d_in[4];
    const float* Wo   = (const float*)d_in[5];
    const float* bo   = (const float*)d_in[6];
    const float* ln_g = (const float*)d_in[7];
    const float* ln_b = (const float*)d_in[8];
    const float* hsc  = (const float*)d_in[9];
    const float* ls   = (const float*)d_in[10];
    float* out = (float*)d_out;

    rope_table_kernel<<<(NB*NSEQ*DH + 255)/256, 256>>>(rope);
    qkv_rope_kernel<<<dim3(MROWS/64, 24), 256>>>(x, Wq, Wk, Wv);

    cudaFuncSetAttribute(attn_kernel, cudaFuncAttributeMaxDynamicSharedMemorySize, 65536);
    attn_kernel<<<dim3(NSEQ/64, NB*HEADS), 256, 65536>>>(hsc);

    outproj_kernel<<<dim3(MROWS/64, DIM/64), 256>>>(Wo, bo);
    ln_kernel<<<MROWS, 128>>>(ln_g, ln_b, ls, out);
}

// round 5
// speedup vs baseline: 1.6270x; 1.6270x over previous
#include <cuda_runtime.h>
#include <cuda_bf16.h>
#include <cstdint>
#include <math.h>

#define HEADS   8
#define DH      64
#define DIM     512
#define NSEQ    2048
#define NB      4
#define MROWS   (NB*NSEQ)          // 8192
#define QSCALE  0.125f             // dh^-0.5
#define ASTRIDE 40                 // padded smem row stride (elems) -> conflict-free frags

// -------- scratch (device globals; no allocation allowed) --------
__device__ float g_q[NB*HEADS*NSEQ*DH];     // [b,h,n,d]
__device__ float g_k[NB*HEADS*NSEQ*DH];
__device__ float g_v[NB*HEADS*NSEQ*DH];
__device__ float g_ao[MROWS*DIM];           // attn out, rows = b*2048+n
__device__ float g_y[MROWS*DIM];            // out-proj result pre-LN
__device__ float g_cos[NB*NSEQ*DH];
__device__ float g_sin[NB*NSEQ*DH];

// ============================================================
// mma.sync helpers (plain PTX, works on non-'a' target)
// ============================================================
__device__ __forceinline__ void mma16816(float* c, const uint32_t* a, const uint32_t* b) {
    asm volatile(
        "mma.sync.aligned.m16n8k16.row.col.f32.bf16.bf16.f32 "
        "{%0,%1,%2,%3}, {%4,%5,%6,%7}, {%8,%9}, {%0,%1,%2,%3};"
        : "+f"(c[0]), "+f"(c[1]), "+f"(c[2]), "+f"(c[3])
        : "r"(a[0]), "r"(a[1]), "r"(a[2]), "r"(a[3]), "r"(b[0]), "r"(b[1]));
}

// pack float4 -> hi bf16x4 + lo (residual) bf16x4
__device__ __forceinline__ void split4(float4 v, uint2& h, uint2& l) {
    __nv_bfloat162 ha = __floats2bfloat162_rn(v.x, v.y);
    __nv_bfloat162 hb = __floats2bfloat162_rn(v.z, v.w);
    float rx = v.x - __bfloat162float(ha.x);
    float ry = v.y - __bfloat162float(ha.y);
    float rz = v.z - __bfloat162float(hb.x);
    float rw = v.w - __bfloat162float(hb.y);
    __nv_bfloat162 la = __floats2bfloat162_rn(rx, ry);
    __nv_bfloat162 lb = __floats2bfloat162_rn(rz, rw);
    h.x = *(uint32_t*)&ha; h.y = *(uint32_t*)&hb;
    l.x = *(uint32_t*)&la; l.y = *(uint32_t*)&lb;
}

// ============================================================
// Kernel 0: precompute cos/sin of rope freqs
// ============================================================
__global__ void rope_table_kernel(const float* __restrict__ rope)
{
    int i = blockIdx.x * blockDim.x + threadIdx.x;
    if (i < NB*NSEQ*DH) {
        float f = rope[i];
        g_cos[i] = cosf(f);
        g_sin[i] = sinf(f);
    }
}

// ============================================================
// Kernel 1: QKV projection via mma.sync bf16 3-term split + RoPE epilogue
// grid: (64, 12)  by: mat=by>>2 (0=q,1=k,2=v), col0=(by&3)*128
// block: 256 (8 warps; warp grid 2x4 -> warp tile 64x32)
// ============================================================
__global__ void __launch_bounds__(256) qkv_mma(const float* __restrict__ x,
                                               const float* __restrict__ Wq,
                                               const float* __restrict__ Wk,
                                               const float* __restrict__ Wv)
{
    __shared__ __align__(16) __nv_bfloat16 Ah[128*ASTRIDE];
    __shared__ __align__(16) __nv_bfloat16 Al[128*ASTRIDE];
    __shared__ __align__(16) __nv_bfloat16 Bh[128*ASTRIDE];
    __shared__ __align__(16) __nv_bfloat16 Bl[128*ASTRIDE];

    const int tid = threadIdx.x, lid = tid & 31, wid = tid >> 5;
    const int wm = wid >> 2, wn = wid & 3;           // warp coords
    const int m0   = blockIdx.x * 128;
    const int by   = blockIdx.y;
    const int mat  = by >> 2;
    const int col0 = (by & 3) * 128;
    const float* W = (mat == 0) ? Wq : ((mat == 1) ? Wk : Wv);

    const int g  = lid >> 2;                          // group id 0..7
    const int t2 = (lid & 3) * 2;                     // 0,2,4,6

    float c[4][4][4];
    #pragma unroll
    for (int i = 0; i < 4; i++)
        #pragma unroll
        for (int j = 0; j < 4; j++)
            #pragma unroll
            for (int q = 0; q < 4; q++) c[i][j][q] = 0.f;

    const int lrow = tid >> 3;        // 0..31
    const int f4   = tid & 7;         // float4 index in 32-col chunk

    for (int kc = 0; kc < 16; kc++) {
        const int kk = kc * 32;
        // ---- load A (x) tile 128x32 + B (W) tile 128x32, split hi/lo ----
        #pragma unroll
        for (int p = 0; p < 4; p++) {
            int row = p*32 + lrow;
            int m = m0 + row, n = m & 2047, b = m >> 11;
            float4 v = *(const float4*)(x + (size_t)(n*NB + b)*DIM + kk + f4*4);
            uint2 h, l; split4(v, h, l);
            *(uint2*)&Ah[row*ASTRIDE + f4*4] = h;
            *(uint2*)&Al[row*ASTRIDE + f4*4] = l;
            float4 w = *(const float4*)(W + (size_t)(col0 + row)*DIM + kk + f4*4);
            split4(w, h, l);
            *(uint2*)&Bh[row*ASTRIDE + f4*4] = h;
            *(uint2*)&Bl[row*ASTRIDE + f4*4] = l;
        }
        __syncthreads();

        #pragma unroll
        for (int ks = 0; ks < 2; ks++) {
            const int kb = ks*16 + t2;
            uint32_t bh[4][2], bl[4][2];
            #pragma unroll
            for (int nt = 0; nt < 4; nt++) {
                int nr = wn*32 + nt*8 + g;
                bh[nt][0] = *(const uint32_t*)&Bh[nr*ASTRIDE + kb];
                bh[nt][1] = *(const uint32_t*)&Bh[nr*ASTRIDE + kb + 8];
                bl[nt][0] = *(const uint32_t*)&Bl[nr*ASTRIDE + kb];
                bl[nt][1] = *(const uint32_t*)&Bl[nr*ASTRIDE + kb + 8];
            }
            #pragma unroll
            for (int mt = 0; mt < 4; mt++) {
                int ar = wm*64 + mt*16 + g;
                uint32_t ah[4], al[4];
                ah[0] = *(const uint32_t*)&Ah[ar*ASTRIDE + kb];
                ah[1] = *(const uint32_t*)&Ah[(ar+8)*ASTRIDE + kb];
                ah[2] = *(const uint32_t*)&Ah[ar*ASTRIDE + kb + 8];
                ah[3] = *(const uint32_t*)&Ah[(ar+8)*ASTRIDE + kb + 8];
                al[0] = *(const uint32_t*)&Al[ar*ASTRIDE + kb];
                al[1] = *(const uint32_t*)&Al[(ar+8)*ASTRIDE + kb];
                al[2] = *(const uint32_t*)&Al[ar*ASTRIDE + kb + 8];
                al[3] = *(const uint32_t*)&Al[(ar+8)*ASTRIDE + kb + 8];
                #pragma unroll
                for (int nt = 0; nt < 4; nt++) {
                    mma16816(c[mt][nt], ah, bh[nt]);
                    mma16816(c[mt][nt], ah, bl[nt]);
                    mma16816(c[mt][nt], al, bh[nt]);
                }
            }
        }
        __syncthreads();
    }

    // ---- epilogue: RoPE (+qscale) and scatter to [b,h,n,d] ----
    #pragma unroll
    for (int mt = 0; mt < 4; mt++) {
        #pragma unroll
        for (int half = 0; half < 2; half++) {
            int m = m0 + wm*64 + mt*16 + g + half*8;
            int n = m & 2047, b = m >> 11;
            #pragma unroll
            for (int nt = 0; nt < 4; nt++) {
                int gc = col0 + wn*32 + nt*8 + t2;   // even col
                int h = gc >> 6, d = gc & 63;
                float v0 = c[mt][nt][half*2 + 0];
                float v1 = c[mt][nt][half*2 + 1];
                if (mat < 2) {
                    size_t fo = ((size_t)(b*NSEQ + n))*DH + d;
                    float co0 = g_cos[fo], co1 = g_cos[fo+1];
                    float si0 = g_sin[fo], si1 = g_sin[fo+1];
                    float o0 = v0*co0 - v1*si0;
                    float o1 = v1*co1 + v0*si1;
                    if (mat == 0) { o0 *= QSCALE; o1 *= QSCALE; }
                    float* dst = ((mat == 0) ? g_q : g_k) +
                                 (((size_t)(b*HEADS + h))*NSEQ + n)*DH + d;
                    dst[0] = o0; dst[1] = o1;
                } else {
                    float* dst = g_v + (((size_t)(b*HEADS + h))*NSEQ + n)*DH + d;
                    dst[0] = v0; dst[1] = v1;
                }
            }
        }
    }
}

// ============================================================
// Kernel 3: output projection via mma.sync bf16 3-term split (+bias)
// grid: (64, 4), block 256
// ============================================================
__global__ void __launch_bounds__(256) outproj_mma(const float* __restrict__ Wo,
                                                   const float* __restrict__ bo)
{
    __shared__ __align__(16) __nv_bfloat16 Ah[128*ASTRIDE];
    __shared__ __align__(16) __nv_bfloat16 Al[128*ASTRIDE];
    __shared__ __align__(16) __nv_bfloat16 Bh[128*ASTRIDE];
    __shared__ __align__(16) __nv_bfloat16 Bl[128*ASTRIDE];

    const int tid = threadIdx.x, lid = tid & 31, wid = tid >> 5;
    const int wm = wid >> 2, wn = wid & 3;
    const int m0   = blockIdx.x * 128;
    const int col0 = blockIdx.y * 128;
    const int g  = lid >> 2;
    const int t2 = (lid & 3) * 2;

    float c[4][4][4];
    #pragma unroll
    for (int i = 0; i < 4; i++)
        #pragma unroll
        for (int j = 0; j < 4; j++)
            #pragma unroll
            for (int q = 0; q < 4; q++) c[i][j][q] = 0.f;

    const int lrow = tid >> 3;
    const int f4   = tid & 7;

    for (int kc = 0; kc < 16; kc++) {
        const int kk = kc * 32;
        #pragma unroll
        for (int p = 0; p < 4; p++) {
            int row = p*32 + lrow;
            float4 v = *(const float4*)(g_ao + (size_t)(m0 + row)*DIM + kk + f4*4);
            uint2 h, l; split4(v, h, l);
            *(uint2*)&Ah[row*ASTRIDE + f4*4] = h;
            *(uint2*)&Al[row*ASTRIDE + f4*4] = l;
            float4 w = *(const float4*)(Wo + (size_t)(col0 + row)*DIM + kk + f4*4);
            split4(w, h, l);
            *(uint2*)&Bh[row*ASTRIDE + f4*4] = h;
            *(uint2*)&Bl[row*ASTRIDE + f4*4] = l;
        }
        __syncthreads();

        #pragma unroll
        for (int ks = 0; ks < 2; ks++) {
            const int kb = ks*16 + t2;
            uint32_t bh[4][2], bl[4][2];
            #pragma unroll
            for (int nt = 0; nt < 4; nt++) {
                int nr = wn*32 + nt*8 + g;
                bh[nt][0] = *(const uint32_t*)&Bh[nr*ASTRIDE + kb];
                bh[nt][1] = *(const uint32_t*)&Bh[nr*ASTRIDE + kb + 8];
                bl[nt][0] = *(const uint32_t*)&Bl[nr*ASTRIDE + kb];
                bl[nt][1] = *(const uint32_t*)&Bl[nr*ASTRIDE + kb + 8];
            }
            #pragma unroll
            for (int mt = 0; mt < 4; mt++) {
                int ar = wm*64 + mt*16 + g;
                uint32_t ah[4], al[4];
                ah[0] = *(const uint32_t*)&Ah[ar*ASTRIDE + kb];
                ah[1] = *(const uint32_t*)&Ah[(ar+8)*ASTRIDE + kb];
                ah[2] = *(const uint32_t*)&Ah[ar*ASTRIDE + kb + 8];
                ah[3] = *(const uint32_t*)&Ah[(ar+8)*ASTRIDE + kb + 8];
                al[0] = *(const uint32_t*)&Al[ar*ASTRIDE + kb];
                al[1] = *(const uint32_t*)&Al[(ar+8)*ASTRIDE + kb];
                al[2] = *(const uint32_t*)&Al[ar*ASTRIDE + kb + 8];
                al[3] = *(const uint32_t*)&Al[(ar+8)*ASTRIDE + kb + 8];
                #pragma unroll
                for (int nt = 0; nt < 4; nt++) {
                    mma16816(c[mt][nt], ah, bh[nt]);
                    mma16816(c[mt][nt], ah, bl[nt]);
                    mma16816(c[mt][nt], al, bh[nt]);
                }
            }
        }
        __syncthreads();
    }

    #pragma unroll
    for (int mt = 0; mt < 4; mt++) {
        #pragma unroll
        for (int half = 0; half < 2; half++) {
            int m = m0 + wm*64 + mt*16 + g + half*8;
            #pragma unroll
            for (int nt = 0; nt < 4; nt++) {
                int gc = col0 + wn*32 + nt*8 + t2;
                float* dst = g_y + (size_t)m*DIM + gc;
                dst[0] = c[mt][nt][half*2 + 0] + __ldg(bo + gc);
                dst[1] = c[mt][nt][half*2 + 1] + __ldg(bo + gc + 1);
            }
        }
    }
}

// ============================================================
// Kernel 2: causal flash attention, fp32 SIMT (unchanged this round)
// grid: (32 qtiles, 32 bh), block 256, dyn smem 64KB
// ============================================================
__global__ void attn_kernel(const float* __restrict__ head_scale)
{
    extern __shared__ __align__(16) float sm[];
    float* Qs = sm;           // [d][i]  64x64
    float* Ks = sm + 4096;    // [d][j]
    float* Vs = sm + 8192;    // [j][d]
    float* Ps = sm + 12288;   // [j][i]

    const int tid = threadIdx.x;
    const int tx = tid & 15, ty = tid >> 4;
    const int qt = blockIdx.x;
    const int bh = blockIdx.y;
    const int q0 = qt * 64;
    const float* qb = g_q + bh*NSEQ*DH;
    const float* kb = g_k + bh*NSEQ*DH;
    const float* vb = g_v + bh*NSEQ*DH;

    const int lrow = tid >> 4;
    const int ld4  = (tid & 15) * 4;

    #pragma unroll
    for (int p = 0; p < 4; p++) {
        int r = lrow + p*16;
        float4 v4 = *(const float4*)(qb + (q0 + r)*DH + ld4);
        Qs[(ld4+0)*64 + r] = v4.x;
        Qs[(ld4+1)*64 + r] = v4.y;
        Qs[(ld4+2)*64 + r] = v4.z;
        Qs[(ld4+3)*64 + r] = v4.w;
    }

    float m_i[4], l_i[4], o[4][4];
    #pragma unroll
    for (int i = 0; i < 4; i++) {
        m_i[i] = -1e30f; l_i[i] = 0.f;
        #pragma unroll
        for (int j = 0; j < 4; j++) o[i][j] = 0.f;
    }

    const float4* Qs4 = (const float4*)Qs;
    const float4* Ks4 = (const float4*)Ks;
    const float4* Vs4 = (const float4*)Vs;
    const float4* Ps4 = (const float4*)Ps;

    for (int kt = 0; kt <= qt; kt++) {
        int k0 = kt * 64;
        __syncthreads();
        #pragma unroll
        for (int p = 0; p < 4; p++) {
            int r = lrow + p*16;
            float4 kv = *(const float4*)(kb + (k0 + r)*DH + ld4);
            Ks[(ld4+0)*64 + r] = kv.x;
            Ks[(ld4+1)*64 + r] = kv.y;
            Ks[(ld4+2)*64 + r] = kv.z;
            Ks[(ld4+3)*64 + r] = kv.w;
            *(float4*)(Vs + r*64 + ld4) = *(const float4*)(vb + (k0 + r)*DH + ld4);
        }
        __syncthreads();

        float s[4][4];
        #pragma unroll
        for (int i = 0; i < 4; i++)
            #pragma unroll
            for (int j = 0; j < 4; j++) s[i][j] = 0.f;

        #pragma unroll
        for (int d = 0; d < 64; d++) {
            float4 a = Qs4[d*16 + ty];
            float4 b = Ks4[d*16 + tx];
            float av[4] = {a.x, a.y, a.z, a.w};
            float bv[4] = {b.x, b.y, b.z, b.w};
            #pragma unroll
            for (int i = 0; i < 4; i++)
                #pragma unroll
                for (int j = 0; j < 4; j++)
                    s[i][j] = fmaf(av[i], bv[j], s[i][j]);
        }

        if (kt == qt) {
            #pragma unroll
            for (int i = 0; i < 4; i++) {
                int qi = q0 + ty*4 + i;
                #pragma unroll
                for (int j = 0; j < 4; j++) {
                    int kj = k0 + tx*4 + j;
                    if (kj > qi) s[i][j] = -1e30f;
                }
            }
        }

        float alpha[4];
        #pragma unroll
        for (int i = 0; i < 4; i++) {
            float rm = fmaxf(fmaxf(s[i][0], s[i][1]), fmaxf(s[i][2], s[i][3]));
            #pragma unroll
            for (int off = 8; off > 0; off >>= 1)
                rm = fmaxf(rm, __shfl_xor_sync(0xffffffffu, rm, off));
            float mnew = fmaxf(m_i[i], rm);
            alpha[i] = __expf(m_i[i] - mnew);
            m_i[i] = mnew;
            float rs = 0.f;
            #pragma unroll
            for (int j = 0; j < 4; j++) {
                float p = __expf(s[i][j] - mnew);
                s[i][j] = p;
                rs += p;
            }
            #pragma unroll
            for (int off = 8; off > 0; off >>= 1)
                rs += __shfl_xor_sync(0xffffffffu, rs, off);
            l_i[i] = l_i[i]*alpha[i] + rs;
        }

        #pragma unroll
        for (int j = 0; j < 4; j++)
            #pragma unroll
            for (int i = 0; i < 4; i++)
                Ps[(tx*4 + j)*64 + ty*4 + i] = s[i][j];

        #pragma unroll
        for (int i = 0; i < 4; i++)
            #pragma unroll
            for (int jd = 0; jd < 4; jd++)
                o[i][jd] *= alpha[i];

        __syncthreads();
        #pragma unroll
        for (int j = 0; j < 64; j++) {
            float4 a = Ps4[j*16 + ty];
            float4 b = Vs4[j*16 + tx];
            float av[4] = {a.x, a.y, a.z, a.w};
            float bv[4] = {b.x, b.y, b.z, b.w};
            #pragma unroll
            for (int i = 0; i < 4; i++)
                #pragma unroll
                for (int jd = 0; jd < 4; jd++)
                    o[i][jd] = fmaf(av[i], bv[jd], o[i][jd]);
        }
    }

    const int b = bh >> 3, h = bh & 7;
    const float hs = head_scale[h];
    #pragma unroll
    for (int i = 0; i < 4; i++) {
        int n = q0 + ty*4 + i;
        float inv = hs / l_i[i];
        float* dst = g_ao + (b*NSEQ + n)*DIM + h*DH + tx*4;
        #pragma unroll
        for (int jd = 0; jd < 4; jd++) dst[jd] = o[i][jd] * inv;
    }
}

// ============================================================
// Kernel 4: LayerNorm + ls_scale + (b,n,d)->(n,b,d) transpose
// ============================================================
__global__ void ln_kernel(const float* __restrict__ ln_g,
                          const float* __restrict__ ln_b,
                          const float* __restrict__ ls,
                          float* __restrict__ out)
{
    __shared__ float red[8];
    const int m = blockIdx.x;
    const int b = m >> 11, n = m & 2047;
    const int tid = threadIdx.x;
    float4 v = ((const float4*)(g_y + (size_t)m*DIM))[tid];
    float s  = v.x + v.y + v.z + v.w;
    float sq = v.x*v.x + v.y*v.y + v.z*v.z + v.w*v.w;
    #pragma unroll
    for (int off = 16; off > 0; off >>= 1) {
        s  += __shfl_xor_sync(0xffffffffu, s,  off);
        sq += __shfl_xor_sync(0xffffffffu, sq, off);
    }
    const int wid = tid >> 5;
    if ((tid & 31) == 0) { red[wid] = s; red[wid + 4] = sq; }
    __syncthreads();
    s  = red[0] + red[1] + red[2] + red[3];
    sq = red[4] + red[5] + red[6] + red[7];
    float mu  = s * (1.f/DIM);
    float var = sq * (1.f/DIM) - mu*mu;
    float r   = rsqrtf(var + 1e-5f);

    float* dst = out + (size_t)(n*NB + b)*DIM;
    const int d0 = tid * 4;
    float vv[4] = {v.x, v.y, v.z, v.w};
    #pragma unroll
    for (int q = 0; q < 4; q++) {
        int d = d0 + q;
        dst[d] = ls[d] * ((vv[q] - mu) * r * ln_g[d] + ln_b[d]);
    }
}

// ============================================================
extern "C" void kernel_launch(void* const* d_in, const int* in_sizes, int n_in,
                              void* d_out, int out_size)
{
    const float* x    = (const float*)d_in[0];
    const float* rope = (const float*)d_in[1];
    const float* Wq   = (const float*)d_in[2];
    const float* Wk   = (const float*)d_in[3];
    const float* Wv   = (const float*)d_in[4];
    const float* Wo   = (const float*)d_in[5];
    const float* bo   = (const float*)d_in[6];
    const float* ln_g = (const float*)d_in[7];
    const float* ln_b = (const float*)d_in[8];
    const float* hsc  = (const float*)d_in[9];
    const float* ls   = (const float*)d_in[10];
    float* out = (float*)d_out;

    cudaFuncSetAttribute(attn_kernel, cudaFuncAttributeMaxDynamicSharedMemorySize, 65536);

    rope_table_kernel<<<(NB*NSEQ*DH + 255)/256, 256>>>(rope);
    qkv_mma<<<dim3(MROWS/128, 12), 256>>>(x, Wq, Wk, Wv);
    attn_kernel<<<dim3(NSEQ/64, NB*HEADS), 256, 65536>>>(hsc);
    outproj_mma<<<dim3(MROWS/128, 4), 256>>>(Wo, bo);
    ln_kernel<<<MROWS, 128>>>(ln_g, ln_b, ls, out);
}

// round 7
// speedup vs baseline: 3.0085x; 1.8491x over previous
#include <cuda_runtime.h>
#include <cuda_bf16.h>
#include <cstdint>
#include <math.h>

#define HEADS   8
#define DH      64
#define DIM     512
#define NSEQ    2048
#define NB      4
#define MROWS   (NB*NSEQ)          // 8192
#define QSCALE  0.125f             // dh^-0.5
#define ASTRIDE 40                 // padded smem row stride (elems) for GEMM tiles
#define KSTR    72                 // padded stride for attention K/V tiles

// -------- scratch (device globals; no allocation allowed) --------
__device__ __nv_bfloat16 g_qh[NB*HEADS*NSEQ*DH];   // [b,h,n,d] hi
__device__ __nv_bfloat16 g_ql[NB*HEADS*NSEQ*DH];   // lo
__device__ __nv_bfloat16 g_kh[NB*HEADS*NSEQ*DH];
__device__ __nv_bfloat16 g_kl[NB*HEADS*NSEQ*DH];
__device__ __nv_bfloat16 g_vth[NB*HEADS*DH*NSEQ];  // [b,h,d,n] (transposed)
__device__ __nv_bfloat16 g_vtl[NB*HEADS*DH*NSEQ];
__device__ __nv_bfloat16 g_aoh[MROWS*DIM];         // attn out hi, rows = b*2048+n
__device__ __nv_bfloat16 g_aol[MROWS*DIM];         // attn out lo
__device__ float g_y[MROWS*DIM];                   // out-proj result pre-LN
__device__ float g_cos[NB*NSEQ*DH];
__device__ float g_sin[NB*NSEQ*DH];

// ============================================================
// mma.sync helpers (plain PTX, works on non-'a' target)
// ============================================================
__device__ __forceinline__ void mma16816(float* c, const uint32_t* a, const uint32_t* b) {
    asm volatile(
        "mma.sync.aligned.m16n8k16.row.col.f32.bf16.bf16.f32 "
        "{%0,%1,%2,%3}, {%4,%5,%6,%7}, {%8,%9}, {%0,%1,%2,%3};"
        : "+f"(c[0]), "+f"(c[1]), "+f"(c[2]), "+f"(c[3])
        : "r"(a[0]), "r"(a[1]), "r"(a[2]), "r"(a[3]), "r"(b[0]), "r"(b[1]));
}

// pack float4 -> hi bf16x4 + lo (residual) bf16x4
__device__ __forceinline__ void split4(float4 v, uint2& h, uint2& l) {
    __nv_bfloat162 ha = __floats2bfloat162_rn(v.x, v.y);
    __nv_bfloat162 hb = __floats2bfloat162_rn(v.z, v.w);
    float rx = v.x - __bfloat162float(ha.x);
    float ry = v.y - __bfloat162float(ha.y);
    float rz = v.z - __bfloat162float(hb.x);
    float rw = v.w - __bfloat162float(hb.y);
    __nv_bfloat162 la = __floats2bfloat162_rn(rx, ry);
    __nv_bfloat162 lb = __floats2bfloat162_rn(rz, rw);
    h.x = *(uint32_t*)&ha; h.y = *(uint32_t*)&hb;
    l.x = *(uint32_t*)&la; l.y = *(uint32_t*)&lb;
}

__device__ __forceinline__ void split2(float a, float b, uint32_t& h, uint32_t& l) {
    __nv_bfloat162 hh = __floats2bfloat162_rn(a, b);
    float ra = a - __bfloat162float(hh.x);
    float rb = b - __bfloat162float(hh.y);
    __nv_bfloat162 ll = __floats2bfloat162_rn(ra, rb);
    h = *(uint32_t*)&hh; l = *(uint32_t*)&ll;
}

// ============================================================
// Kernel 0: precompute cos/sin of rope freqs
// ============================================================
__global__ void rope_table_kernel(const float* __restrict__ rope)
{
    int i = blockIdx.x * blockDim.x + threadIdx.x;
    if (i < NB*NSEQ*DH) {
        float f = rope[i];
        g_cos[i] = cosf(f);
        g_sin[i] = sinf(f);
    }
}

// ============================================================
// Kernel 1: QKV projection via mma.sync bf16 3-term split.
// Epilogue: RoPE (+qscale), split to bf16 hi/lo, scatter:
//   q,k -> [b,h,n,d]; v -> transposed [b,h,d,n]
// grid: (64, 12), block 256 (8 warps, warp tile 64x32)
// ============================================================
__global__ void __launch_bounds__(256) qkv_mma(const float* __restrict__ x,
                                               const float* __restrict__ Wq,
                                               const float* __restrict__ Wk,
                                               const float* __restrict__ Wv)
{
    __shared__ __align__(16) __nv_bfloat16 Ah[128*ASTRIDE];
    __shared__ __align__(16) __nv_bfloat16 Al[128*ASTRIDE];
    __shared__ __align__(16) __nv_bfloat16 Bh[128*ASTRIDE];
    __shared__ __align__(16) __nv_bfloat16 Bl[128*ASTRIDE];

    const int tid = threadIdx.x, lid = tid & 31, wid = tid >> 5;
    const int wm = wid >> 2, wn = wid & 3;
    const int m0   = blockIdx.x * 128;
    const int by   = blockIdx.y;
    const int mat  = by >> 2;
    const int col0 = (by & 3) * 128;
    const float* W = (mat == 0) ? Wq : ((mat == 1) ? Wk : Wv);

    const int g  = lid >> 2;
    const int t2 = (lid & 3) * 2;

    float c[4][4][4];
    #pragma unroll
    for (int i = 0; i < 4; i++)
        #pragma unroll
        for (int j = 0; j < 4; j++)
            #pragma unroll
            for (int q = 0; q < 4; q++) c[i][j][q] = 0.f;

    const int lrow = tid >> 3;
    const int f4   = tid & 7;

    for (int kc = 0; kc < 16; kc++) {
        const int kk = kc * 32;
        #pragma unroll
        for (int p = 0; p < 4; p++) {
            int row = p*32 + lrow;
            int m = m0 + row, n = m & 2047, b = m >> 11;
            float4 v = *(const float4*)(x + (size_t)(n*NB + b)*DIM + kk + f4*4);
            uint2 h, l; split4(v, h, l);
            *(uint2*)&Ah[row*ASTRIDE + f4*4] = h;
            *(uint2*)&Al[row*ASTRIDE + f4*4] = l;
            float4 w = *(const float4*)(W + (size_t)(col0 + row)*DIM + kk + f4*4);
            split4(w, h, l);
            *(uint2*)&Bh[row*ASTRIDE + f4*4] = h;
            *(uint2*)&Bl[row*ASTRIDE + f4*4] = l;
        }
        __syncthreads();

        #pragma unroll
        for (int ks = 0; ks < 2; ks++) {
            const int kb = ks*16 + t2;
            uint32_t bh[4][2], bl[4][2];
            #pragma unroll
            for (int nt = 0; nt < 4; nt++) {
                int nr = wn*32 + nt*8 + g;
                bh[nt][0] = *(const uint32_t*)&Bh[nr*ASTRIDE + kb];
                bh[nt][1] = *(const uint32_t*)&Bh[nr*ASTRIDE + kb + 8];
                bl[nt][0] = *(const uint32_t*)&Bl[nr*ASTRIDE + kb];
                bl[nt][1] = *(const uint32_t*)&Bl[nr*ASTRIDE + kb + 8];
            }
            #pragma unroll
            for (int mt = 0; mt < 4; mt++) {
                int ar = wm*64 + mt*16 + g;
                uint32_t ah[4], al[4];
                ah[0] = *(const uint32_t*)&Ah[ar*ASTRIDE + kb];
                ah[1] = *(const uint32_t*)&Ah[(ar+8)*ASTRIDE + kb];
                ah[2] = *(const uint32_t*)&Ah[ar*ASTRIDE + kb + 8];
                ah[3] = *(const uint32_t*)&Ah[(ar+8)*ASTRIDE + kb + 8];
                al[0] = *(const uint32_t*)&Al[ar*ASTRIDE + kb];
                al[1] = *(const uint32_t*)&Al[(ar+8)*ASTRIDE + kb];
                al[2] = *(const uint32_t*)&Al[ar*ASTRIDE + kb + 8];
                al[3] = *(const uint32_t*)&Al[(ar+8)*ASTRIDE + kb + 8];
                #pragma unroll
                for (int nt = 0; nt < 4; nt++) {
                    mma16816(c[mt][nt], ah, bh[nt]);
                    mma16816(c[mt][nt], ah, bl[nt]);
                    mma16816(c[mt][nt], al, bh[nt]);
                }
            }
        }
        __syncthreads();
    }

    // ---- epilogue ----
    #pragma unroll
    for (int mt = 0; mt < 4; mt++) {
        #pragma unroll
        for (int half = 0; half < 2; half++) {
            int m = m0 + wm*64 + mt*16 + g + half*8;
            int n = m & 2047, b = m >> 11;
            #pragma unroll
            for (int nt = 0; nt < 4; nt++) {
                int gc = col0 + wn*32 + nt*8 + t2;   // even col
                int h = gc >> 6, d = gc & 63;
                float v0 = c[mt][nt][half*2 + 0];
                float v1 = c[mt][nt][half*2 + 1];
                if (mat < 2) {
                    size_t fo = ((size_t)(b*NSEQ + n))*DH + d;
                    float co0 = g_cos[fo], co1 = g_cos[fo+1];
                    float si0 = g_sin[fo], si1 = g_sin[fo+1];
                    float o0 = v0*co0 - v1*si0;
                    float o1 = v1*co1 + v0*si1;
                    if (mat == 0) { o0 *= QSCALE; o1 *= QSCALE; }
                    uint32_t hh, ll; split2(o0, o1, hh, ll);
                    size_t off = (((size_t)(b*HEADS + h))*NSEQ + n)*DH + d;
                    if (mat == 0) {
                        *(uint32_t*)&g_qh[off] = hh;
                        *(uint32_t*)&g_ql[off] = ll;
                    } else {
                        *(uint32_t*)&g_kh[off] = hh;
                        *(uint32_t*)&g_kl[off] = ll;
                    }
                } else {
                    // v: store transposed [b,h,d,n]
                    uint32_t hh, ll; split2(v0, v1, hh, ll);
                    __nv_bfloat162 h2 = *(__nv_bfloat162*)&hh;
                    __nv_bfloat162 l2 = *(__nv_bfloat162*)&ll;
                    size_t base = ((size_t)(b*HEADS + h))*DH*NSEQ;
                    g_vth[base + (size_t)d*NSEQ + n]     = h2.x;
                    g_vth[base + (size_t)(d+1)*NSEQ + n] = h2.y;
                    g_vtl[base + (size_t)d*NSEQ + n]     = l2.x;
                    g_vtl[base + (size_t)(d+1)*NSEQ + n] = l2.y;
                }
            }
        }
    }
}

// ============================================================
// Kernel 2: causal flash attention via mma.sync bf16 3-term split
// grid: (32 qtiles, 32 bh), block 128 (4 warps x 16 q-rows)
// ============================================================
__global__ void __launch_bounds__(128) attn_mma(const float* __restrict__ head_scale)
{
    __shared__ __align__(16) __nv_bfloat16 Ksh[64*KSTR];
    __shared__ __align__(16) __nv_bfloat16 Ksl[64*KSTR];
    __shared__ __align__(16) __nv_bfloat16 Vsh[64*KSTR];   // VT: [d][kpos]
    __shared__ __align__(16) __nv_bfloat16 Vsl[64*KSTR];

    const int tid = threadIdx.x, lid = tid & 31, wid = tid >> 5;
    const int qt = blockIdx.x;
    const int bh = blockIdx.y;
    const int q0 = qt * 64;
    const int g  = lid >> 2;
    const int t2 = (lid & 3) * 2;

    const size_t hb_nd = (size_t)bh * NSEQ * DH;   // base for q/k [n][d]
    const size_t hb_dn = (size_t)bh * DH * NSEQ;   // base for vt [d][n]

    // ---- load Q fragments (rows q0+wid*16 .. +15), hi & lo ----
    uint32_t qh[4][4], ql[4][4];
    {
        const __nv_bfloat16* qhp = g_qh + hb_nd + (size_t)(q0 + wid*16)*DH;
        const __nv_bfloat16* qlp = g_ql + hb_nd + (size_t)(q0 + wid*16)*DH;
        #pragma unroll
        for (int kt = 0; kt < 4; kt++) {
            int kc = kt*16 + t2;
            qh[kt][0] = *(const uint32_t*)&qhp[(size_t)g*DH + kc];
            qh[kt][1] = *(const uint32_t*)&qhp[(size_t)(g+8)*DH + kc];
            qh[kt][2] = *(const uint32_t*)&qhp[(size_t)g*DH + kc + 8];
            qh[kt][3] = *(const uint32_t*)&qhp[(size_t)(g+8)*DH + kc + 8];
            ql[kt][0] = *(const uint32_t*)&qlp[(size_t)g*DH + kc];
            ql[kt][1] = *(const uint32_t*)&qlp[(size_t)(g+8)*DH + kc];
            ql[kt][2] = *(const uint32_t*)&qlp[(size_t)g*DH + kc + 8];
            ql[kt][3] = *(const uint32_t*)&qlp[(size_t)(g+8)*DH + kc + 8];
        }
    }

    float m_i[2] = {-1e30f, -1e30f};
    float l_i[2] = {0.f, 0.f};
    float o[8][4];
    #pragma unroll
    for (int dt = 0; dt < 8; dt++)
        #pragma unroll
        for (int q = 0; q < 4; q++) o[dt][q] = 0.f;

    const int lrow = tid >> 1;        // 0..63
    const int halfc = (tid & 1) * 32; // col offset 0 or 32

    for (int kb = 0; kb <= qt; kb++) {
        const int k0 = kb * 64;
        __syncthreads();
        // ---- stage K tile [kpos][d] and VT tile [d][kpos] ----
        {
            const __nv_bfloat16* kh = g_kh + hb_nd + (size_t)(k0 + lrow)*DH + halfc;
            const __nv_bfloat16* kl = g_kl + hb_nd + (size_t)(k0 + lrow)*DH + halfc;
            const __nv_bfloat16* vh = g_vth + hb_dn + (size_t)lrow*NSEQ + k0 + halfc;
            const __nv_bfloat16* vl = g_vtl + hb_dn + (size_t)lrow*NSEQ + k0 + halfc;
            __nv_bfloat16* dk = &Ksh[lrow*KSTR + halfc];
            __nv_bfloat16* dl = &Ksl[lrow*KSTR + halfc];
            __nv_bfloat16* dvh = &Vsh[lrow*KSTR + halfc];
            __nv_bfloat16* dvl = &Vsl[lrow*KSTR + halfc];
            #pragma unroll
            for (int j = 0; j < 4; j++) {
                *(uint4*)&dk[j*8]  = *(const uint4*)&kh[j*8];
                *(uint4*)&dl[j*8]  = *(const uint4*)&kl[j*8];
                *(uint4*)&dvh[j*8] = *(const uint4*)&vh[j*8];
                *(uint4*)&dvl[j*8] = *(const uint4*)&vl[j*8];
            }
        }
        __syncthreads();

        // ---- S = Q K^T (3-term) ----
        float sc[8][4];
        #pragma unroll
        for (int j = 0; j < 8; j++)
            #pragma unroll
            for (int q = 0; q < 4; q++) sc[j][q] = 0.f;

        #pragma unroll
        for (int j = 0; j < 8; j++) {
            const int nr = j*8 + g;
            #pragma unroll
            for (int kt = 0; kt < 4; kt++) {
                const int kc = kt*16 + t2;
                uint32_t bhf[2], blf[2];
                bhf[0] = *(const uint32_t*)&Ksh[nr*KSTR + kc];
                bhf[1] = *(const uint32_t*)&Ksh[nr*KSTR + kc + 8];
                blf[0] = *(const uint32_t*)&Ksl[nr*KSTR + kc];
                blf[1] = *(const uint32_t*)&Ksl[nr*KSTR + kc + 8];
                mma16816(sc[j], qh[kt], bhf);
                mma16816(sc[j], qh[kt], blf);
                mma16816(sc[j], ql[kt], bhf);
            }
        }

        // ---- causal mask (diagonal block only) ----
        if (kb == qt) {
            const int r0 = q0 + wid*16 + g;
            #pragma unroll
            for (int j = 0; j < 8; j++) {
                int col = k0 + j*8 + t2;
                if (col     > r0)   sc[j][0] = -1e30f;
                if (col + 1 > r0)   sc[j][1] = -1e30f;
                if (col     > r0+8) sc[j][2] = -1e30f;
                if (col + 1 > r0+8) sc[j][3] = -1e30f;
            }
        }

        // ---- online softmax (rows g, g+8) ----
        float alpha[2];
        #pragma unroll
        for (int r = 0; r < 2; r++) {
            float mx = -1e30f;
            #pragma unroll
            for (int j = 0; j < 8; j++)
                mx = fmaxf(mx, fmaxf(sc[j][2*r], sc[j][2*r+1]));
            mx = fmaxf(mx, __shfl_xor_sync(0xffffffffu, mx, 1));
            mx = fmaxf(mx, __shfl_xor_sync(0xffffffffu, mx, 2));
            float mnew = fmaxf(m_i[r], mx);
            alpha[r] = __expf(m_i[r] - mnew);
            m_i[r] = mnew;
            float rs = 0.f;
            #pragma unroll
            for (int j = 0; j < 8; j++) {
                float p0 = __expf(sc[j][2*r]   - mnew);
                float p1 = __expf(sc[j][2*r+1] - mnew);
                sc[j][2*r] = p0; sc[j][2*r+1] = p1;
                rs += p0 + p1;
            }
            rs += __shfl_xor_sync(0xffffffffu, rs, 1);
            rs += __shfl_xor_sync(0xffffffffu, rs, 2);
            l_i[r] = l_i[r]*alpha[r] + rs;
        }

        // ---- rescale O ----
        #pragma unroll
        for (int dt = 0; dt < 8; dt++) {
            o[dt][0] *= alpha[0]; o[dt][1] *= alpha[0];
            o[dt][2] *= alpha[1]; o[dt][3] *= alpha[1];
        }

        // ---- convert P to A-fragments (hi/lo) ----
        uint32_t ph[4][4], pl[4][4];
        #pragma unroll
        for (int kt = 0; kt < 4; kt++) {
            split2(sc[2*kt][0],   sc[2*kt][1],   ph[kt][0], pl[kt][0]);
            split2(sc[2*kt][2],   sc[2*kt][3],   ph[kt][1], pl[kt][1]);
            split2(sc[2*kt+1][0], sc[2*kt+1][1], ph[kt][2], pl[kt][2]);
            split2(sc[2*kt+1][2], sc[2*kt+1][3], ph[kt][3], pl[kt][3]);
        }

        // ---- O += P V (3-term) ----
        #pragma unroll
        for (int dt = 0; dt < 8; dt++) {
            const int nr = dt*8 + g;
            #pragma unroll
            for (int kt = 0; kt < 4; kt++) {
                const int kc = kt*16 + t2;
                uint32_t vhf[2], vlf[2];
                vhf[0] = *(const uint32_t*)&Vsh[nr*KSTR + kc];
                vhf[1] = *(const uint32_t*)&Vsh[nr*KSTR + kc + 8];
                vlf[0] = *(const uint32_t*)&Vsl[nr*KSTR + kc];
                vlf[1] = *(const uint32_t*)&Vsl[nr*KSTR + kc + 8];
                mma16816(o[dt], ph[kt], vhf);
                mma16816(o[dt], ph[kt], vlf);
                mma16816(o[dt], pl[kt], vhf);
            }
        }
    }

    // ---- epilogue: scale by hs/l, split, store to g_aoh/g_aol ----
    const int b = bh >> 3, h = bh & 7;
    const float hs = head_scale[h];
    #pragma unroll
    for (int r = 0; r < 2; r++) {
        const float inv = hs / l_i[r];
        const int n = q0 + wid*16 + g + r*8;
        __nv_bfloat16* dsth = g_aoh + ((size_t)(b*NSEQ + n))*DIM + h*DH;
        __nv_bfloat16* dstl = g_aol + ((size_t)(b*NSEQ + n))*DIM + h*DH;
        #pragma unroll
        for (int dt = 0; dt < 8; dt++) {
            int d = dt*8 + t2;
            uint32_t hh, ll;
            split2(o[dt][2*r]*inv, o[dt][2*r+1]*inv, hh, ll);
            *(uint32_t*)&dsth[d] = hh;
            *(uint32_t*)&dstl[d] = ll;
        }
    }
}

// ============================================================
// Kernel 3: output projection (+bias); A comes pre-split (g_aoh/g_aol)
// grid: (64, 4), block 256
// ============================================================
__global__ void __launch_bounds__(256) outproj_mma(const float* __restrict__ Wo,
                                                   const float* __restrict__ bo)
{
    __shared__ __align__(16) __nv_bfloat16 Ah[128*ASTRIDE];
    __shared__ __align__(16) __nv_bfloat16 Al[128*ASTRIDE];
    __shared__ __align__(16) __nv_bfloat16 Bh[128*ASTRIDE];
    __shared__ __align__(16) __nv_bfloat16 Bl[128*ASTRIDE];

    const int tid = threadIdx.x, lid = tid & 31, wid = tid >> 5;
    const int wm = wid >> 2, wn = wid & 3;
    const int m0   = blockIdx.x * 128;
    const int col0 = blockIdx.y * 128;
    const int g  = lid >> 2;
    const int t2 = (lid & 3) * 2;

    float c[4][4][4];
    #pragma unroll
    for (int i = 0; i < 4; i++)
        #pragma unroll
        for (int j = 0; j < 4; j++)
            #pragma unroll
            for (int q = 0; q < 4; q++) c[i][j][q] = 0.f;

    const int lrow = tid >> 3;
    const int f4   = tid & 7;

    for (int kc = 0; kc < 16; kc++) {
        const int kk = kc * 32;
        #pragma unroll
        for (int p = 0; p < 4; p++) {
            int row = p*32 + lrow;
            size_t aoff = (size_t)(m0 + row)*DIM + kk + f4*4;
            *(uint2*)&Ah[row*ASTRIDE + f4*4] = *(const uint2*)&g_aoh[aoff];
            *(uint2*)&Al[row*ASTRIDE + f4*4] = *(const uint2*)&g_aol[aoff];
            float4 w = *(const float4*)(Wo + (size_t)(col0 + row)*DIM + kk + f4*4);
            uint2 h, l; split4(w, h, l);
            *(uint2*)&Bh[row*ASTRIDE + f4*4] = h;
            *(uint2*)&Bl[row*ASTRIDE + f4*4] = l;
        }
        __syncthreads();

        #pragma unroll
        for (int ks = 0; ks < 2; ks++) {
            const int kb = ks*16 + t2;
            uint32_t bh[4][2], bl[4][2];
            #pragma unroll
            for (int nt = 0; nt < 4; nt++) {
                int nr = wn*32 + nt*8 + g;
                bh[nt][0] = *(const uint32_t*)&Bh[nr*ASTRIDE + kb];
                bh[nt][1] = *(const uint32_t*)&Bh[nr*ASTRIDE + kb + 8];
                bl[nt][0] = *(const uint32_t*)&Bl[nr*ASTRIDE + kb];
                bl[nt][1] = *(const uint32_t*)&Bl[nr*ASTRIDE + kb + 8];
            }
            #pragma unroll
            for (int mt = 0; mt < 4; mt++) {
                int ar = wm*64 + mt*16 + g;
                uint32_t ah[4], al[4];
                ah[0] = *(const uint32_t*)&Ah[ar*ASTRIDE + kb];
                ah[1] = *(const uint32_t*)&Ah[(ar+8)*ASTRIDE + kb];
                ah[2] = *(const uint32_t*)&Ah[ar*ASTRIDE + kb + 8];
                ah[3] = *(const uint32_t*)&Ah[(ar+8)*ASTRIDE + kb + 8];
                al[0] = *(const uint32_t*)&Al[ar*ASTRIDE + kb];
                al[1] = *(const uint32_t*)&Al[(ar+8)*ASTRIDE + kb];
                al[2] = *(const uint32_t*)&Al[ar*ASTRIDE + kb + 8];
                al[3] = *(const uint32_t*)&Al[(ar+8)*ASTRIDE + kb + 8];
                #pragma unroll
                for (int nt = 0; nt < 4; nt++) {
                    mma16816(c[mt][nt], ah, bh[nt]);
                    mma16816(c[mt][nt], ah, bl[nt]);
                    mma16816(c[mt][nt], al, bh[nt]);
                }
            }
        }
        __syncthreads();
    }

    #pragma unroll
    for (int mt = 0; mt < 4; mt++) {
        #pragma unroll
        for (int half = 0; half < 2; half++) {
            int m = m0 + wm*64 + mt*16 + g + half*8;
            #pragma unroll
            for (int nt = 0; nt < 4; nt++) {
                int gc = col0 + wn*32 + nt*8 + t2;
                float* dst = g_y + (size_t)m*DIM + gc;
                dst[0] = c[mt][nt][half*2 + 0] + __ldg(bo + gc);
                dst[1] = c[mt][nt][half*2 + 1] + __ldg(bo + gc + 1);
            }
        }
    }
}

// ============================================================
// Kernel 4: LayerNorm + ls_scale + (b,n,d)->(n,b,d) transpose
// ============================================================
__global__ void ln_kernel(const float* __restrict__ ln_g,
                          const float* __restrict__ ln_b,
                          const float* __restrict__ ls,
                          float* __restrict__ out)
{
    __shared__ float red[8];
    const int m = blockIdx.x;
    const int b = m >> 11, n = m & 2047;
    const int tid = threadIdx.x;
    float4 v = ((const float4*)(g_y + (size_t)m*DIM))[tid];
    float s  = v.x + v.y + v.z + v.w;
    float sq = v.x*v.x + v.y*v.y + v.z*v.z + v.w*v.w;
    #pragma unroll
    for (int off = 16; off > 0; off >>= 1) {
        s  += __shfl_xor_sync(0xffffffffu, s,  off);
        sq += __shfl_xor_sync(0xffffffffu, sq, off);
    }
    const int wid = tid >> 5;
    if ((tid & 31) == 0) { red[wid] = s; red[wid + 4] = sq; }
    __syncthreads();
    s  = red[0] + red[1] + red[2] + red[3];
    sq = red[4] + red[5] + red[6] + red[7];
    float mu  = s * (1.f/DIM);
    float var = sq * (1.f/DIM) - mu*mu;
    float r   = rsqrtf(var + 1e-5f);

    float* dst = out + (size_t)(n*NB + b)*DIM;
    const int d0 = tid * 4;
    float vv[4] = {v.x, v.y, v.z, v.w};
    #pragma unroll
    for (int q = 0; q < 4; q++) {
        int d = d0 + q;
        dst[d] = ls[d] * ((vv[q] - mu) * r * ln_g[d] + ln_b[d]);
    }
}

// ============================================================
extern "C" void kernel_launch(void* const* d_in, const int* in_sizes, int n_in,
                              void* d_out, int out_size)
{
    const float* x    = (const float*)d_in[0];
    const float* rope = (const float*)d_in[1];
    const float* Wq   = (const float*)d_in[2];
    const float* Wk   = (const float*)d_in[3];
    const float* Wv   = (const float*)d_in[4];
    const float* Wo   = (const float*)d_in[5];
    const float* bo   = (const float*)d_in[6];
    const float* ln_g = (const float*)d_in[7];
    const float* ln_b = (const float*)d_in[8];
    const float* hsc  = (const float*)d_in[9];
    const float* ls   = (const float*)d_in[10];
    float* out = (float*)d_out;

    rope_table_kernel<<<(NB*NSEQ*DH + 255)/256, 256>>>(rope);
    qkv_mma<<<dim3(MROWS/128, 12), 256>>>(x, Wq, Wk, Wv);
    attn_mma<<<dim3(NSEQ/64, NB*HEADS), 128>>>(hsc);
    outproj_mma<<<dim3(MROWS/128, 4), 256>>>(Wo, bo);
    ln_kernel<<<MROWS, 128>>>(ln_g, ln_b, ls, out);
}

// round 8
// speedup vs baseline: 3.5236x; 1.1712x over previous
#include <cuda_runtime.h>
#include <cuda_bf16.h>
#include <cstdint>
#include <math.h>

#define HEADS   8
#define DH      64
#define DIM     512
#define NSEQ    2048
#define NB      4
#define MROWS   (NB*NSEQ)          // 8192
#define QSCALE  0.125f             // dh^-0.5
#define ASTRIDE 40                 // padded smem row stride (elems) for GEMM tiles
#define KSTR    72                 // padded stride for attention K/V tiles

// -------- scratch (device globals; no allocation allowed) --------
__device__ __nv_bfloat16 g_xh[MROWS*DIM];          // x pre-split (physical layout of x)
__device__ __nv_bfloat16 g_xl[MROWS*DIM];
__device__ __nv_bfloat16 g_wqh[DIM*DIM], g_wql[DIM*DIM];
__device__ __nv_bfloat16 g_wkh[DIM*DIM], g_wkl[DIM*DIM];
__device__ __nv_bfloat16 g_wvh[DIM*DIM], g_wvl[DIM*DIM];
__device__ __nv_bfloat16 g_woh[DIM*DIM], g_wol[DIM*DIM];
__device__ __nv_bfloat16 g_qh[NB*HEADS*NSEQ*DH];   // [b,h,n,d] hi
__device__ __nv_bfloat16 g_ql[NB*HEADS*NSEQ*DH];   // lo
__device__ __nv_bfloat16 g_kh[NB*HEADS*NSEQ*DH];
__device__ __nv_bfloat16 g_kl[NB*HEADS*NSEQ*DH];
__device__ __nv_bfloat16 g_vth[NB*HEADS*DH*NSEQ];  // [b,h,d,n] (transposed)
__device__ __nv_bfloat16 g_vtl[NB*HEADS*DH*NSEQ];
__device__ __nv_bfloat16 g_aoh[MROWS*DIM];         // attn out hi, rows = b*2048+n
__device__ __nv_bfloat16 g_aol[MROWS*DIM];         // attn out lo
__device__ float g_y[MROWS*DIM];                   // out-proj result pre-LN
__device__ float g_cos[NB*NSEQ*DH];
__device__ float g_sin[NB*NSEQ*DH];

// ============================================================
// mma.sync helpers (plain PTX, works on non-'a' target)
// ============================================================
__device__ __forceinline__ void mma16816(float* c, const uint32_t* a, const uint32_t* b) {
    asm volatile(
        "mma.sync.aligned.m16n8k16.row.col.f32.bf16.bf16.f32 "
        "{%0,%1,%2,%3}, {%4,%5,%6,%7}, {%8,%9}, {%0,%1,%2,%3};"
        : "+f"(c[0]), "+f"(c[1]), "+f"(c[2]), "+f"(c[3])
        : "r"(a[0]), "r"(a[1]), "r"(a[2]), "r"(a[3]), "r"(b[0]), "r"(b[1]));
}

// pack float4 -> hi bf16x4 + lo (residual) bf16x4
__device__ __forceinline__ void split4(float4 v, uint2& h, uint2& l) {
    __nv_bfloat162 ha = __floats2bfloat162_rn(v.x, v.y);
    __nv_bfloat162 hb = __floats2bfloat162_rn(v.z, v.w);
    float rx = v.x - __bfloat162float(ha.x);
    float ry = v.y - __bfloat162float(ha.y);
    float rz = v.z - __bfloat162float(hb.x);
    float rw = v.w - __bfloat162float(hb.y);
    __nv_bfloat162 la = __floats2bfloat162_rn(rx, ry);
    __nv_bfloat162 lb = __floats2bfloat162_rn(rz, rw);
    h.x = *(uint32_t*)&ha; h.y = *(uint32_t*)&hb;
    l.x = *(uint32_t*)&la; l.y = *(uint32_t*)&lb;
}

__device__ __forceinline__ void split2(float a, float b, uint32_t& h, uint32_t& l) {
    __nv_bfloat162 hh = __floats2bfloat162_rn(a, b);
    float ra = a - __bfloat162float(hh.x);
    float rb = b - __bfloat162float(hh.y);
    __nv_bfloat162 ll = __floats2bfloat162_rn(ra, rb);
    h = *(uint32_t*)&hh; l = *(uint32_t*)&ll;
}

// ============================================================
// Kernel S: elementwise fp32 -> bf16 hi/lo split (vectorized x4)
// ============================================================
__global__ void split_kernel(const float* __restrict__ src,
                             __nv_bfloat16* __restrict__ dh,
                             __nv_bfloat16* __restrict__ dl, int n4)
{
    int i = blockIdx.x * blockDim.x + threadIdx.x;
    if (i < n4) {
        float4 v = ((const float4*)src)[i];
        uint2 h, l; split4(v, h, l);
        ((uint2*)dh)[i] = h;
        ((uint2*)dl)[i] = l;
    }
}

// ============================================================
// Kernel 0: precompute cos/sin of rope freqs
// ============================================================
__global__ void rope_table_kernel(const float* __restrict__ rope)
{
    int i = blockIdx.x * blockDim.x + threadIdx.x;
    if (i < NB*NSEQ*DH) {
        float f = rope[i];
        g_cos[i] = cosf(f);
        g_sin[i] = sinf(f);
    }
}

// ============================================================
// Kernel 1: QKV projection (pre-split inputs) + RoPE epilogue
// grid: (64, 12), block 256 (8 warps, warp tile 64x32)
// ============================================================
__global__ void __launch_bounds__(256) qkv_mma()
{
    __shared__ __align__(16) __nv_bfloat16 Ah[128*ASTRIDE];
    __shared__ __align__(16) __nv_bfloat16 Al[128*ASTRIDE];
    __shared__ __align__(16) __nv_bfloat16 Bh[128*ASTRIDE];
    __shared__ __align__(16) __nv_bfloat16 Bl[128*ASTRIDE];

    const int tid = threadIdx.x, lid = tid & 31, wid = tid >> 5;
    const int wm = wid >> 2, wn = wid & 3;
    const int m0   = blockIdx.x * 128;
    const int by   = blockIdx.y;
    const int mat  = by >> 2;
    const int col0 = (by & 3) * 128;
    const __nv_bfloat16* Wh = (mat == 0) ? g_wqh : ((mat == 1) ? g_wkh : g_wvh);
    const __nv_bfloat16* Wl = (mat == 0) ? g_wql : ((mat == 1) ? g_wkl : g_wvl);

    const int g  = lid >> 2;
    const int t2 = (lid & 3) * 2;

    float c[4][4][4];
    #pragma unroll
    for (int i = 0; i < 4; i++)
        #pragma unroll
        for (int j = 0; j < 4; j++)
            #pragma unroll
            for (int q = 0; q < 4; q++) c[i][j][q] = 0.f;

    const int lrow = tid >> 3;
    const int f4   = tid & 7;

    for (int kc = 0; kc < 16; kc++) {
        const int kk = kc * 32;
        #pragma unroll
        for (int p = 0; p < 4; p++) {
            int row = p*32 + lrow;
            int m = m0 + row, n = m & 2047, b = m >> 11;
            size_t xo = (size_t)(n*NB + b)*DIM + kk + f4*4;
            *(uint2*)&Ah[row*ASTRIDE + f4*4] = *(const uint2*)&g_xh[xo];
            *(uint2*)&Al[row*ASTRIDE + f4*4] = *(const uint2*)&g_xl[xo];
            size_t wo = (size_t)(col0 + row)*DIM + kk + f4*4;
            *(uint2*)&Bh[row*ASTRIDE + f4*4] = *(const uint2*)&Wh[wo];
            *(uint2*)&Bl[row*ASTRIDE + f4*4] = *(const uint2*)&Wl[wo];
        }
        __syncthreads();

        #pragma unroll
        for (int ks = 0; ks < 2; ks++) {
            const int kb = ks*16 + t2;
            uint32_t bh[4][2], bl[4][2];
            #pragma unroll
            for (int nt = 0; nt < 4; nt++) {
                int nr = wn*32 + nt*8 + g;
                bh[nt][0] = *(const uint32_t*)&Bh[nr*ASTRIDE + kb];
                bh[nt][1] = *(const uint32_t*)&Bh[nr*ASTRIDE + kb + 8];
                bl[nt][0] = *(const uint32_t*)&Bl[nr*ASTRIDE + kb];
                bl[nt][1] = *(const uint32_t*)&Bl[nr*ASTRIDE + kb + 8];
            }
            #pragma unroll
            for (int mt = 0; mt < 4; mt++) {
                int ar = wm*64 + mt*16 + g;
                uint32_t ah[4], al[4];
                ah[0] = *(const uint32_t*)&Ah[ar*ASTRIDE + kb];
                ah[1] = *(const uint32_t*)&Ah[(ar+8)*ASTRIDE + kb];
                ah[2] = *(const uint32_t*)&Ah[ar*ASTRIDE + kb + 8];
                ah[3] = *(const uint32_t*)&Ah[(ar+8)*ASTRIDE + kb + 8];
                al[0] = *(const uint32_t*)&Al[ar*ASTRIDE + kb];
                al[1] = *(const uint32_t*)&Al[(ar+8)*ASTRIDE + kb];
                al[2] = *(const uint32_t*)&Al[ar*ASTRIDE + kb + 8];
                al[3] = *(const uint32_t*)&Al[(ar+8)*ASTRIDE + kb + 8];
                #pragma unroll
                for (int nt = 0; nt < 4; nt++) {
                    mma16816(c[mt][nt], ah, bh[nt]);
                    mma16816(c[mt][nt], ah, bl[nt]);
                    mma16816(c[mt][nt], al, bh[nt]);
                }
            }
        }
        __syncthreads();
    }

    // ---- epilogue: RoPE (+qscale), split, scatter ----
    #pragma unroll
    for (int mt = 0; mt < 4; mt++) {
        #pragma unroll
        for (int half = 0; half < 2; half++) {
            int m = m0 + wm*64 + mt*16 + g + half*8;
            int n = m & 2047, b = m >> 11;
            #pragma unroll
            for (int nt = 0; nt < 4; nt++) {
                int gc = col0 + wn*32 + nt*8 + t2;   // even col
                int h = gc >> 6, d = gc & 63;
                float v0 = c[mt][nt][half*2 + 0];
                float v1 = c[mt][nt][half*2 + 1];
                if (mat < 2) {
                    size_t fo = ((size_t)(b*NSEQ + n))*DH + d;
                    float co0 = g_cos[fo], co1 = g_cos[fo+1];
                    float si0 = g_sin[fo], si1 = g_sin[fo+1];
                    float o0 = v0*co0 - v1*si0;
                    float o1 = v1*co1 + v0*si1;
                    if (mat == 0) { o0 *= QSCALE; o1 *= QSCALE; }
                    uint32_t hh, ll; split2(o0, o1, hh, ll);
                    size_t off = (((size_t)(b*HEADS + h))*NSEQ + n)*DH + d;
                    if (mat == 0) {
                        *(uint32_t*)&g_qh[off] = hh;
                        *(uint32_t*)&g_ql[off] = ll;
                    } else {
                        *(uint32_t*)&g_kh[off] = hh;
                        *(uint32_t*)&g_kl[off] = ll;
                    }
                } else {
                    uint32_t hh, ll; split2(v0, v1, hh, ll);
                    __nv_bfloat162 h2 = *(__nv_bfloat162*)&hh;
                    __nv_bfloat162 l2 = *(__nv_bfloat162*)&ll;
                    size_t base = ((size_t)(b*HEADS + h))*DH*NSEQ;
                    g_vth[base + (size_t)d*NSEQ + n]     = h2.x;
                    g_vth[base + (size_t)(d+1)*NSEQ + n] = h2.y;
                    g_vtl[base + (size_t)d*NSEQ + n]     = l2.x;
                    g_vtl[base + (size_t)(d+1)*NSEQ + n] = l2.y;
                }
            }
        }
    }
}

// ============================================================
// Kernel 2: causal flash attention, BM=128, register-prefetched K/V
// grid: (32 bh, 16 qtiles DESCENDING), block 256 (8 warps x 16 q-rows)
// ============================================================
__global__ void __launch_bounds__(256) attn_mma(const float* __restrict__ head_scale)
{
    __shared__ __align__(16) __nv_bfloat16 Ksh[64*KSTR];
    __shared__ __align__(16) __nv_bfloat16 Ksl[64*KSTR];
    __shared__ __align__(16) __nv_bfloat16 Vsh[64*KSTR];   // VT: [d][kpos]
    __shared__ __align__(16) __nv_bfloat16 Vsl[64*KSTR];

    const int tid = threadIdx.x, lid = tid & 31, wid = tid >> 5;
    const int bh = blockIdx.x;
    const int qt = (NSEQ/128 - 1) - blockIdx.y;    // longest first
    const int q0 = qt * 128;
    const int g  = lid >> 2;
    const int t2 = (lid & 3) * 2;
    const int kmax = 2*qt + 2;                     // 64-wide k blocks

    const size_t hb_nd = (size_t)bh * NSEQ * DH;
    const size_t hb_dn = (size_t)bh * DH * NSEQ;

    // ---- load Q fragments (rows q0+wid*16 .. +15), hi & lo ----
    uint32_t qh[4][4], ql[4][4];
    {
        const __nv_bfloat16* qhp = g_qh + hb_nd + (size_t)(q0 + wid*16)*DH;
        const __nv_bfloat16* qlp = g_ql + hb_nd + (size_t)(q0 + wid*16)*DH;
        #pragma unroll
        for (int kt = 0; kt < 4; kt++) {
            int kc = kt*16 + t2;
            qh[kt][0] = *(const uint32_t*)&qhp[(size_t)g*DH + kc];
            qh[kt][1] = *(const uint32_t*)&qhp[(size_t)(g+8)*DH + kc];
            qh[kt][2] = *(const uint32_t*)&qhp[(size_t)g*DH + kc + 8];
            qh[kt][3] = *(const uint32_t*)&qhp[(size_t)(g+8)*DH + kc + 8];
            ql[kt][0] = *(const uint32_t*)&qlp[(size_t)g*DH + kc];
            ql[kt][1] = *(const uint32_t*)&qlp[(size_t)(g+8)*DH + kc];
            ql[kt][2] = *(const uint32_t*)&qlp[(size_t)g*DH + kc + 8];
            ql[kt][3] = *(const uint32_t*)&qlp[(size_t)(g+8)*DH + kc + 8];
        }
    }

    float m_i[2] = {-1e30f, -1e30f};
    float l_i[2] = {0.f, 0.f};
    float o[8][4];
    #pragma unroll
    for (int dt = 0; dt < 8; dt++)
        #pragma unroll
        for (int q = 0; q < 4; q++) o[dt][q] = 0.f;

    // staging geometry: 256 threads, each covers 32B of one row of each tile
    const int lrow = tid >> 2;        // 0..63
    const int seg  = (tid & 3) * 16;  // elem offset within 64

    // prefetch registers (next K/V tile)
    uint4 pk0, pk1, pl0, pl1, pv0, pv1, pw0, pw1;
    {
        const __nv_bfloat16* kh = g_kh + hb_nd + (size_t)lrow*DH + seg;
        const __nv_bfloat16* kl = g_kl + hb_nd + (size_t)lrow*DH + seg;
        const __nv_bfloat16* vh = g_vth + hb_dn + (size_t)lrow*NSEQ + seg;
        const __nv_bfloat16* vl = g_vtl + hb_dn + (size_t)lrow*NSEQ + seg;
        pk0 = *(const uint4*)&kh[0]; pk1 = *(const uint4*)&kh[8];
        pl0 = *(const uint4*)&kl[0]; pl1 = *(const uint4*)&kl[8];
        pv0 = *(const uint4*)&vh[0]; pv1 = *(const uint4*)&vh[8];
        pw0 = *(const uint4*)&vl[0]; pw1 = *(const uint4*)&vl[8];
    }

    for (int kb = 0; kb < kmax; kb++) {
        const int k0 = kb * 64;
        __syncthreads();   // previous compute done with smem
        // store prefetched tile
        {
            __nv_bfloat16* dk = &Ksh[lrow*KSTR + seg];
            __nv_bfloat16* dl = &Ksl[lrow*KSTR + seg];
            __nv_bfloat16* dvh = &Vsh[lrow*KSTR + seg];
            __nv_bfloat16* dvl = &Vsl[lrow*KSTR + seg];
            *(uint4*)&dk[0] = pk0;  *(uint4*)&dk[8] = pk1;
            *(uint4*)&dl[0] = pl0;  *(uint4*)&dl[8] = pl1;
            *(uint4*)&dvh[0] = pv0; *(uint4*)&dvh[8] = pv1;
            *(uint4*)&dvl[0] = pw0; *(uint4*)&dvl[8] = pw1;
        }
        __syncthreads();
        // prefetch next tile (overlaps with compute below)
        if (kb + 1 < kmax) {
            const int kn = (kb + 1) * 64;
            const __nv_bfloat16* kh = g_kh + hb_nd + (size_t)(kn + lrow)*DH + seg;
            const __nv_bfloat16* kl = g_kl + hb_nd + (size_t)(kn + lrow)*DH + seg;
            const __nv_bfloat16* vh = g_vth + hb_dn + (size_t)lrow*NSEQ + kn + seg;
            const __nv_bfloat16* vl = g_vtl + hb_dn + (size_t)lrow*NSEQ + kn + seg;
            pk0 = *(const uint4*)&kh[0]; pk1 = *(const uint4*)&kh[8];
            pl0 = *(const uint4*)&kl[0]; pl1 = *(const uint4*)&kl[8];
            pv0 = *(const uint4*)&vh[0]; pv1 = *(const uint4*)&vh[8];
            pw0 = *(const uint4*)&vl[0]; pw1 = *(const uint4*)&vl[8];
        }

        // warp fully above diagonal? (all cols > all rows) -> skip compute
        if (k0 > q0 + wid*16 + 15) continue;

        // ---- S = Q K^T (3-term) ----
        float sc[8][4];
        #pragma unroll
        for (int j = 0; j < 8; j++)
            #pragma unroll
            for (int q = 0; q < 4; q++) sc[j][q] = 0.f;

        #pragma unroll
        for (int j = 0; j < 8; j++) {
            const int nr = j*8 + g;
            #pragma unroll
            for (int kt = 0; kt < 4; kt++) {
                const int kc = kt*16 + t2;
                uint32_t bhf[2], blf[2];
                bhf[0] = *(const uint32_t*)&Ksh[nr*KSTR + kc];
                bhf[1] = *(const uint32_t*)&Ksh[nr*KSTR + kc + 8];
                blf[0] = *(const uint32_t*)&Ksl[nr*KSTR + kc];
                blf[1] = *(const uint32_t*)&Ksl[nr*KSTR + kc + 8];
                mma16816(sc[j], qh[kt], bhf);
                mma16816(sc[j], qh[kt], blf);
                mma16816(sc[j], ql[kt], bhf);
            }
        }

        // ---- causal mask (only near-diagonal blocks) ----
        if (k0 + 63 > q0 + wid*16) {
            const int r0 = q0 + wid*16 + g;
            #pragma unroll
            for (int j = 0; j < 8; j++) {
                int col = k0 + j*8 + t2;
                if (col     > r0)   sc[j][0] = -1e30f;
                if (col + 1 > r0)   sc[j][1] = -1e30f;
                if (col     > r0+8) sc[j][2] = -1e30f;
                if (col + 1 > r0+8) sc[j][3] = -1e30f;
            }
        }

        // ---- online softmax (rows g, g+8) ----
        float alpha[2];
        #pragma unroll
        for (int r = 0; r < 2; r++) {
            float mx = -1e30f;
            #pragma unroll
            for (int j = 0; j < 8; j++)
                mx = fmaxf(mx, fmaxf(sc[j][2*r], sc[j][2*r+1]));
            mx = fmaxf(mx, __shfl_xor_sync(0xffffffffu, mx, 1));
            mx = fmaxf(mx, __shfl_xor_sync(0xffffffffu, mx, 2));
            float mnew = fmaxf(m_i[r], mx);
            alpha[r] = __expf(m_i[r] - mnew);
            m_i[r] = mnew;
            float rs = 0.f;
            #pragma unroll
            for (int j = 0; j < 8; j++) {
                float p0 = __expf(sc[j][2*r]   - mnew);
                float p1 = __expf(sc[j][2*r+1] - mnew);
                sc[j][2*r] = p0; sc[j][2*r+1] = p1;
                rs += p0 + p1;
            }
            rs += __shfl_xor_sync(0xffffffffu, rs, 1);
            rs += __shfl_xor_sync(0xffffffffu, rs, 2);
            l_i[r] = l_i[r]*alpha[r] + rs;
        }

        // ---- rescale O ----
        #pragma unroll
        for (int dt = 0; dt < 8; dt++) {
            o[dt][0] *= alpha[0]; o[dt][1] *= alpha[0];
            o[dt][2] *= alpha[1]; o[dt][3] *= alpha[1];
        }

        // ---- convert P to A-fragments (hi/lo) ----
        uint32_t ph[4][4], pl[4][4];
        #pragma unroll
        for (int kt = 0; kt < 4; kt++) {
            split2(sc[2*kt][0],   sc[2*kt][1],   ph[kt][0], pl[kt][0]);
            split2(sc[2*kt][2],   sc[2*kt][3],   ph[kt][1], pl[kt][1]);
            split2(sc[2*kt+1][0], sc[2*kt+1][1], ph[kt][2], pl[kt][2]);
            split2(sc[2*kt+1][2], sc[2*kt+1][3], ph[kt][3], pl[kt][3]);
        }

        // ---- O += P V (3-term) ----
        #pragma unroll
        for (int dt = 0; dt < 8; dt++) {
            const int nr = dt*8 + g;
            #pragma unroll
            for (int kt = 0; kt < 4; kt++) {
                const int kc = kt*16 + t2;
                uint32_t vhf[2], vlf[2];
                vhf[0] = *(const uint32_t*)&Vsh[nr*KSTR + kc];
                vhf[1] = *(const uint32_t*)&Vsh[nr*KSTR + kc + 8];
                vlf[0] = *(const uint32_t*)&Vsl[nr*KSTR + kc];
                vlf[1] = *(const uint32_t*)&Vsl[nr*KSTR + kc + 8];
                mma16816(o[dt], ph[kt], vhf);
                mma16816(o[dt], ph[kt], vlf);
                mma16816(o[dt], pl[kt], vhf);
            }
        }
    }

    // ---- epilogue: scale by hs/l, split, store to g_aoh/g_aol ----
    const int b = bh >> 3, h = bh & 7;
    const float hs = head_scale[h];
    #pragma unroll
    for (int r = 0; r < 2; r++) {
        const float inv = hs / l_i[r];
        const int n = q0 + wid*16 + g + r*8;
        __nv_bfloat16* dsth = g_aoh + ((size_t)(b*NSEQ + n))*DIM + h*DH;
        __nv_bfloat16* dstl = g_aol + ((size_t)(b*NSEQ + n))*DIM + h*DH;
        #pragma unroll
        for (int dt = 0; dt < 8; dt++) {
            int d = dt*8 + t2;
            uint32_t hh, ll;
            split2(o[dt][2*r]*inv, o[dt][2*r+1]*inv, hh, ll);
            *(uint32_t*)&dsth[d] = hh;
            *(uint32_t*)&dstl[d] = ll;
        }
    }
}

// ============================================================
// Kernel 3: output projection (+bias); all inputs pre-split
// grid: (64, 4), block 256
// ============================================================
__global__ void __launch_bounds__(256) outproj_mma(const float* __restrict__ bo)
{
    __shared__ __align__(16) __nv_bfloat16 Ah[128*ASTRIDE];
    __shared__ __align__(16) __nv_bfloat16 Al[128*ASTRIDE];
    __shared__ __align__(16) __nv_bfloat16 Bh[128*ASTRIDE];
    __shared__ __align__(16) __nv_bfloat16 Bl[128*ASTRIDE];

    const int tid = threadIdx.x, lid = tid & 31, wid = tid >> 5;
    const int wm = wid >> 2, wn = wid & 3;
    const int m0   = blockIdx.x * 128;
    const int col0 = blockIdx.y * 128;
    const int g  = lid >> 2;
    const int t2 = (lid & 3) * 2;

    float c[4][4][4];
    #pragma unroll
    for (int i = 0; i < 4; i++)
        #pragma unroll
        for (int j = 0; j < 4; j++)
            #pragma unroll
            for (int q = 0; q < 4; q++) c[i][j][q] = 0.f;

    const int lrow = tid >> 3;
    const int f4   = tid & 7;

    for (int kc = 0; kc < 16; kc++) {
        const int kk = kc * 32;
        #pragma unroll
        for (int p = 0; p < 4; p++) {
            int row = p*32 + lrow;
            size_t aoff = (size_t)(m0 + row)*DIM + kk + f4*4;
            *(uint2*)&Ah[row*ASTRIDE + f4*4] = *(const uint2*)&g_aoh[aoff];
            *(uint2*)&Al[row*ASTRIDE + f4*4] = *(const uint2*)&g_aol[aoff];
            size_t woff = (size_t)(col0 + row)*DIM + kk + f4*4;
            *(uint2*)&Bh[row*ASTRIDE + f4*4] = *(const uint2*)&g_woh[woff];
            *(uint2*)&Bl[row*ASTRIDE + f4*4] = *(const uint2*)&g_wol[woff];
        }
        __syncthreads();

        #pragma unroll
        for (int ks = 0; ks < 2; ks++) {
            const int kb = ks*16 + t2;
            uint32_t bh[4][2], bl[4][2];
            #pragma unroll
            for (int nt = 0; nt < 4; nt++) {
                int nr = wn*32 + nt*8 + g;
                bh[nt][0] = *(const uint32_t*)&Bh[nr*ASTRIDE + kb];
                bh[nt][1] = *(const uint32_t*)&Bh[nr*ASTRIDE + kb + 8];
                bl[nt][0] = *(const uint32_t*)&Bl[nr*ASTRIDE + kb];
                bl[nt][1] = *(const uint32_t*)&Bl[nr*ASTRIDE + kb + 8];
            }
            #pragma unroll
            for (int mt = 0; mt < 4; mt++) {
                int ar = wm*64 + mt*16 + g;
                uint32_t ah[4], al[4];
                ah[0] = *(const uint32_t*)&Ah[ar*ASTRIDE + kb];
                ah[1] = *(const uint32_t*)&Ah[(ar+8)*ASTRIDE + kb];
                ah[2] = *(const uint32_t*)&Ah[ar*ASTRIDE + kb + 8];
                ah[3] = *(const uint32_t*)&Ah[(ar+8)*ASTRIDE + kb + 8];
                al[0] = *(const uint32_t*)&Al[ar*ASTRIDE + kb];
                al[1] = *(const uint32_t*)&Al[(ar+8)*ASTRIDE + kb];
                al[2] = *(const uint32_t*)&Al[ar*ASTRIDE + kb + 8];
                al[3] = *(const uint32_t*)&Al[(ar+8)*ASTRIDE + kb + 8];
                #pragma unroll
                for (int nt = 0; nt < 4; nt++) {
                    mma16816(c[mt][nt], ah, bh[nt]);
                    mma16816(c[mt][nt], ah, bl[nt]);
                    mma16816(c[mt][nt], al, bh[nt]);
                }
            }
        }
        __syncthreads();
    }

    #pragma unroll
    for (int mt = 0; mt < 4; mt++) {
        #pragma unroll
        for (int half = 0; half < 2; half++) {
            int m = m0 + wm*64 + mt*16 + g + half*8;
            #pragma unroll
            for (int nt = 0; nt < 4; nt++) {
                int gc = col0 + wn*32 + nt*8 + t2;
                float* dst = g_y + (size_t)m*DIM + gc;
                dst[0] = c[mt][nt][half*2 + 0] + __ldg(bo + gc);
                dst[1] = c[mt][nt][half*2 + 1] + __ldg(bo + gc + 1);
            }
        }
    }
}

// ============================================================
// Kernel 4: LayerNorm + ls_scale + (b,n,d)->(n,b,d) transpose
// ============================================================
__global__ void ln_kernel(const float* __restrict__ ln_g,
                          const float* __restrict__ ln_b,
                          const float* __restrict__ ls,
                          float* __restrict__ out)
{
    __shared__ float red[8];
    const int m = blockIdx.x;
    const int b = m >> 11, n = m & 2047;
    const int tid = threadIdx.x;
    float4 v = ((const float4*)(g_y + (size_t)m*DIM))[tid];
    float s  = v.x + v.y + v.z + v.w;
    float sq = v.x*v.x + v.y*v.y + v.z*v.z + v.w*v.w;
    #pragma unroll
    for (int off = 16; off > 0; off >>= 1) {
        s  += __shfl_xor_sync(0xffffffffu, s,  off);
        sq += __shfl_xor_sync(0xffffffffu, sq, off);
    }
    const int wid = tid >> 5;
    if ((tid & 31) == 0) { red[wid] = s; red[wid + 4] = sq; }
    __syncthreads();
    s  = red[0] + red[1] + red[2] + red[3];
    sq = red[4] + red[5] + red[6] + red[7];
    float mu  = s * (1.f/DIM);
    float var = sq * (1.f/DIM) - mu*mu;
    float r   = rsqrtf(var + 1e-5f);

    float* dst = out + (size_t)(n*NB + b)*DIM;
    const int d0 = tid * 4;
    float vv[4] = {v.x, v.y, v.z, v.w};
    #pragma unroll
    for (int q = 0; q < 4; q++) {
        int d = d0 + q;
        dst[d] = ls[d] * ((vv[q] - mu) * r * ln_g[d] + ln_b[d]);
    }
}

// ============================================================
extern "C" void kernel_launch(void* const* d_in, const int* in_sizes, int n_in,
                              void* d_out, int out_size)
{
    const float* x    = (const float*)d_in[0];
    const float* rope = (const float*)d_in[1];
    const float* Wq   = (const float*)d_in[2];
    const float* Wk   = (const float*)d_in[3];
    const float* Wv   = (const float*)d_in[4];
    const float* Wo   = (const float*)d_in[5];
    const float* bo   = (const float*)d_in[6];
    const float* ln_g = (const float*)d_in[7];
    const float* ln_b = (const float*)d_in[8];
    const float* hsc  = (const float*)d_in[9];
    const float* ls   = (const float*)d_in[10];
    float* out = (float*)d_out;

    __nv_bfloat16 *xh, *xl, *wqh, *wql, *wkh, *wkl, *wvh, *wvl, *woh, *wol;
    cudaGetSymbolAddress((void**)&xh,  g_xh);  cudaGetSymbolAddress((void**)&xl,  g_xl);
    cudaGetSymbolAddress((void**)&wqh, g_wqh); cudaGetSymbolAddress((void**)&wql, g_wql);
    cudaGetSymbolAddress((void**)&wkh, g_wkh); cudaGetSymbolAddress((void**)&wkl, g_wkl);
    cudaGetSymbolAddress((void**)&wvh, g_wvh); cudaGetSymbolAddress((void**)&wvl, g_wvl);
    cudaGetSymbolAddress((void**)&woh, g_woh); cudaGetSymbolAddress((void**)&wol, g_wol);

    const int XN4 = MROWS*DIM/4, WN4 = DIM*DIM/4;
    split_kernel<<<(XN4+255)/256, 256>>>(x,  xh,  xl,  XN4);
    split_kernel<<<(WN4+255)/256, 256>>>(Wq, wqh, wql, WN4);
    split_kernel<<<(WN4+255)/256, 256>>>(Wk, wkh, wkl, WN4);
    split_kernel<<<(WN4+255)/256, 256>>>(Wv, wvh, wvl, WN4);
    split_kernel<<<(WN4+255)/256, 256>>>(Wo, woh, wol, WN4);
    rope_table_kernel<<<(NB*NSEQ*DH + 255)/256, 256>>>(rope);

    qkv_mma<<<dim3(MROWS/128, 12), 256>>>();
    attn_mma<<<dim3(NB*HEADS, NSEQ/128), 256>>>(hsc);
    outproj_mma<<<dim3(MROWS/128, 4), 256>>>(bo);
    ln_kernel<<<MROWS, 128>>>(ln_g, ln_b, ls, out);
}

// round 9
// speedup vs baseline: 3.5425x; 1.0054x over previous
#include <cuda_runtime.h>
#include <cuda_bf16.h>
#include <cstdint>
#include <math.h>

#define HEADS   8
#define DH      64
#define DIM     512
#define NSEQ    2048
#define NB      4
#define MROWS   (NB*NSEQ)          // 8192
#define QSCALE  0.125f             // dh^-0.5
#define ASTRIDE 40                 // padded smem row stride (elems); 80B = 16B-aligned
#define KSTR    72                 // attention tile stride; 144B = 16B-aligned
#define TS      (128*ASTRIDE)      // GEMM tile elems (5120)
#define AS      (64*KSTR)          // attn tile elems (4608)

// -------- scratch (device globals; no allocation allowed) --------
__device__ __nv_bfloat16 g_xh[MROWS*DIM];
__device__ __nv_bfloat16 g_xl[MROWS*DIM];
__device__ __nv_bfloat16 g_wqh[DIM*DIM], g_wql[DIM*DIM];
__device__ __nv_bfloat16 g_wkh[DIM*DIM], g_wkl[DIM*DIM];
__device__ __nv_bfloat16 g_wvh[DIM*DIM], g_wvl[DIM*DIM];
__device__ __nv_bfloat16 g_woh[DIM*DIM], g_wol[DIM*DIM];
__device__ __nv_bfloat16 g_qh[NB*HEADS*NSEQ*DH];   // [b,h,n,d]
__device__ __nv_bfloat16 g_ql[NB*HEADS*NSEQ*DH];
__device__ __nv_bfloat16 g_kh[NB*HEADS*NSEQ*DH];
__device__ __nv_bfloat16 g_kl[NB*HEADS*NSEQ*DH];
__device__ __nv_bfloat16 g_vth[NB*HEADS*DH*NSEQ];  // [b,h,d,n]
__device__ __nv_bfloat16 g_vtl[NB*HEADS*DH*NSEQ];
__device__ __nv_bfloat16 g_aoh[MROWS*DIM];
__device__ __nv_bfloat16 g_aol[MROWS*DIM];
__device__ float g_y[MROWS*DIM];
__device__ float g_cos[NB*NSEQ*DH];
__device__ float g_sin[NB*NSEQ*DH];

// ============================================================
// helpers
// ============================================================
__device__ __forceinline__ void mma16816(float* c, const uint32_t* a, const uint32_t* b) {
    asm volatile(
        "mma.sync.aligned.m16n8k16.row.col.f32.bf16.bf16.f32 "
        "{%0,%1,%2,%3}, {%4,%5,%6,%7}, {%8,%9}, {%0,%1,%2,%3};"
        : "+f"(c[0]), "+f"(c[1]), "+f"(c[2]), "+f"(c[3])
        : "r"(a[0]), "r"(a[1]), "r"(a[2]), "r"(a[3]), "r"(b[0]), "r"(b[1]));
}

__device__ __forceinline__ uint32_t su32(const void* p) {
    uint32_t a;
    asm("{ .reg .u64 t; cvta.to.shared.u64 t, %1; cvt.u32.u64 %0, t; }"
        : "=r"(a) : "l"(p));
    return a;
}
#define CPA(dst, src) asm volatile("cp.async.cg.shared.global [%0], [%1], 16;" :: "r"(dst), "l"(src))
#define CPC()         asm volatile("cp.async.commit_group;")
#define CPW(n)        asm volatile("cp.async.wait_group %0;" :: "n"(n))

__device__ __forceinline__ void split4(float4 v, uint2& h, uint2& l) {
    __nv_bfloat162 ha = __floats2bfloat162_rn(v.x, v.y);
    __nv_bfloat162 hb = __floats2bfloat162_rn(v.z, v.w);
    float rx = v.x - __bfloat162float(ha.x);
    float ry = v.y - __bfloat162float(ha.y);
    float rz = v.z - __bfloat162float(hb.x);
    float rw = v.w - __bfloat162float(hb.y);
    __nv_bfloat162 la = __floats2bfloat162_rn(rx, ry);
    __nv_bfloat162 lb = __floats2bfloat162_rn(rz, rw);
    h.x = *(uint32_t*)&ha; h.y = *(uint32_t*)&hb;
    l.x = *(uint32_t*)&la; l.y = *(uint32_t*)&lb;
}
__device__ __forceinline__ void split2(float a, float b, uint32_t& h, uint32_t& l) {
    __nv_bfloat162 hh = __floats2bfloat162_rn(a, b);
    float ra = a - __bfloat162float(hh.x);
    float rb = b - __bfloat162float(hh.y);
    __nv_bfloat162 ll = __floats2bfloat162_rn(ra, rb);
    h = *(uint32_t*)&hh; l = *(uint32_t*)&ll;
}

// ============================================================
__global__ void split_kernel(const float* __restrict__ src,
                             __nv_bfloat16* __restrict__ dh,
                             __nv_bfloat16* __restrict__ dl, int n4)
{
    int i = blockIdx.x * blockDim.x + threadIdx.x;
    if (i < n4) {
        float4 v = ((const float4*)src)[i];
        uint2 h, l; split4(v, h, l);
        ((uint2*)dh)[i] = h;
        ((uint2*)dl)[i] = l;
    }
}

__global__ void rope_table_kernel(const float* __restrict__ rope)
{
    int i = blockIdx.x * blockDim.x + threadIdx.x;
    if (i < NB*NSEQ*DH) {
        float f = rope[i];
        g_cos[i] = cosf(f);
        g_sin[i] = sinf(f);
    }
}

// ============================================================
// Kernel 1: QKV projection, cp.async double-buffered
// grid: (64, 12), block 256; dyn smem 2*4*TS*2 = 81920 B
// ============================================================
__global__ void __launch_bounds__(256) qkv_mma()
{
    extern __shared__ __align__(16) __nv_bfloat16 dsm[];
    const uint32_t sbase = su32(dsm);

    const int tid = threadIdx.x, lid = tid & 31, wid = tid >> 5;
    const int wm = wid >> 2, wn = wid & 3;
    const int m0   = blockIdx.x * 128;
    const int by   = blockIdx.y;
    const int mat  = by >> 2;
    const int col0 = (by & 3) * 128;
    const __nv_bfloat16* Wh = (mat == 0) ? g_wqh : ((mat == 1) ? g_wkh : g_wvh);
    const __nv_bfloat16* Wl = (mat == 0) ? g_wql : ((mat == 1) ? g_wkl : g_wvl);

    const int g  = lid >> 2;
    const int t2 = (lid & 3) * 2;

    // staging: row = tid>>1 (0..127), seg = (tid&1)*16 elems; 2 chunks/array
    const int srow = tid >> 1;
    const int sseg = (tid & 1) * 16;
    const int sm  = m0 + srow, sn = sm & 2047, sb2 = sm >> 11;
    const size_t axo = (size_t)(sn*NB + sb2)*DIM + sseg;
    const size_t bwo = (size_t)(col0 + srow)*DIM + sseg;
    const uint32_t doff = (uint32_t)(srow*ASTRIDE + sseg) * 2;

    #define QKV_STAGE(kk, buf) do { \
        uint32_t b0 = sbase + (uint32_t)(buf)*(4*TS*2) + doff; \
        const __nv_bfloat16* pa = g_xh + axo + (kk); \
        const __nv_bfloat16* pb = g_xl + axo + (kk); \
        const __nv_bfloat16* pc = Wh + bwo + (kk); \
        const __nv_bfloat16* pd = Wl + bwo + (kk); \
        CPA(b0,            pa); CPA(b0 + 16,            pa + 8); \
        CPA(b0 + TS*2,     pb); CPA(b0 + TS*2 + 16,     pb + 8); \
        CPA(b0 + 2*TS*2,   pc); CPA(b0 + 2*TS*2 + 16,   pc + 8); \
        CPA(b0 + 3*TS*2,   pd); CPA(b0 + 3*TS*2 + 16,   pd + 8); \
    } while (0)

    float c[4][4][4];
    #pragma unroll
    for (int i = 0; i < 4; i++)
        #pragma unroll
        for (int j = 0; j < 4; j++)
            #pragma unroll
            for (int q = 0; q < 4; q++) c[i][j][q] = 0.f;

    QKV_STAGE(0, 0); CPC();

    for (int kc = 0; kc < 16; kc++) {
        if (kc + 1 < 16) { QKV_STAGE((kc+1)*32, (kc+1)&1); CPC(); CPW(1); }
        else             { CPW(0); }
        __syncthreads();

        const __nv_bfloat16* Ah = dsm + (kc&1)*(4*TS);
        const __nv_bfloat16* Al = Ah + TS;
        const __nv_bfloat16* Bh = Ah + 2*TS;
        const __nv_bfloat16* Bl = Ah + 3*TS;

        #pragma unroll
        for (int ks = 0; ks < 2; ks++) {
            const int kb = ks*16 + t2;
            uint32_t bh[4][2], bl[4][2];
            #pragma unroll
            for (int nt = 0; nt < 4; nt++) {
                int nr = wn*32 + nt*8 + g;
                bh[nt][0] = *(const uint32_t*)&Bh[nr*ASTRIDE + kb];
                bh[nt][1] = *(const uint32_t*)&Bh[nr*ASTRIDE + kb + 8];
                bl[nt][0] = *(const uint32_t*)&Bl[nr*ASTRIDE + kb];
                bl[nt][1] = *(const uint32_t*)&Bl[nr*ASTRIDE + kb + 8];
            }
            #pragma unroll
            for (int mt = 0; mt < 4; mt++) {
                int ar = wm*64 + mt*16 + g;
                uint32_t ah[4], al[4];
                ah[0] = *(const uint32_t*)&Ah[ar*ASTRIDE + kb];
                ah[1] = *(const uint32_t*)&Ah[(ar+8)*ASTRIDE + kb];
                ah[2] = *(const uint32_t*)&Ah[ar*ASTRIDE + kb + 8];
                ah[3] = *(const uint32_t*)&Ah[(ar+8)*ASTRIDE + kb + 8];
                al[0] = *(const uint32_t*)&Al[ar*ASTRIDE + kb];
                al[1] = *(const uint32_t*)&Al[(ar+8)*ASTRIDE + kb];
                al[2] = *(const uint32_t*)&Al[ar*ASTRIDE + kb + 8];
                al[3] = *(const uint32_t*)&Al[(ar+8)*ASTRIDE + kb + 8];
                #pragma unroll
                for (int nt = 0; nt < 4; nt++) {
                    mma16816(c[mt][nt], ah, bh[nt]);
                    mma16816(c[mt][nt], ah, bl[nt]);
                    mma16816(c[mt][nt], al, bh[nt]);
                }
            }
        }
        __syncthreads();
    }

    // ---- epilogue: RoPE (+qscale), split, scatter ----
    #pragma unroll
    for (int mt = 0; mt < 4; mt++) {
        #pragma unroll
        for (int half = 0; half < 2; half++) {
            int m = m0 + wm*64 + mt*16 + g + half*8;
            int n = m & 2047, b = m >> 11;
            #pragma unroll
            for (int nt = 0; nt < 4; nt++) {
                int gc = col0 + wn*32 + nt*8 + t2;
                int h = gc >> 6, d = gc & 63;
                float v0 = c[mt][nt][half*2 + 0];
                float v1 = c[mt][nt][half*2 + 1];
                if (mat < 2) {
                    size_t fo = ((size_t)(b*NSEQ + n))*DH + d;
                    float co0 = g_cos[fo], co1 = g_cos[fo+1];
                    float si0 = g_sin[fo], si1 = g_sin[fo+1];
                    float o0 = v0*co0 - v1*si0;
                    float o1 = v1*co1 + v0*si1;
                    if (mat == 0) { o0 *= QSCALE; o1 *= QSCALE; }
                    uint32_t hh, ll; split2(o0, o1, hh, ll);
                    size_t off = (((size_t)(b*HEADS + h))*NSEQ + n)*DH + d;
                    if (mat == 0) {
                        *(uint32_t*)&g_qh[off] = hh;
                        *(uint32_t*)&g_ql[off] = ll;
                    } else {
                        *(uint32_t*)&g_kh[off] = hh;
                        *(uint32_t*)&g_kl[off] = ll;
                    }
                } else {
                    uint32_t hh, ll; split2(v0, v1, hh, ll);
                    __nv_bfloat162 h2 = *(__nv_bfloat162*)&hh;
                    __nv_bfloat162 l2 = *(__nv_bfloat162*)&ll;
                    size_t base = ((size_t)(b*HEADS + h))*DH*NSEQ;
                    g_vth[base + (size_t)d*NSEQ + n]     = h2.x;
                    g_vth[base + (size_t)(d+1)*NSEQ + n] = h2.y;
                    g_vtl[base + (size_t)d*NSEQ + n]     = l2.x;
                    g_vtl[base + (size_t)(d+1)*NSEQ + n] = l2.y;
                }
            }
        }
    }
}

// ============================================================
// Kernel 2: causal flash attention, BM=128, cp.async double-buffered
// grid: (32 bh, 16 qtiles DESC), block 256; dyn smem 2*4*AS*2 = 73728 B
// ============================================================
__global__ void __launch_bounds__(256) attn_mma(const float* __restrict__ head_scale)
{
    extern __shared__ __align__(16) __nv_bfloat16 dsm[];
    const uint32_t sbase = su32(dsm);

    const int tid = threadIdx.x, lid = tid & 31, wid = tid >> 5;
    const int bh = blockIdx.x;
    const int qt = (NSEQ/128 - 1) - blockIdx.y;    // longest first
    const int q0 = qt * 128;
    const int g  = lid >> 2;
    const int t2 = (lid & 3) * 2;
    const int kmax = 2*qt + 2;

    const size_t hb_nd = (size_t)bh * NSEQ * DH;
    const size_t hb_dn = (size_t)bh * DH * NSEQ;

    // staging: row = tid>>2 (0..63), seg = (tid&3)*16; 2 chunks/array
    const int srow = tid >> 2;
    const int sseg = (tid & 3) * 16;
    const uint32_t doff = (uint32_t)(srow*KSTR + sseg) * 2;
    const __nv_bfloat16* kh_s = g_kh + hb_nd + (size_t)srow*DH + sseg;
    const __nv_bfloat16* kl_s = g_kl + hb_nd + (size_t)srow*DH + sseg;
    const __nv_bfloat16* vh_s = g_vth + hb_dn + (size_t)srow*NSEQ + sseg;
    const __nv_bfloat16* vl_s = g_vtl + hb_dn + (size_t)srow*NSEQ + sseg;

    #define ATTN_STAGE(k0v, buf) do { \
        uint32_t b0 = sbase + (uint32_t)(buf)*(4*AS*2) + doff; \
        const __nv_bfloat16* pa = kh_s + (size_t)(k0v)*DH; \
        const __nv_bfloat16* pb = kl_s + (size_t)(k0v)*DH; \
        const __nv_bfloat16* pc = vh_s + (k0v); \
        const __nv_bfloat16* pd = vl_s + (k0v); \
        CPA(b0,          pa); CPA(b0 + 16,          pa + 8); \
        CPA(b0 + AS*2,   pb); CPA(b0 + AS*2 + 16,   pb + 8); \
        CPA(b0 + 2*AS*2, pc); CPA(b0 + 2*AS*2 + 16, pc + 8); \
        CPA(b0 + 3*AS*2, pd); CPA(b0 + 3*AS*2 + 16, pd + 8); \
    } while (0)

    // ---- load Q fragments, hi & lo ----
    uint32_t qh[4][4], ql[4][4];
    {
        const __nv_bfloat16* qhp = g_qh + hb_nd + (size_t)(q0 + wid*16)*DH;
        const __nv_bfloat16* qlp = g_ql + hb_nd + (size_t)(q0 + wid*16)*DH;
        #pragma unroll
        for (int kt = 0; kt < 4; kt++) {
            int kc = kt*16 + t2;
            qh[kt][0] = *(const uint32_t*)&qhp[(size_t)g*DH + kc];
            qh[kt][1] = *(const uint32_t*)&qhp[(size_t)(g+8)*DH + kc];
            qh[kt][2] = *(const uint32_t*)&qhp[(size_t)g*DH + kc + 8];
            qh[kt][3] = *(const uint32_t*)&qhp[(size_t)(g+8)*DH + kc + 8];
            ql[kt][0] = *(const uint32_t*)&qlp[(size_t)g*DH + kc];
            ql[kt][1] = *(const uint32_t*)&qlp[(size_t)(g+8)*DH + kc];
            ql[kt][2] = *(const uint32_t*)&qlp[(size_t)g*DH + kc + 8];
            ql[kt][3] = *(const uint32_t*)&qlp[(size_t)(g+8)*DH + kc + 8];
        }
    }

    float m_i[2] = {-1e30f, -1e30f};
    float l_i[2] = {0.f, 0.f};
    float o[8][4];
    #pragma unroll
    for (int dt = 0; dt < 8; dt++)
        #pragma unroll
        for (int q = 0; q < 4; q++) o[dt][q] = 0.f;

    ATTN_STAGE(0, 0); CPC();

    for (int kb = 0; kb < kmax; kb++) {
        const int k0 = kb * 64;
        if (kb + 1 < kmax) { ATTN_STAGE((kb+1)*64, (kb+1)&1); CPC(); CPW(1); }
        else               { CPW(0); }
        __syncthreads();

        const __nv_bfloat16* Ksh = dsm + (kb&1)*(4*AS);
        const __nv_bfloat16* Ksl = Ksh + AS;
        const __nv_bfloat16* Vsh = Ksh + 2*AS;
        const __nv_bfloat16* Vsl = Ksh + 3*AS;

        if (k0 <= q0 + wid*16 + 15) {      // warp has unmasked work
            // ---- S = Q K^T (3-term) ----
            float sc[8][4];
            #pragma unroll
            for (int j = 0; j < 8; j++)
                #pragma unroll
                for (int q = 0; q < 4; q++) sc[j][q] = 0.f;

            #pragma unroll
            for (int j = 0; j < 8; j++) {
                const int nr = j*8 + g;
                #pragma unroll
                for (int kt = 0; kt < 4; kt++) {
                    const int kc = kt*16 + t2;
                    uint32_t bhf[2], blf[2];
                    bhf[0] = *(const uint32_t*)&Ksh[nr*KSTR + kc];
                    bhf[1] = *(const uint32_t*)&Ksh[nr*KSTR + kc + 8];
                    blf[0] = *(const uint32_t*)&Ksl[nr*KSTR + kc];
                    blf[1] = *(const uint32_t*)&Ksl[nr*KSTR + kc + 8];
                    mma16816(sc[j], qh[kt], bhf);
                    mma16816(sc[j], qh[kt], blf);
                    mma16816(sc[j], ql[kt], bhf);
                }
            }

            // ---- causal mask (near-diagonal blocks only) ----
            if (k0 + 63 > q0 + wid*16) {
                const int r0 = q0 + wid*16 + g;
                #pragma unroll
                for (int j = 0; j < 8; j++) {
                    int col = k0 + j*8 + t2;
                    if (col     > r0)   sc[j][0] = -1e30f;
                    if (col + 1 > r0)   sc[j][1] = -1e30f;
                    if (col     > r0+8) sc[j][2] = -1e30f;
                    if (col + 1 > r0+8) sc[j][3] = -1e30f;
                }
            }

            // ---- online softmax ----
            float alpha[2];
            #pragma unroll
            for (int r = 0; r < 2; r++) {
                float mx = -1e30f;
                #pragma unroll
                for (int j = 0; j < 8; j++)
                    mx = fmaxf(mx, fmaxf(sc[j][2*r], sc[j][2*r+1]));
                mx = fmaxf(mx, __shfl_xor_sync(0xffffffffu, mx, 1));
                mx = fmaxf(mx, __shfl_xor_sync(0xffffffffu, mx, 2));
                float mnew = fmaxf(m_i[r], mx);
                alpha[r] = __expf(m_i[r] - mnew);
                m_i[r] = mnew;
                float rs = 0.f;
                #pragma unroll
                for (int j = 0; j < 8; j++) {
                    float p0 = __expf(sc[j][2*r]   - mnew);
                    float p1 = __expf(sc[j][2*r+1] - mnew);
                    sc[j][2*r] = p0; sc[j][2*r+1] = p1;
                    rs += p0 + p1;
                }
                rs += __shfl_xor_sync(0xffffffffu, rs, 1);
                rs += __shfl_xor_sync(0xffffffffu, rs, 2);
                l_i[r] = l_i[r]*alpha[r] + rs;
            }

            #pragma unroll
            for (int dt = 0; dt < 8; dt++) {
                o[dt][0] *= alpha[0]; o[dt][1] *= alpha[0];
                o[dt][2] *= alpha[1]; o[dt][3] *= alpha[1];
            }

            // ---- P -> A-fragments (hi/lo) ----
            uint32_t ph[4][4], pl[4][4];
            #pragma unroll
            for (int kt = 0; kt < 4; kt++) {
                split2(sc[2*kt][0],   sc[2*kt][1],   ph[kt][0], pl[kt][0]);
                split2(sc[2*kt][2],   sc[2*kt][3],   ph[kt][1], pl[kt][1]);
                split2(sc[2*kt+1][0], sc[2*kt+1][1], ph[kt][2], pl[kt][2]);
                split2(sc[2*kt+1][2], sc[2*kt+1][3], ph[kt][3], pl[kt][3]);
            }

            // ---- O += P V (3-term) ----
            #pragma unroll
            for (int dt = 0; dt < 8; dt++) {
                const int nr = dt*8 + g;
                #pragma unroll
                for (int kt = 0; kt < 4; kt++) {
                    const int kc = kt*16 + t2;
                    uint32_t vhf[2], vlf[2];
                    vhf[0] = *(const uint32_t*)&Vsh[nr*KSTR + kc];
                    vhf[1] = *(const uint32_t*)&Vsh[nr*KSTR + kc + 8];
                    vlf[0] = *(const uint32_t*)&Vsl[nr*KSTR + kc];
                    vlf[1] = *(const uint32_t*)&Vsl[nr*KSTR + kc + 8];
                    mma16816(o[dt], ph[kt], vhf);
                    mma16816(o[dt], ph[kt], vlf);
                    mma16816(o[dt], pl[kt], vhf);
                }
            }
        }
        __syncthreads();
    }

    // ---- epilogue ----
    const int b = bh >> 3, h = bh & 7;
    const float hs = head_scale[h];
    #pragma unroll
    for (int r = 0; r < 2; r++) {
        const float inv = hs / l_i[r];
        const int n = q0 + wid*16 + g + r*8;
        __nv_bfloat16* dsth = g_aoh + ((size_t)(b*NSEQ + n))*DIM + h*DH;
        __nv_bfloat16* dstl = g_aol + ((size_t)(b*NSEQ + n))*DIM + h*DH;
        #pragma unroll
        for (int dt = 0; dt < 8; dt++) {
            int d = dt*8 + t2;
            uint32_t hh, ll;
            split2(o[dt][2*r]*inv, o[dt][2*r+1]*inv, hh, ll);
            *(uint32_t*)&dsth[d] = hh;
            *(uint32_t*)&dstl[d] = ll;
        }
    }
}

// ============================================================
// Kernel 3: output projection, cp.async double-buffered
// grid: (64, 4), block 256; dyn smem 81920 B
// ============================================================
__global__ void __launch_bounds__(256) outproj_mma(const float* __restrict__ bo)
{
    extern __shared__ __align__(16) __nv_bfloat16 dsm[];
    const uint32_t sbase = su32(dsm);

    const int tid = threadIdx.x, lid = tid & 31, wid = tid >> 5;
    const int wm = wid >> 2, wn = wid & 3;
    const int m0   = blockIdx.x * 128;
    const int col0 = blockIdx.y * 128;
    const int g  = lid >> 2;
    const int t2 = (lid & 3) * 2;

    const int srow = tid >> 1;
    const int sseg = (tid & 1) * 16;
    const size_t aoo = (size_t)(m0 + srow)*DIM + sseg;
    const size_t woo = (size_t)(col0 + srow)*DIM + sseg;
    const uint32_t doff = (uint32_t)(srow*ASTRIDE + sseg) * 2;

    #define OP_STAGE(kk, buf) do { \
        uint32_t b0 = sbase + (uint32_t)(buf)*(4*TS*2) + doff; \
        const __nv_bfloat16* pa = g_aoh + aoo + (kk); \
        const __nv_bfloat16* pb = g_aol + aoo + (kk); \
        const __nv_bfloat16* pc = g_woh + woo + (kk); \
        const __nv_bfloat16* pd = g_wol + woo + (kk); \
        CPA(b0,          pa); CPA(b0 + 16,          pa + 8); \
        CPA(b0 + TS*2,   pb); CPA(b0 + TS*2 + 16,   pb + 8); \
        CPA(b0 + 2*TS*2, pc); CPA(b0 + 2*TS*2 + 16, pc + 8); \
        CPA(b0 + 3*TS*2, pd); CPA(b0 + 3*TS*2 + 16, pd + 8); \
    } while (0)

    float c[4][4][4];
    #pragma unroll
    for (int i = 0; i < 4; i++)
        #pragma unroll
        for (int j = 0; j < 4; j++)
            #pragma unroll
            for (int q = 0; q < 4; q++) c[i][j][q] = 0.f;

    OP_STAGE(0, 0); CPC();

    for (int kc = 0; kc < 16; kc++) {
        if (kc + 1 < 16) { OP_STAGE((kc+1)*32, (kc+1)&1); CPC(); CPW(1); }
        else             { CPW(0); }
        __syncthreads();

        const __nv_bfloat16* Ah = dsm + (kc&1)*(4*TS);
        const __nv_bfloat16* Al = Ah + TS;
        const __nv_bfloat16* Bh = Ah + 2*TS;
        const __nv_bfloat16* Bl = Ah + 3*TS;

        #pragma unroll
        for (int ks = 0; ks < 2; ks++) {
            const int kb = ks*16 + t2;
            uint32_t bh[4][2], bl[4][2];
            #pragma unroll
            for (int nt = 0; nt < 4; nt++) {
                int nr = wn*32 + nt*8 + g;
                bh[nt][0] = *(const uint32_t*)&Bh[nr*ASTRIDE + kb];
                bh[nt][1] = *(const uint32_t*)&Bh[nr*ASTRIDE + kb + 8];
                bl[nt][0] = *(const uint32_t*)&Bl[nr*ASTRIDE + kb];
                bl[nt][1] = *(const uint32_t*)&Bl[nr*ASTRIDE + kb + 8];
            }
            #pragma unroll
            for (int mt = 0; mt < 4; mt++) {
                int ar = wm*64 + mt*16 + g;
                uint32_t ah[4], al[4];
                ah[0] = *(const uint32_t*)&Ah[ar*ASTRIDE + kb];
                ah[1] = *(const uint32_t*)&Ah[(ar+8)*ASTRIDE + kb];
                ah[2] = *(const uint32_t*)&Ah[ar*ASTRIDE + kb + 8];
                ah[3] = *(const uint32_t*)&Ah[(ar+8)*ASTRIDE + kb + 8];
                al[0] = *(const uint32_t*)&Al[ar*ASTRIDE + kb];
                al[1] = *(const uint32_t*)&Al[(ar+8)*ASTRIDE + kb];
                al[2] = *(const uint32_t*)&Al[ar*ASTRIDE + kb + 8];
                al[3] = *(const uint32_t*)&Al[(ar+8)*ASTRIDE + kb + 8];
                #pragma unroll
                for (int nt = 0; nt < 4; nt++) {
                    mma16816(c[mt][nt], ah, bh[nt]);
                    mma16816(c[mt][nt], ah, bl[nt]);
                    mma16816(c[mt][nt], al, bh[nt]);
                }
            }
        }
        __syncthreads();
    }

    #pragma unroll
    for (int mt = 0; mt < 4; mt++) {
        #pragma unroll
        for (int half = 0; half < 2; half++) {
            int m = m0 + wm*64 + mt*16 + g + half*8;
            #pragma unroll
            for (int nt = 0; nt < 4; nt++) {
                int gc = col0 + wn*32 + nt*8 + t2;
                float* dst = g_y + (size_t)m*DIM + gc;
                dst[0] = c[mt][nt][half*2 + 0] + __ldg(bo + gc);
                dst[1] = c[mt][nt][half*2 + 1] + __ldg(bo + gc + 1);
            }
        }
    }
}

// ============================================================
// Kernel 4: LayerNorm + ls_scale + transpose
// ============================================================
__global__ void ln_kernel(const float* __restrict__ ln_g,
                          const float* __restrict__ ln_b,
                          const float* __restrict__ ls,
                          float* __restrict__ out)
{
    __shared__ float red[8];
    const int m = blockIdx.x;
    const int b = m >> 11, n = m & 2047;
    const int tid = threadIdx.x;
    float4 v = ((const float4*)(g_y + (size_t)m*DIM))[tid];
    float s  = v.x + v.y + v.z + v.w;
    float sq = v.x*v.x + v.y*v.y + v.z*v.z + v.w*v.w;
    #pragma unroll
    for (int off = 16; off > 0; off >>= 1) {
        s  += __shfl_xor_sync(0xffffffffu, s,  off);
        sq += __shfl_xor_sync(0xffffffffu, sq, off);
    }
    const int wid = tid >> 5;
    if ((tid & 31) == 0) { red[wid] = s; red[wid + 4] = sq; }
    __syncthreads();
    s  = red[0] + red[1] + red[2] + red[3];
    sq = red[4] + red[5] + red[6] + red[7];
    float mu  = s * (1.f/DIM);
    float var = sq * (1.f/DIM) - mu*mu;
    float r   = rsqrtf(var + 1e-5f);

    float* dst = out + (size_t)(n*NB + b)*DIM;
    const int d0 = tid * 4;
    float vv[4] = {v.x, v.y, v.z, v.w};
    #pragma unroll
    for (int q = 0; q < 4; q++) {
        int d = d0 + q;
        dst[d] = ls[d] * ((vv[q] - mu) * r * ln_g[d] + ln_b[d]);
    }
}

// ============================================================
extern "C" void kernel_launch(void* const* d_in, const int* in_sizes, int n_in,
                              void* d_out, int out_size)
{
    const float* x    = (const float*)d_in[0];
    const float* rope = (const float*)d_in[1];
    const float* Wq   = (const float*)d_in[2];
    const float* Wk   = (const float*)d_in[3];
    const float* Wv   = (const float*)d_in[4];
    const float* Wo   = (const float*)d_in[5];
    const float* bo   = (const float*)d_in[6];
    const float* ln_g = (const float*)d_in[7];
    const float* ln_b = (const float*)d_in[8];
    const float* hsc  = (const float*)d_in[9];
    const float* ls   = (const float*)d_in[10];
    float* out = (float*)d_out;

    __nv_bfloat16 *xh, *xl, *wqh, *wql, *wkh, *wkl, *wvh, *wvl, *woh, *wol;
    cudaGetSymbolAddress((void**)&xh,  g_xh);  cudaGetSymbolAddress((void**)&xl,  g_xl);
    cudaGetSymbolAddress((void**)&wqh, g_wqh); cudaGetSymbolAddress((void**)&wql, g_wql);
    cudaGetSymbolAddress((void**)&wkh, g_wkh); cudaGetSymbolAddress((void**)&wkl, g_wkl);
    cudaGetSymbolAddress((void**)&wvh, g_wvh); cudaGetSymbolAddress((void**)&wvl, g_wvl);
    cudaGetSymbolAddress((void**)&woh, g_woh); cudaGetSymbolAddress((void**)&wol, g_wol);

    static bool attr_done = false;
    if (!attr_done) {
        cudaFuncSetAttribute(qkv_mma,     cudaFuncAttributeMaxDynamicSharedMemorySize, 2*4*TS*2);
        cudaFuncSetAttribute(outproj_mma, cudaFuncAttributeMaxDynamicSharedMemorySize, 2*4*TS*2);
        cudaFuncSetAttribute(attn_mma,    cudaFuncAttributeMaxDynamicSharedMemorySize, 2*4*AS*2);
        attr_done = true;
    }

    const int XN4 = MROWS*DIM/4, WN4 = DIM*DIM/4;
    split_kernel<<<(XN4+255)/256, 256>>>(x,  xh,  xl,  XN4);
    split_kernel<<<(WN4+255)/256, 256>>>(Wq, wqh, wql, WN4);
    split_kernel<<<(WN4+255)/256, 256>>>(Wk, wkh, wkl, WN4);
    split_kernel<<<(WN4+255)/256, 256>>>(Wv, wvh, wvl, WN4);
    split_kernel<<<(WN4+255)/256, 256>>>(Wo, woh, wol, WN4);
    rope_table_kernel<<<(NB*NSEQ*DH + 255)/256, 256>>>(rope);

    qkv_mma<<<dim3(MROWS/128, 12), 256, 2*4*TS*2>>>();
    attn_mma<<<dim3(NB*HEADS, NSEQ/128), 256, 2*4*AS*2>>>(hsc);
    outproj_mma<<<dim3(MROWS/128, 4), 256, 2*4*TS*2>>>(bo);
    ln_kernel<<<MROWS, 128>>>(ln_g, ln_b, ls, out);
}

// round 12
// speedup vs baseline: 3.5504x; 1.0022x over previous
#include <cuda_runtime.h>
#include <cuda_bf16.h>
#include <cstdint>
#include <math.h>

#define HEADS   8
#define DH      64
#define DIM     512
#define NSEQ    2048
#define NB      4
#define MROWS   (NB*NSEQ)          // 8192
#define QSCALE  0.125f             // dh^-0.5
#define ASTRIDE 40                 // padded smem row stride (elems); 80B
#define KSTR    72                 // attention tile stride; 144B
#define TS      (128*ASTRIDE)      // GEMM tile elems (5120)
#define AS      (64*KSTR)          // attn tile elems (4608)

// -------- scratch (device globals; no allocation allowed) --------
__device__ __nv_bfloat16 g_xh[MROWS*DIM];
__device__ __nv_bfloat16 g_xl[MROWS*DIM];
__device__ __nv_bfloat16 g_wqh[DIM*DIM], g_wql[DIM*DIM];
__device__ __nv_bfloat16 g_wkh[DIM*DIM], g_wkl[DIM*DIM];
__device__ __nv_bfloat16 g_wvh[DIM*DIM], g_wvl[DIM*DIM];
__device__ __nv_bfloat16 g_woh[DIM*DIM], g_wol[DIM*DIM];
__device__ __nv_bfloat16 g_qh[NB*HEADS*NSEQ*DH];   // [b,h,n,d]
__device__ __nv_bfloat16 g_ql[NB*HEADS*NSEQ*DH];
__device__ __nv_bfloat16 g_kh[NB*HEADS*NSEQ*DH];
__device__ __nv_bfloat16 g_kl[NB*HEADS*NSEQ*DH];
__device__ __nv_bfloat16 g_vth[NB*HEADS*DH*NSEQ];  // [b,h,d,n]
__device__ __nv_bfloat16 g_vtl[NB*HEADS*DH*NSEQ];
__device__ __nv_bfloat16 g_aoh[MROWS*DIM];
__device__ __nv_bfloat16 g_aol[MROWS*DIM];
__device__ float g_y[MROWS*DIM];
__device__ float g_cos[NB*NSEQ*DH];
__device__ float g_sin[NB*NSEQ*DH];

// ============================================================
// helpers
// ============================================================
__device__ __forceinline__ void mma16816(float* c, const uint32_t* a, const uint32_t* b) {
    asm volatile(
        "mma.sync.aligned.m16n8k16.row.col.f32.bf16.bf16.f32 "
        "{%0,%1,%2,%3}, {%4,%5,%6,%7}, {%8,%9}, {%0,%1,%2,%3};"
        : "+f"(c[0]), "+f"(c[1]), "+f"(c[2]), "+f"(c[3])
        : "r"(a[0]), "r"(a[1]), "r"(a[2]), "r"(a[3]), "r"(b[0]), "r"(b[1]));
}

__device__ __forceinline__ void ldsm4(uint32_t* r, uint32_t addr) {
    asm volatile("ldmatrix.sync.aligned.m8n8.x4.shared.b16 {%0,%1,%2,%3}, [%4];"
        : "=r"(r[0]), "=r"(r[1]), "=r"(r[2]), "=r"(r[3]) : "r"(addr));
}

__device__ __forceinline__ uint32_t su32(const void* p) {
    uint32_t a;
    asm("{ .reg .u64 t; cvta.to.shared.u64 t, %1; cvt.u32.u64 %0, t; }"
        : "=r"(a) : "l"(p));
    return a;
}
#define CPA(dst, src) asm volatile("cp.async.cg.shared.global [%0], [%1], 16;" :: "r"(dst), "l"(src))
#define CPC()         asm volatile("cp.async.commit_group;")
#define CPW(n)        asm volatile("cp.async.wait_group %0;" :: "n"(n))

__device__ __forceinline__ void split4(float4 v, uint2& h, uint2& l) {
    __nv_bfloat162 ha = __floats2bfloat162_rn(v.x, v.y);
    __nv_bfloat162 hb = __floats2bfloat162_rn(v.z, v.w);
    float rx = v.x - __bfloat162float(ha.x);
    float ry = v.y - __bfloat162float(ha.y);
    float rz = v.z - __bfloat162float(hb.x);
    float rw = v.w - __bfloat162float(hb.y);
    __nv_bfloat162 la = __floats2bfloat162_rn(rx, ry);
    __nv_bfloat162 lb = __floats2bfloat162_rn(rz, rw);
    h.x = *(uint32_t*)&ha; h.y = *(uint32_t*)&hb;
    l.x = *(uint32_t*)&la; l.y = *(uint32_t*)&lb;
}
__device__ __forceinline__ void split2(float a, float b, uint32_t& h, uint32_t& l) {
    __nv_bfloat162 hh = __floats2bfloat162_rn(a, b);
    float ra = a - __bfloat162float(hh.x);
    float rb = b - __bfloat162float(hh.y);
    __nv_bfloat162 ll = __floats2bfloat162_rn(ra, rb);
    h = *(uint32_t*)&hh; l = *(uint32_t*)&ll;
}

// ============================================================
__global__ void split_kernel(const float* __restrict__ src,
                             __nv_bfloat16* __restrict__ dh,
                             __nv_bfloat16* __restrict__ dl, int n4)
{
    int i = blockIdx.x * blockDim.x + threadIdx.x;
    if (i < n4) {
        float4 v = ((const float4*)src)[i];
        uint2 h, l; split4(v, h, l);
        ((uint2*)dh)[i] = h;
        ((uint2*)dl)[i] = l;
    }
}

__global__ void rope_table_kernel(const float* __restrict__ rope)
{
    int i = blockIdx.x * blockDim.x + threadIdx.x;
    if (i < NB*NSEQ*DH) {
        float f = rope[i];
        g_cos[i] = cosf(f);
        g_sin[i] = sinf(f);
    }
}

// ============================================================
// Kernel 1: QKV projection, cp.async double-buffered + ldmatrix frags
// grid: (64, 12), block 256; dyn smem 81920 B
// ============================================================
__global__ void __launch_bounds__(256) qkv_mma()
{
    extern __shared__ __align__(16) __nv_bfloat16 dsm[];
    const uint32_t sbase = su32(dsm);

    const int tid = threadIdx.x, lid = tid & 31, wid = tid >> 5;
    const int wm = wid >> 2, wn = wid & 3;
    const int m0   = blockIdx.x * 128;
    const int by   = blockIdx.y;
    const int mat  = by >> 2;
    const int col0 = (by & 3) * 128;
    const __nv_bfloat16* Wh = (mat == 0) ? g_wqh : ((mat == 1) ? g_wkh : g_wvh);
    const __nv_bfloat16* Wl = (mat == 0) ? g_wql : ((mat == 1) ? g_wkl : g_wvl);

    const int g  = lid >> 2;
    const int t2 = (lid & 3) * 2;
    // ldmatrix per-lane fragment offset (bytes)
    const uint32_t fofsG = (uint32_t)((lid & 15)*ASTRIDE + ((lid >> 4) & 1)*8) * 2;

    // staging geometry
    const int srow = tid >> 1;
    const int sseg = (tid & 1) * 16;
    const int sm  = m0 + srow, sn = sm & 2047, sb2 = sm >> 11;
    const size_t axo = (size_t)(sn*NB + sb2)*DIM + sseg;
    const size_t bwo = (size_t)(col0 + srow)*DIM + sseg;
    const uint32_t doff = (uint32_t)(srow*ASTRIDE + sseg) * 2;

    #define QKV_STAGE(kk, buf) do { \
        uint32_t b0 = sbase + (uint32_t)(buf)*(4*TS*2) + doff; \
        const __nv_bfloat16* pa = g_xh + axo + (kk); \
        const __nv_bfloat16* pb = g_xl + axo + (kk); \
        const __nv_bfloat16* pc = Wh + bwo + (kk); \
        const __nv_bfloat16* pd = Wl + bwo + (kk); \
        CPA(b0,            pa); CPA(b0 + 16,            pa + 8); \
        CPA(b0 + TS*2,     pb); CPA(b0 + TS*2 + 16,     pb + 8); \
        CPA(b0 + 2*TS*2,   pc); CPA(b0 + 2*TS*2 + 16,   pc + 8); \
        CPA(b0 + 3*TS*2,   pd); CPA(b0 + 3*TS*2 + 16,   pd + 8); \
    } while (0)

    float c[4][4][4];
    #pragma unroll
    for (int i = 0; i < 4; i++)
        #pragma unroll
        for (int j = 0; j < 4; j++)
            #pragma unroll
            for (int q = 0; q < 4; q++) c[i][j][q] = 0.f;

    QKV_STAGE(0, 0); CPC();

    for (int kc = 0; kc < 16; kc++) {
        if (kc + 1 < 16) { QKV_STAGE((kc+1)*32, (kc+1)&1); CPC(); CPW(1); }
        else             { CPW(0); }
        __syncthreads();

        const uint32_t bufb = sbase + (uint32_t)(kc&1)*(4*TS*2);

        #pragma unroll
        for (int ks = 0; ks < 2; ks++) {
            const uint32_t kB = (uint32_t)(ks*16)*2;
            uint32_t bh[4][2], bl[4][2];
            #pragma unroll
            for (int np = 0; np < 2; np++) {
                uint32_t r[4];
                uint32_t ba = bufb + (uint32_t)(2*TS*2) +
                              (uint32_t)((wn*32 + np*16)*ASTRIDE)*2 + kB + fofsG;
                ldsm4(r, ba);
                bh[np*2][0]=r[0]; bh[np*2+1][0]=r[1]; bh[np*2][1]=r[2]; bh[np*2+1][1]=r[3];
                ldsm4(r, ba + (uint32_t)(TS*2));
                bl[np*2][0]=r[0]; bl[np*2+1][0]=r[1]; bl[np*2][1]=r[2]; bl[np*2+1][1]=r[3];
            }
            #pragma unroll
            for (int mt = 0; mt < 4; mt++) {
                uint32_t aa = bufb + (uint32_t)((wm*64 + mt*16)*ASTRIDE)*2 + kB + fofsG;
                uint32_t ah[4], al[4];
                ldsm4(ah, aa);
                ldsm4(al, aa + (uint32_t)(TS*2));
                #pragma unroll
                for (int nt = 0; nt < 4; nt++) {
                    mma16816(c[mt][nt], ah, bh[nt]);
                    mma16816(c[mt][nt], ah, bl[nt]);
                    mma16816(c[mt][nt], al, bh[nt]);
                }
            }
        }
        __syncthreads();
    }

    // ---- epilogue: RoPE (+qscale), split, scatter ----
    #pragma unroll
    for (int mt = 0; mt < 4; mt++) {
        #pragma unroll
        for (int half = 0; half < 2; half++) {
            int m = m0 + wm*64 + mt*16 + g + half*8;
            int n = m & 2047, b = m >> 11;
            #pragma unroll
            for (int nt = 0; nt < 4; nt++) {
                int gc = col0 + wn*32 + nt*8 + t2;
                int h = gc >> 6, d = gc & 63;
                float v0 = c[mt][nt][half*2 + 0];
                float v1 = c[mt][nt][half*2 + 1];
                if (mat < 2) {
                    size_t fo = ((size_t)(b*NSEQ + n))*DH + d;
                    float co0 = g_cos[fo], co1 = g_cos[fo+1];
                    float si0 = g_sin[fo], si1 = g_sin[fo+1];
                    float o0 = v0*co0 - v1*si0;
                    float o1 = v1*co1 + v0*si1;
                    if (mat == 0) { o0 *= QSCALE; o1 *= QSCALE; }
                    uint32_t hh, ll; split2(o0, o1, hh, ll);
                    size_t off = (((size_t)(b*HEADS + h))*NSEQ + n)*DH + d;
                    if (mat == 0) {
                        *(uint32_t*)&g_qh[off] = hh;
                        *(uint32_t*)&g_ql[off] = ll;
                    } else {
                        *(uint32_t*)&g_kh[off] = hh;
                        *(uint32_t*)&g_kl[off] = ll;
                    }
                } else {
                    uint32_t hh, ll; split2(v0, v1, hh, ll);
                    __nv_bfloat162 h2 = *(__nv_bfloat162*)&hh;
                    __nv_bfloat162 l2 = *(__nv_bfloat162*)&ll;
                    size_t base = ((size_t)(b*HEADS + h))*DH*NSEQ;
                    g_vth[base + (size_t)d*NSEQ + n]     = h2.x;
                    g_vth[base + (size_t)(d+1)*NSEQ + n] = h2.y;
                    g_vtl[base + (size_t)d*NSEQ + n]     = l2.x;
                    g_vtl[base + (size_t)(d+1)*NSEQ + n] = l2.y;
                }
            }
        }
    }
}

// ============================================================
// Kernel 2: causal flash attention, BM=128, cp.async + ldmatrix frags
// grid: (32 bh, 16 qtiles DESC), block 256; dyn smem 73728 B
// ============================================================
__global__ void __launch_bounds__(256) attn_mma(const float* __restrict__ head_scale)
{
    extern __shared__ __align__(16) __nv_bfloat16 dsm[];
    const uint32_t sbase = su32(dsm);

    const int tid = threadIdx.x, lid = tid & 31, wid = tid >> 5;
    const int bh = blockIdx.x;
    const int qt = (NSEQ/128 - 1) - blockIdx.y;    // longest first
    const int q0 = qt * 128;
    const int g  = lid >> 2;
    const int t2 = (lid & 3) * 2;
    const int kmax = 2*qt + 2;
    const uint32_t fofsA = (uint32_t)((lid & 15)*KSTR + ((lid >> 4) & 1)*8) * 2;

    const size_t hb_nd = (size_t)bh * NSEQ * DH;
    const size_t hb_dn = (size_t)bh * DH * NSEQ;

    // staging geometry
    const int srow = tid >> 2;
    const int sseg = (tid & 3) * 16;
    const uint32_t doff = (uint32_t)(srow*KSTR + sseg) * 2;
    const __nv_bfloat16* kh_s = g_kh + hb_nd + (size_t)srow*DH + sseg;
    const __nv_bfloat16* kl_s = g_kl + hb_nd + (size_t)srow*DH + sseg;
    const __nv_bfloat16* vh_s = g_vth + hb_dn + (size_t)srow*NSEQ + sseg;
    const __nv_bfloat16* vl_s = g_vtl + hb_dn + (size_t)srow*NSEQ + sseg;

    #define ATTN_STAGE(k0v, buf) do { \
        uint32_t b0 = sbase + (uint32_t)(buf)*(4*AS*2) + doff; \
        const __nv_bfloat16* pa = kh_s + (size_t)(k0v)*DH; \
        const __nv_bfloat16* pb = kl_s + (size_t)(k0v)*DH; \
        const __nv_bfloat16* pc = vh_s + (k0v); \
        const __nv_bfloat16* pd = vl_s + (k0v); \
        CPA(b0,          pa); CPA(b0 + 16,          pa + 8); \
        CPA(b0 + AS*2,   pb); CPA(b0 + AS*2 + 16,   pb + 8); \
        CPA(b0 + 2*AS*2, pc); CPA(b0 + 2*AS*2 + 16, pc + 8); \
        CPA(b0 + 3*AS*2, pd); CPA(b0 + 3*AS*2 + 16, pd + 8); \
    } while (0)

    // ---- load Q fragments, hi & lo ----
    uint32_t qh[4][4], ql[4][4];
    {
        const __nv_bfloat16* qhp = g_qh + hb_nd + (size_t)(q0 + wid*16)*DH;
        const __nv_bfloat16* qlp = g_ql + hb_nd + (size_t)(q0 + wid*16)*DH;
        #pragma unroll
        for (int kt = 0; kt < 4; kt++) {
            int kc = kt*16 + t2;
            qh[kt][0] = *(const uint32_t*)&qhp[(size_t)g*DH + kc];
            qh[kt][1] = *(const uint32_t*)&qhp[(size_t)(g+8)*DH + kc];
            qh[kt][2] = *(const uint32_t*)&qhp[(size_t)g*DH + kc + 8];
            qh[kt][3] = *(const uint32_t*)&qhp[(size_t)(g+8)*DH + kc + 8];
            ql[kt][0] = *(const uint32_t*)&qlp[(size_t)g*DH + kc];
            ql[kt][1] = *(const uint32_t*)&qlp[(size_t)(g+8)*DH + kc];
            ql[kt][2] = *(const uint32_t*)&qlp[(size_t)g*DH + kc + 8];
            ql[kt][3] = *(const uint32_t*)&qlp[(size_t)(g+8)*DH + kc + 8];
        }
    }

    float m_i[2] = {-1e30f, -1e30f};
    float l_i[2] = {0.f, 0.f};
    float o[8][4];
    #pragma unroll
    for (int dt = 0; dt < 8; dt++)
        #pragma unroll
        for (int q = 0; q < 4; q++) o[dt][q] = 0.f;

    ATTN_STAGE(0, 0); CPC();

    for (int kb = 0; kb < kmax; kb++) {
        const int k0 = kb * 64;
        if (kb + 1 < kmax) { ATTN_STAGE((kb+1)*64, (kb+1)&1); CPC(); CPW(1); }
        else               { CPW(0); }
        __syncthreads();

        const uint32_t kbufb = sbase + (uint32_t)(kb&1)*(4*AS*2);

        if (k0 <= q0 + wid*16 + 15) {      // warp has unmasked work (uniform per warp)
            // ---- S = Q K^T (3-term), ldmatrix over j-pairs ----
            float sc[8][4];
            #pragma unroll
            for (int j = 0; j < 8; j++)
                #pragma unroll
                for (int q = 0; q < 4; q++) sc[j][q] = 0.f;

            #pragma unroll
            for (int jp = 0; jp < 4; jp++) {
                #pragma unroll
                for (int kt = 0; kt < 4; kt++) {
                    uint32_t ka = kbufb + (uint32_t)((jp*16)*KSTR + kt*16)*2 + fofsA;
                    uint32_t rh[4], rl[4];
                    ldsm4(rh, ka);
                    ldsm4(rl, ka + (uint32_t)(AS*2));
                    uint32_t b0h[2] = {rh[0], rh[2]}, b1h[2] = {rh[1], rh[3]};
                    uint32_t b0l[2] = {rl[0], rl[2]}, b1l[2] = {rl[1], rl[3]};
                    mma16816(sc[2*jp],   qh[kt], b0h);
                    mma16816(sc[2*jp],   qh[kt], b0l);
                    mma16816(sc[2*jp],   ql[kt], b0h);
                    mma16816(sc[2*jp+1], qh[kt], b1h);
                    mma16816(sc[2*jp+1], qh[kt], b1l);
                    mma16816(sc[2*jp+1], ql[kt], b1h);
                }
            }

            // ---- causal mask (near-diagonal blocks only) ----
            if (k0 + 63 > q0 + wid*16) {
                const int r0 = q0 + wid*16 + g;
                #pragma unroll
                for (int j = 0; j < 8; j++) {
                    int col = k0 + j*8 + t2;
                    if (col     > r0)   sc[j][0] = -1e30f;
                    if (col + 1 > r0)   sc[j][1] = -1e30f;
                    if (col     > r0+8) sc[j][2] = -1e30f;
                    if (col + 1 > r0+8) sc[j][3] = -1e30f;
                }
            }

            // ---- online softmax ----
            float alpha[2];
            #pragma unroll
            for (int r = 0; r < 2; r++) {
                float mx = -1e30f;
                #pragma unroll
                for (int j = 0; j < 8; j++)
                    mx = fmaxf(mx, fmaxf(sc[j][2*r], sc[j][2*r+1]));
                mx = fmaxf(mx, __shfl_xor_sync(0xffffffffu, mx, 1));
                mx = fmaxf(mx, __shfl_xor_sync(0xffffffffu, mx, 2));
                float mnew = fmaxf(m_i[r], mx);
                alpha[r] = __expf(m_i[r] - mnew);
                m_i[r] = mnew;
                float rs = 0.f;
                #pragma unroll
                for (int j = 0; j < 8; j++) {
                    float p0 = __expf(sc[j][2*r]   - mnew);
                    float p1 = __expf(sc[j][2*r+1] - mnew);
                    sc[j][2*r] = p0; sc[j][2*r+1] = p1;
                    rs += p0 + p1;
                }
                rs += __shfl_xor_sync(0xffffffffu, rs, 1);
                rs += __shfl_xor_sync(0xffffffffu, rs, 2);
                l_i[r] = l_i[r]*alpha[r] + rs;
            }

            #pragma unroll
            for (int dt = 0; dt < 8; dt++) {
                o[dt][0] *= alpha[0]; o[dt][1] *= alpha[0];
                o[dt][2] *= alpha[1]; o[dt][3] *= alpha[1];
            }

            // ---- P -> A-fragments (hi/lo) ----
            uint32_t ph[4][4], pl[4][4];
            #pragma unroll
            for (int kt = 0; kt < 4; kt++) {
                split2(sc[2*kt][0],   sc[2*kt][1],   ph[kt][0], pl[kt][0]);
                split2(sc[2*kt][2],   sc[2*kt][3],   ph[kt][1], pl[kt][1]);
                split2(sc[2*kt+1][0], sc[2*kt+1][1], ph[kt][2], pl[kt][2]);
                split2(sc[2*kt+1][2], sc[2*kt+1][3], ph[kt][3], pl[kt][3]);
            }

            // ---- O += P V (3-term), ldmatrix over d-pairs ----
            #pragma unroll
            for (int dp = 0; dp < 4; dp++) {
                #pragma unroll
                for (int kt = 0; kt < 4; kt++) {
                    uint32_t va = kbufb + (uint32_t)(2*AS*2) +
                                  (uint32_t)((dp*16)*KSTR + kt*16)*2 + fofsA;
                    uint32_t rh[4], rl[4];
                    ldsm4(rh, va);
                    ldsm4(rl, va + (uint32_t)(AS*2));
                    uint32_t b0h[2] = {rh[0], rh[2]}, b1h[2] = {rh[1], rh[3]};
                    uint32_t b0l[2] = {rl[0], rl[2]}, b1l[2] = {rl[1], rl[3]};
                    mma16816(o[2*dp],   ph[kt], b0h);
                    mma16816(o[2*dp],   ph[kt], b0l);
                    mma16816(o[2*dp],   pl[kt], b0h);
                    mma16816(o[2*dp+1], ph[kt], b1h);
                    mma16816(o[2*dp+1], ph[kt], b1l);
                    mma16816(o[2*dp+1], pl[kt], b1h);
                }
            }
        }
        __syncthreads();
    }

    // ---- epilogue ----
    const int b = bh >> 3, h = bh & 7;
    const float hs = head_scale[h];
    #pragma unroll
    for (int r = 0; r < 2; r++) {
        const float inv = hs / l_i[r];
        const int n = q0 + wid*16 + g + r*8;
        __nv_bfloat16* dsth = g_aoh + ((size_t)(b*NSEQ + n))*DIM + h*DH;
        __nv_bfloat16* dstl = g_aol + ((size_t)(b*NSEQ + n))*DIM + h*DH;
        #pragma unroll
        for (int dt = 0; dt < 8; dt++) {
            int d = dt*8 + t2;
            uint32_t hh, ll;
            split2(o[dt][2*r]*inv, o[dt][2*r+1]*inv, hh, ll);
            *(uint32_t*)&dsth[d] = hh;
            *(uint32_t*)&dstl[d] = ll;
        }
    }
}

// ============================================================
// Kernel 3: output projection, cp.async + ldmatrix frags
// grid: (64, 4), block 256; dyn smem 81920 B
// ============================================================
__global__ void __launch_bounds__(256) outproj_mma(const float* __restrict__ bo)
{
    extern __shared__ __align__(16) __nv_bfloat16 dsm[];
    const uint32_t sbase = su32(dsm);

    const int tid = threadIdx.x, lid = tid & 31, wid = tid >> 5;
    const int wm = wid >> 2, wn = wid & 3;
    const int m0   = blockIdx.x * 128;
    const int col0 = blockIdx.y * 128;
    const int g  = lid >> 2;
    const int t2 = (lid & 3) * 2;
    const uint32_t fofsG = (uint32_t)((lid & 15)*ASTRIDE + ((lid >> 4) & 1)*8) * 2;

    const int srow = tid >> 1;
    const int sseg = (tid & 1) * 16;
    const size_t aoo = (size_t)(m0 + srow)*DIM + sseg;
    const size_t woo = (size_t)(col0 + srow)*DIM + sseg;
    const uint32_t doff = (uint32_t)(srow*ASTRIDE + sseg) * 2;

    #define OP_STAGE(kk, buf) do { \
        uint32_t b0 = sbase + (uint32_t)(buf)*(4*TS*2) + doff; \
        const __nv_bfloat16* pa = g_aoh + aoo + (kk); \
        const __nv_bfloat16* pb = g_aol + aoo + (kk); \
        const __nv_bfloat16* pc = g_woh + woo + (kk); \
        const __nv_bfloat16* pd = g_wol + woo + (kk); \
        CPA(b0,          pa); CPA(b0 + 16,          pa + 8); \
        CPA(b0 + TS*2,   pb); CPA(b0 + TS*2 + 16,   pb + 8); \
        CPA(b0 + 2*TS*2, pc); CPA(b0 + 2*TS*2 + 16, pc + 8); \
        CPA(b0 + 3*TS*2, pd); CPA(b0 + 3*TS*2 + 16, pd + 8); \
    } while (0)

    float c[4][4][4];
    #pragma unroll
    for (int i = 0; i < 4; i++)
        #pragma unroll
        for (int j = 0; j < 4; j++)
            #pragma unroll
            for (int q = 0; q < 4; q++) c[i][j][q] = 0.f;

    OP_STAGE(0, 0); CPC();

    for (int kc = 0; kc < 16; kc++) {
        if (kc + 1 < 16) { OP_STAGE((kc+1)*32, (kc+1)&1); CPC(); CPW(1); }
        else             { CPW(0); }
        __syncthreads();

        const uint32_t bufb = sbase + (uint32_t)(kc&1)*(4*TS*2);

        #pragma unroll
        for (int ks = 0; ks < 2; ks++) {
            const uint32_t kB = (uint32_t)(ks*16)*2;
            uint32_t bh[4][2], bl[4][2];
            #pragma unroll
            for (int np = 0; np < 2; np++) {
                uint32_t r[4];
                uint32_t ba = bufb + (uint32_t)(2*TS*2) +
                              (uint32_t)((wn*32 + np*16)*ASTRIDE)*2 + kB + fofsG;
                ldsm4(r, ba);
                bh[np*2][0]=r[0]; bh[np*2+1][0]=r[1]; bh[np*2][1]=r[2]; bh[np*2+1][1]=r[3];
                ldsm4(r, ba + (uint32_t)(TS*2));
                bl[np*2][0]=r[0]; bl[np*2+1][0]=r[1]; bl[np*2][1]=r[2]; bl[np*2+1][1]=r[3];
            }
            #pragma unroll
            for (int mt = 0; mt < 4; mt++) {
                uint32_t aa = bufb + (uint32_t)((wm*64 + mt*16)*ASTRIDE)*2 + kB + fofsG;
                uint32_t ah[4], al[4];
                ldsm4(ah, aa);
                ldsm4(al, aa + (uint32_t)(TS*2));
                #pragma unroll
                for (int nt = 0; nt < 4; nt++) {
                    mma16816(c[mt][nt], ah, bh[nt]);
                    mma16816(c[mt][nt], ah, bl[nt]);
                    mma16816(c[mt][nt], al, bh[nt]);
                }
            }
        }
        __syncthreads();
    }

    #pragma unroll
    for (int mt = 0; mt < 4; mt++) {
        #pragma unroll
        for (int half = 0; half < 2; half++) {
            int m = m0 + wm*64 + mt*16 + g + half*8;
            #pragma unroll
            for (int nt = 0; nt < 4; nt++) {
                int gc = col0 + wn*32 + nt*8 + t2;
                float* dst = g_y + (size_t)m*DIM + gc;
                dst[0] = c[mt][nt][half*2 + 0] + __ldg(bo + gc);
                dst[1] = c[mt][nt][half*2 + 1] + __ldg(bo + gc + 1);
            }
        }
    }
}

// ============================================================
// Kernel 4: LayerNorm + ls_scale + transpose
// ============================================================
__global__ void ln_kernel(const float* __restrict__ ln_g,
                          const float* __restrict__ ln_b,
                          const float* __restrict__ ls,
                          float* __restrict__ out)
{
    __shared__ float red[8];
    const int m = blockIdx.x;
    const int b = m >> 11, n = m & 2047;
    const int tid = threadIdx.x;
    float4 v = ((const float4*)(g_y + (size_t)m*DIM))[tid];
    float s  = v.x + v.y + v.z + v.w;
    float sq = v.x*v.x + v.y*v.y + v.z*v.z + v.w*v.w;
    #pragma unroll
    for (int off = 16; off > 0; off >>= 1) {
        s  += __shfl_xor_sync(0xffffffffu, s,  off);
        sq += __shfl_xor_sync(0xffffffffu, sq, off);
    }
    const int wid = tid >> 5;
    if ((tid & 31) == 0) { red[wid] = s; red[wid + 4] = sq; }
    __syncthreads();
    s  = red[0] + red[1] + red[2] + red[3];
    sq = red[4] + red[5] + red[6] + red[7];
    float mu  = s * (1.f/DIM);
    float var = sq * (1.f/DIM) - mu*mu;
    float r   = rsqrtf(var + 1e-5f);

    float* dst = out + (size_t)(n*NB + b)*DIM;
    const int d0 = tid * 4;
    float vv[4] = {v.x, v.y, v.z, v.w};
    #pragma unroll
    for (int q = 0; q < 4; q++) {
        int d = d0 + q;
        dst[d] = ls[d] * ((vv[q] - mu) * r * ln_g[d] + ln_b[d]);
    }
}

// ============================================================
extern "C" void kernel_launch(void* const* d_in, const int* in_sizes, int n_in,
                              void* d_out, int out_size)
{
    const float* x    = (const float*)d_in[0];
    const float* rope = (const float*)d_in[1];
    const float* Wq   = (const float*)d_in[2];
    const float* Wk   = (const float*)d_in[3];
    const float* Wv   = (const float*)d_in[4];
    const float* Wo   = (const float*)d_in[5];
    const float* bo   = (const float*)d_in[6];
    const float* ln_g = (const float*)d_in[7];
    const float* ln_b = (const float*)d_in[8];
    const float* hsc  = (const float*)d_in[9];
    const float* ls   = (const float*)d_in[10];
    float* out = (float*)d_out;

    __nv_bfloat16 *xh, *xl, *wqh, *wql, *wkh, *wkl, *wvh, *wvl, *woh, *wol;
    cudaGetSymbolAddress((void**)&xh,  g_xh);  cudaGetSymbolAddress((void**)&xl,  g_xl);
    cudaGetSymbolAddress((void**)&wqh, g_wqh); cudaGetSymbolAddress((void**)&wql, g_wql);
    cudaGetSymbolAddress((void**)&wkh, g_wkh); cudaGetSymbolAddress((void**)&wkl, g_wkl);
    cudaGetSymbolAddress((void**)&wvh, g_wvh); cudaGetSymbolAddress((void**)&wvl, g_wvl);
    cudaGetSymbolAddress((void**)&woh, g_woh); cudaGetSymbolAddress((void**)&wol, g_wol);

    static bool attr_done = false;
    if (!attr_done) {
        cudaFuncSetAttribute(qkv_mma,     cudaFuncAttributeMaxDynamicSharedMemorySize, 2*4*TS*2);
        cudaFuncSetAttribute(outproj_mma, cudaFuncAttributeMaxDynamicSharedMemorySize, 2*4*TS*2);
        cudaFuncSetAttribute(attn_mma,    cudaFuncAttributeMaxDynamicSharedMemorySize, 2*4*AS*2);
        attr_done = true;
    }

    const int XN4 = MROWS*DIM/4, WN4 = DIM*DIM/4;
    split_kernel<<<(XN4+255)/256, 256>>>(x,  xh,  xl,  XN4);
    split_kernel<<<(WN4+255)/256, 256>>>(Wq, wqh, wql, WN4);
    split_kernel<<<(WN4+255)/256, 256>>>(Wk, wkh, wkl, WN4);
    split_kernel<<<(WN4+255)/256, 256>>>(Wv, wvh, wvl, WN4);
    split_kernel<<<(WN4+255)/256, 256>>>(Wo, woh, wol, WN4);
    rope_table_kernel<<<(NB*NSEQ*DH + 255)/256, 256>>>(rope);

    qkv_mma<<<dim3(MROWS/128, 12), 256, 2*4*TS*2>>>();
    attn_mma<<<dim3(NB*HEADS, NSEQ/128), 256, 2*4*AS*2>>>(hsc);
    outproj_mma<<<dim3(MROWS/128, 4), 256, 2*4*TS*2>>>(bo);
    ln_kernel<<<MROWS, 128>>>(ln_g, ln_b, ls, out);
}

// round 13
// speedup vs baseline: 4.9883x; 1.4050x over previous
#include <cuda_runtime.h>
#include <cuda_fp16.h>
#include <cstdint>
#include <math.h>

#define HEADS   8
#define DH      64
#define DIM     512
#define NSEQ    2048
#define NB      4
#define MROWS   (NB*NSEQ)          // 8192
#define QSCALE  0.125f             // dh^-0.5
#define ASTRIDE 40                 // padded smem row stride (elems); 80B
#define KSTR    72                 // attention tile stride; 144B
#define TS      (128*ASTRIDE)      // GEMM tile elems (5120)
#define AS      (64*KSTR)          // attn tile elems (4608)

// -------- scratch (device globals; no allocation allowed) --------
__device__ __half g_xh[MROWS*DIM];
__device__ __half g_xl[MROWS*DIM];
__device__ __half g_wqh[DIM*DIM];
__device__ __half g_wkh[DIM*DIM];
__device__ __half g_wvh[DIM*DIM];
__device__ __half g_woh[DIM*DIM];
__device__ __half g_qh[NB*HEADS*NSEQ*DH];   // [b,h,n,d] hi
__device__ __half g_ql[NB*HEADS*NSEQ*DH];   // lo
__device__ __half g_kh[NB*HEADS*NSEQ*DH];   // hi only
__device__ __half g_vth[NB*HEADS*DH*NSEQ];  // [b,h,d,n], hi only
__device__ __half g_aoh[MROWS*DIM];
__device__ __half g_aol[MROWS*DIM];
__device__ float g_y[MROWS*DIM];
__device__ float g_cos[NB*NSEQ*DH];
__device__ float g_sin[NB*NSEQ*DH];

// ============================================================
// helpers
// ============================================================
__device__ __forceinline__ void mma16816(float* c, const uint32_t* a, const uint32_t* b) {
    asm volatile(
        "mma.sync.aligned.m16n8k16.row.col.f32.f16.f16.f32 "
        "{%0,%1,%2,%3}, {%4,%5,%6,%7}, {%8,%9}, {%0,%1,%2,%3};"
        : "+f"(c[0]), "+f"(c[1]), "+f"(c[2]), "+f"(c[3])
        : "r"(a[0]), "r"(a[1]), "r"(a[2]), "r"(a[3]), "r"(b[0]), "r"(b[1]));
}

__device__ __forceinline__ void ldsm4(uint32_t* r, uint32_t addr) {
    asm volatile("ldmatrix.sync.aligned.m8n8.x4.shared.b16 {%0,%1,%2,%3}, [%4];"
        : "=r"(r[0]), "=r"(r[1]), "=r"(r[2]), "=r"(r[3]) : "r"(addr));
}

__device__ __forceinline__ uint32_t su32(const void* p) {
    uint32_t a;
    asm("{ .reg .u64 t; cvta.to.shared.u64 t, %1; cvt.u32.u64 %0, t; }"
        : "=r"(a) : "l"(p));
    return a;
}
#define CPA(dst, src) asm volatile("cp.async.cg.shared.global [%0], [%1], 16;" :: "r"(dst), "l"(src))
#define CPC()         asm volatile("cp.async.commit_group;")
#define CPW(n)        asm volatile("cp.async.wait_group %0;" :: "n"(n))

// fp16 hi/lo split helpers
__device__ __forceinline__ void hsplit4(float4 v, uint2& h, uint2& l) {
    __half2 ha = __floats2half2_rn(v.x, v.y);
    __half2 hb = __floats2half2_rn(v.z, v.w);
    float rx = v.x - __half2float(ha.x);
    float ry = v.y - __half2float(ha.y);
    float rz = v.z - __half2float(hb.x);
    float rw = v.w - __half2float(hb.y);
    __half2 la = __floats2half2_rn(rx, ry);
    __half2 lb = __floats2half2_rn(rz, rw);
    h.x = *(uint32_t*)&ha; h.y = *(uint32_t*)&hb;
    l.x = *(uint32_t*)&la; l.y = *(uint32_t*)&lb;
}
__device__ __forceinline__ void hsplit2(float a, float b, uint32_t& h, uint32_t& l) {
    __half2 hh = __floats2half2_rn(a, b);
    float ra = a - __half2float(hh.x);
    float rb = b - __half2float(hh.y);
    __half2 ll = __floats2half2_rn(ra, rb);
    h = *(uint32_t*)&hh; l = *(uint32_t*)&ll;
}

// ============================================================
// Kernel S1: fp32 -> fp16 hi/lo split (for x)
// ============================================================
__global__ void split_kernel(const float* __restrict__ src,
                             __half* __restrict__ dh,
                             __half* __restrict__ dl, int n4)
{
    int i = blockIdx.x * blockDim.x + threadIdx.x;
    if (i < n4) {
        float4 v = ((const float4*)src)[i];
        uint2 h, l; hsplit4(v, h, l);
        ((uint2*)dh)[i] = h;
        ((uint2*)dl)[i] = l;
    }
}

// Kernel S2: fp32 -> fp16 convert (hi only, for weights)
__global__ void tohalf_kernel(const float* __restrict__ src,
                              __half* __restrict__ dh, int n4)
{
    int i = blockIdx.x * blockDim.x + threadIdx.x;
    if (i < n4) {
        float4 v = ((const float4*)src)[i];
        __half2 a = __floats2half2_rn(v.x, v.y);
        __half2 b = __floats2half2_rn(v.z, v.w);
        uint2 o; o.x = *(uint32_t*)&a; o.y = *(uint32_t*)&b;
        ((uint2*)dh)[i] = o;
    }
}

__global__ void rope_table_kernel(const float* __restrict__ rope)
{
    int i = blockIdx.x * blockDim.x + threadIdx.x;
    if (i < NB*NSEQ*DH) {
        float f = rope[i];
        g_cos[i] = cosf(f);
        g_sin[i] = sinf(f);
    }
}

// ============================================================
// Kernel 1: QKV projection, fp16 2-term (A exact, W hi only)
// grid: (64, 12), block 256; dyn smem 2*3*TS*2 = 61440 B
// ============================================================
__global__ void __launch_bounds__(256) qkv_mma()
{
    extern __shared__ __align__(16) __half dsm[];
    const uint32_t sbase = su32(dsm);

    const int tid = threadIdx.x, lid = tid & 31, wid = tid >> 5;
    const int wm = wid >> 2, wn = wid & 3;
    const int m0   = blockIdx.x * 128;
    const int by   = blockIdx.y;
    const int mat  = by >> 2;
    const int col0 = (by & 3) * 128;
    const __half* Wh = (mat == 0) ? g_wqh : ((mat == 1) ? g_wkh : g_wvh);

    const int g  = lid >> 2;
    const int t2 = (lid & 3) * 2;
    const uint32_t fofsG = (uint32_t)((lid & 15)*ASTRIDE + ((lid >> 4) & 1)*8) * 2;

    // staging geometry: 3 arrays [Ah, Al, Bh]
    const int srow = tid >> 1;
    const int sseg = (tid & 1) * 16;
    const int sm  = m0 + srow, sn = sm & 2047, sb2 = sm >> 11;
    const size_t axo = (size_t)(sn*NB + sb2)*DIM + sseg;
    const size_t bwo = (size_t)(col0 + srow)*DIM + sseg;
    const uint32_t doff = (uint32_t)(srow*ASTRIDE + sseg) * 2;

    #define QKV_STAGE(kk, buf) do { \
        uint32_t b0 = sbase + (uint32_t)(buf)*(3*TS*2) + doff; \
        const __half* pa = g_xh + axo + (kk); \
        const __half* pb = g_xl + axo + (kk); \
        const __half* pc = Wh + bwo + (kk); \
        CPA(b0,          pa); CPA(b0 + 16,          pa + 8); \
        CPA(b0 + TS*2,   pb); CPA(b0 + TS*2 + 16,   pb + 8); \
        CPA(b0 + 2*TS*2, pc); CPA(b0 + 2*TS*2 + 16, pc + 8); \
    } while (0)

    float c[4][4][4];
    #pragma unroll
    for (int i = 0; i < 4; i++)
        #pragma unroll
        for (int j = 0; j < 4; j++)
            #pragma unroll
            for (int q = 0; q < 4; q++) c[i][j][q] = 0.f;

    QKV_STAGE(0, 0); CPC();

    for (int kc = 0; kc < 16; kc++) {
        if (kc + 1 < 16) { QKV_STAGE((kc+1)*32, (kc+1)&1); CPC(); CPW(1); }
        else             { CPW(0); }
        __syncthreads();

        const uint32_t bufb = sbase + (uint32_t)(kc&1)*(3*TS*2);

        #pragma unroll
        for (int ks = 0; ks < 2; ks++) {
            const uint32_t kB = (uint32_t)(ks*16)*2;
            uint32_t bh[4][2];
            #pragma unroll
            for (int np = 0; np < 2; np++) {
                uint32_t r[4];
                uint32_t ba = bufb + (uint32_t)(2*TS*2) +
                              (uint32_t)((wn*32 + np*16)*ASTRIDE)*2 + kB + fofsG;
                ldsm4(r, ba);
                bh[np*2][0]=r[0]; bh[np*2+1][0]=r[1]; bh[np*2][1]=r[2]; bh[np*2+1][1]=r[3];
            }
            #pragma unroll
            for (int mt = 0; mt < 4; mt++) {
                uint32_t aa = bufb + (uint32_t)((wm*64 + mt*16)*ASTRIDE)*2 + kB + fofsG;
                uint32_t ah[4], al[4];
                ldsm4(ah, aa);
                ldsm4(al, aa + (uint32_t)(TS*2));
                #pragma unroll
                for (int nt = 0; nt < 4; nt++) {
                    mma16816(c[mt][nt], ah, bh[nt]);
                    mma16816(c[mt][nt], al, bh[nt]);
                }
            }
        }
        __syncthreads();
    }

    // ---- epilogue: RoPE (+qscale), convert, scatter ----
    #pragma unroll
    for (int mt = 0; mt < 4; mt++) {
        #pragma unroll
        for (int half = 0; half < 2; half++) {
            int m = m0 + wm*64 + mt*16 + g + half*8;
            int n = m & 2047, b = m >> 11;
            #pragma unroll
            for (int nt = 0; nt < 4; nt++) {
                int gc = col0 + wn*32 + nt*8 + t2;
                int h = gc >> 6, d = gc & 63;
                float v0 = c[mt][nt][half*2 + 0];
                float v1 = c[mt][nt][half*2 + 1];
                if (mat < 2) {
                    size_t fo = ((size_t)(b*NSEQ + n))*DH + d;
                    float co0 = g_cos[fo], co1 = g_cos[fo+1];
                    float si0 = g_sin[fo], si1 = g_sin[fo+1];
                    float o0 = v0*co0 - v1*si0;
                    float o1 = v1*co1 + v0*si1;
                    size_t off = (((size_t)(b*HEADS + h))*NSEQ + n)*DH + d;
                    if (mat == 0) {
                        o0 *= QSCALE; o1 *= QSCALE;
                        uint32_t hh, ll; hsplit2(o0, o1, hh, ll);
                        *(uint32_t*)&g_qh[off] = hh;
                        *(uint32_t*)&g_ql[off] = ll;
                    } else {
                        __half2 k2 = __floats2half2_rn(o0, o1);
                        *(uint32_t*)&g_kh[off] = *(uint32_t*)&k2;
                    }
                } else {
                    size_t base = ((size_t)(b*HEADS + h))*DH*NSEQ;
                    g_vth[base + (size_t)d*NSEQ + n]     = __float2half_rn(v0);
                    g_vth[base + (size_t)(d+1)*NSEQ + n] = __float2half_rn(v1);
                }
            }
        }
    }
}

// ============================================================
// Kernel 2: causal flash attention, fp16; S = (Qh+Ql)*Kh, O = (Ph+Pl)*Vh
// grid: (32 bh, 16 qtiles DESC), block 256; dyn smem 2*2*AS*2 = 36864 B
// ============================================================
__global__ void __launch_bounds__(256) attn_mma(const float* __restrict__ head_scale)
{
    extern __shared__ __align__(16) __half dsm[];
    const uint32_t sbase = su32(dsm);

    const int tid = threadIdx.x, lid = tid & 31, wid = tid >> 5;
    const int bh = blockIdx.x;
    const int qt = (NSEQ/128 - 1) - blockIdx.y;    // longest first
    const int q0 = qt * 128;
    const int g  = lid >> 2;
    const int t2 = (lid & 3) * 2;
    const int kmax = 2*qt + 2;
    const uint32_t fofsA = (uint32_t)((lid & 15)*KSTR + ((lid >> 4) & 1)*8) * 2;

    const size_t hb_nd = (size_t)bh * NSEQ * DH;
    const size_t hb_dn = (size_t)bh * DH * NSEQ;

    // staging geometry: 2 arrays [Kh, Vh]
    const int srow = tid >> 2;
    const int sseg = (tid & 3) * 16;
    const uint32_t doff = (uint32_t)(srow*KSTR + sseg) * 2;
    const __half* kh_s = g_kh + hb_nd + (size_t)srow*DH + sseg;
    const __half* vh_s = g_vth + hb_dn + (size_t)srow*NSEQ + sseg;

    #define ATTN_STAGE(k0v, buf) do { \
        uint32_t b0 = sbase + (uint32_t)(buf)*(2*AS*2) + doff; \
        const __half* pa = kh_s + (size_t)(k0v)*DH; \
        const __half* pc = vh_s + (k0v); \
        CPA(b0,        pa); CPA(b0 + 16,        pa + 8); \
        CPA(b0 + AS*2, pc); CPA(b0 + AS*2 + 16, pc + 8); \
    } while (0)

    // ---- load Q fragments, hi & lo ----
    uint32_t qh[4][4], ql[4][4];
    {
        const __half* qhp = g_qh + hb_nd + (size_t)(q0 + wid*16)*DH;
        const __half* qlp = g_ql + hb_nd + (size_t)(q0 + wid*16)*DH;
        #pragma unroll
        for (int kt = 0; kt < 4; kt++) {
            int kc = kt*16 + t2;
            qh[kt][0] = *(const uint32_t*)&qhp[(size_t)g*DH + kc];
            qh[kt][1] = *(const uint32_t*)&qhp[(size_t)(g+8)*DH + kc];
            qh[kt][2] = *(const uint32_t*)&qhp[(size_t)g*DH + kc + 8];
            qh[kt][3] = *(const uint32_t*)&qhp[(size_t)(g+8)*DH + kc + 8];
            ql[kt][0] = *(const uint32_t*)&qlp[(size_t)g*DH + kc];
            ql[kt][1] = *(const uint32_t*)&qlp[(size_t)(g+8)*DH + kc];
            ql[kt][2] = *(const uint32_t*)&qlp[(size_t)g*DH + kc + 8];
            ql[kt][3] = *(const uint32_t*)&qlp[(size_t)(g+8)*DH + kc + 8];
        }
    }

    float m_i[2] = {-1e30f, -1e30f};
    float l_i[2] = {0.f, 0.f};
    float o[8][4];
    #pragma unroll
    for (int dt = 0; dt < 8; dt++)
        #pragma unroll
        for (int q = 0; q < 4; q++) o[dt][q] = 0.f;

    ATTN_STAGE(0, 0); CPC();

    for (int kb = 0; kb < kmax; kb++) {
        const int k0 = kb * 64;
        if (kb + 1 < kmax) { ATTN_STAGE((kb+1)*64, (kb+1)&1); CPC(); CPW(1); }
        else               { CPW(0); }
        __syncthreads();

        const uint32_t kbufb = sbase + (uint32_t)(kb&1)*(2*AS*2);

        if (k0 <= q0 + wid*16 + 15) {      // warp has unmasked work
            // ---- S = Q K^T (2-term, Q exact) ----
            float sc[8][4];
            #pragma unroll
            for (int j = 0; j < 8; j++)
                #pragma unroll
                for (int q = 0; q < 4; q++) sc[j][q] = 0.f;

            #pragma unroll
            for (int jp = 0; jp < 4; jp++) {
                #pragma unroll
                for (int kt = 0; kt < 4; kt++) {
                    uint32_t ka = kbufb + (uint32_t)((jp*16)*KSTR + kt*16)*2 + fofsA;
                    uint32_t rh[4];
                    ldsm4(rh, ka);
                    uint32_t b0h[2] = {rh[0], rh[2]}, b1h[2] = {rh[1], rh[3]};
                    mma16816(sc[2*jp],   qh[kt], b0h);
                    mma16816(sc[2*jp],   ql[kt], b0h);
                    mma16816(sc[2*jp+1], qh[kt], b1h);
                    mma16816(sc[2*jp+1], ql[kt], b1h);
                }
            }

            // ---- causal mask (near-diagonal blocks only) ----
            if (k0 + 63 > q0 + wid*16) {
                const int r0 = q0 + wid*16 + g;
                #pragma unroll
                for (int j = 0; j < 8; j++) {
                    int col = k0 + j*8 + t2;
                    if (col     > r0)   sc[j][0] = -1e30f;
                    if (col + 1 > r0)   sc[j][1] = -1e30f;
                    if (col     > r0+8) sc[j][2] = -1e30f;
                    if (col + 1 > r0+8) sc[j][3] = -1e30f;
                }
            }

            // ---- online softmax ----
            float alpha[2];
            #pragma unroll
            for (int r = 0; r < 2; r++) {
                float mx = -1e30f;
                #pragma unroll
                for (int j = 0; j < 8; j++)
                    mx = fmaxf(mx, fmaxf(sc[j][2*r], sc[j][2*r+1]));
                mx = fmaxf(mx, __shfl_xor_sync(0xffffffffu, mx, 1));
                mx = fmaxf(mx, __shfl_xor_sync(0xffffffffu, mx, 2));
                float mnew = fmaxf(m_i[r], mx);
                alpha[r] = __expf(m_i[r] - mnew);
                m_i[r] = mnew;
                float rs = 0.f;
                #pragma unroll
                for (int j = 0; j < 8; j++) {
                    float p0 = __expf(sc[j][2*r]   - mnew);
                    float p1 = __expf(sc[j][2*r+1] - mnew);
                    sc[j][2*r] = p0; sc[j][2*r+1] = p1;
                    rs += p0 + p1;
                }
                rs += __shfl_xor_sync(0xffffffffu, rs, 1);
                rs += __shfl_xor_sync(0xffffffffu, rs, 2);
                l_i[r] = l_i[r]*alpha[r] + rs;
            }

            #pragma unroll
            for (int dt = 0; dt < 8; dt++) {
                o[dt][0] *= alpha[0]; o[dt][1] *= alpha[0];
                o[dt][2] *= alpha[1]; o[dt][3] *= alpha[1];
            }

            // ---- P -> A-fragments (hi/lo fp16) ----
            uint32_t ph[4][4], pl[4][4];
            #pragma unroll
            for (int kt = 0; kt < 4; kt++) {
                hsplit2(sc[2*kt][0],   sc[2*kt][1],   ph[kt][0], pl[kt][0]);
                hsplit2(sc[2*kt][2],   sc[2*kt][3],   ph[kt][1], pl[kt][1]);
                hsplit2(sc[2*kt+1][0], sc[2*kt+1][1], ph[kt][2], pl[kt][2]);
                hsplit2(sc[2*kt+1][2], sc[2*kt+1][3], ph[kt][3], pl[kt][3]);
            }

            // ---- O += P V (2-term, P exact) ----
            #pragma unroll
            for (int dp = 0; dp < 4; dp++) {
                #pragma unroll
                for (int kt = 0; kt < 4; kt++) {
                    uint32_t va = kbufb + (uint32_t)(AS*2) +
                                  (uint32_t)((dp*16)*KSTR + kt*16)*2 + fofsA;
                    uint32_t rh[4];
                    ldsm4(rh, va);
                    uint32_t b0h[2] = {rh[0], rh[2]}, b1h[2] = {rh[1], rh[3]};
                    mma16816(o[2*dp],   ph[kt], b0h);
                    mma16816(o[2*dp],   pl[kt], b0h);
                    mma16816(o[2*dp+1], ph[kt], b1h);
                    mma16816(o[2*dp+1], pl[kt], b1h);
                }
            }
        }
        __syncthreads();
    }

    // ---- epilogue ----
    const int b = bh >> 3, h = bh & 7;
    const float hs = head_scale[h];
    #pragma unroll
    for (int r = 0; r < 2; r++) {
        const float inv = hs / l_i[r];
        const int n = q0 + wid*16 + g + r*8;
        __half* dsth = g_aoh + ((size_t)(b*NSEQ + n))*DIM + h*DH;
        __half* dstl = g_aol + ((size_t)(b*NSEQ + n))*DIM + h*DH;
        #pragma unroll
        for (int dt = 0; dt < 8; dt++) {
            int d = dt*8 + t2;
            uint32_t hh, ll;
            hsplit2(o[dt][2*r]*inv, o[dt][2*r+1]*inv, hh, ll);
            *(uint32_t*)&dsth[d] = hh;
            *(uint32_t*)&dstl[d] = ll;
        }
    }
}

// ============================================================
// Kernel 3: output projection, fp16 2-term (ao exact, Wo hi only)
// grid: (64, 4), block 256; dyn smem 61440 B
// ============================================================
__global__ void __launch_bounds__(256) outproj_mma(const float* __restrict__ bo)
{
    extern __shared__ __align__(16) __half dsm[];
    const uint32_t sbase = su32(dsm);

    const int tid = threadIdx.x, lid = tid & 31, wid = tid >> 5;
    const int wm = wid >> 2, wn = wid & 3;
    const int m0   = blockIdx.x * 128;
    const int col0 = blockIdx.y * 128;
    const int g  = lid >> 2;
    const int t2 = (lid & 3) * 2;
    const uint32_t fofsG = (uint32_t)((lid & 15)*ASTRIDE + ((lid >> 4) & 1)*8) * 2;

    const int srow = tid >> 1;
    const int sseg = (tid & 1) * 16;
    const size_t aoo = (size_t)(m0 + srow)*DIM + sseg;
    const size_t woo = (size_t)(col0 + srow)*DIM + sseg;
    const uint32_t doff = (uint32_t)(srow*ASTRIDE + sseg) * 2;

    #define OP_STAGE(kk, buf) do { \
        uint32_t b0 = sbase + (uint32_t)(buf)*(3*TS*2) + doff; \
        const __half* pa = g_aoh + aoo + (kk); \
        const __half* pb = g_aol + aoo + (kk); \
        const __half* pc = g_woh + woo + (kk); \
        CPA(b0,          pa); CPA(b0 + 16,          pa + 8); \
        CPA(b0 + TS*2,   pb); CPA(b0 + TS*2 + 16,   pb + 8); \
        CPA(b0 + 2*TS*2, pc); CPA(b0 + 2*TS*2 + 16, pc + 8); \
    } while (0)

    float c[4][4][4];
    #pragma unroll
    for (int i = 0; i < 4; i++)
        #pragma unroll
        for (int j = 0; j < 4; j++)
            #pragma unroll
            for (int q = 0; q < 4; q++) c[i][j][q] = 0.f;

    OP_STAGE(0, 0); CPC();

    for (int kc = 0; kc < 16; kc++) {
        if (kc + 1 < 16) { OP_STAGE((kc+1)*32, (kc+1)&1); CPC(); CPW(1); }
        else             { CPW(0); }
        __syncthreads();

        const uint32_t bufb = sbase + (uint32_t)(kc&1)*(3*TS*2);

        #pragma unroll
        for (int ks = 0; ks < 2; ks++) {
            const uint32_t kB = (uint32_t)(ks*16)*2;
            uint32_t bh[4][2];
            #pragma unroll
            for (int np = 0; np < 2; np++) {
                uint32_t r[4];
                uint32_t ba = bufb + (uint32_t)(2*TS*2) +
                              (uint32_t)((wn*32 + np*16)*ASTRIDE)*2 + kB + fofsG;
                ldsm4(r, ba);
                bh[np*2][0]=r[0]; bh[np*2+1][0]=r[1]; bh[np*2][1]=r[2]; bh[np*2+1][1]=r[3];
            }
            #pragma unroll
            for (int mt = 0; mt < 4; mt++) {
                uint32_t aa = bufb + (uint32_t)((wm*64 + mt*16)*ASTRIDE)*2 + kB + fofsG;
                uint32_t ah[4], al[4];
                ldsm4(ah, aa);
                ldsm4(al, aa + (uint32_t)(TS*2));
                #pragma unroll
                for (int nt = 0; nt < 4; nt++) {
                    mma16816(c[mt][nt], ah, bh[nt]);
                    mma16816(c[mt][nt], al, bh[nt]);
                }
            }
        }
        __syncthreads();
    }

    #pragma unroll
    for (int mt = 0; mt < 4; mt++) {
        #pragma unroll
        for (int half = 0; half < 2; half++) {
            int m = m0 + wm*64 + mt*16 + g + half*8;
            #pragma unroll
            for (int nt = 0; nt < 4; nt++) {
                int gc = col0 + wn*32 + nt*8 + t2;
                float* dst = g_y + (size_t)m*DIM + gc;
                dst[0] = c[mt][nt][half*2 + 0] + __ldg(bo + gc);
                dst[1] = c[mt][nt][half*2 + 1] + __ldg(bo + gc + 1);
            }
        }
    }
}

// ============================================================
// Kernel 4: LayerNorm + ls_scale + transpose
// ============================================================
__global__ void ln_kernel(const float* __restrict__ ln_g,
                          const float* __restrict__ ln_b,
                          const float* __restrict__ ls,
                          float* __restrict__ out)
{
    __shared__ float red[8];
    const int m = blockIdx.x;
    const int b = m >> 11, n = m & 2047;
    const int tid = threadIdx.x;
    float4 v = ((const float4*)(g_y + (size_t)m*DIM))[tid];
    float s  = v.x + v.y + v.z + v.w;
    float sq = v.x*v.x + v.y*v.y + v.z*v.z + v.w*v.w;
    #pragma unroll
    for (int off = 16; off > 0; off >>= 1) {
        s  += __shfl_xor_sync(0xffffffffu, s,  off);
        sq += __shfl_xor_sync(0xffffffffu, sq, off);
    }
    const int wid = tid >> 5;
    if ((tid & 31) == 0) { red[wid] = s; red[wid + 4] = sq; }
    __syncthreads();
    s  = red[0] + red[1] + red[2] + red[3];
    sq = red[4] + red[5] + red[6] + red[7];
    float mu  = s * (1.f/DIM);
    float var = sq * (1.f/DIM) - mu*mu;
    float r   = rsqrtf(var + 1e-5f);

    float* dst = out + (size_t)(n*NB + b)*DIM;
    const int d0 = tid * 4;
    float vv[4] = {v.x, v.y, v.z, v.w};
    #pragma unroll
    for (int q = 0; q < 4; q++) {
        int d = d0 + q;
        dst[d] = ls[d] * ((vv[q] - mu) * r * ln_g[d] + ln_b[d]);
    }
}

// ============================================================
extern "C" void kernel_launch(void* const* d_in, const int* in_sizes, int n_in,
                              void* d_out, int out_size)
{
    const float* x    = (const float*)d_in[0];
    const float* rope = (const float*)d_in[1];
    const float* Wq   = (const float*)d_in[2];
    const float* Wk   = (const float*)d_in[3];
    const float* Wv   = (const float*)d_in[4];
    const float* Wo   = (const float*)d_in[5];
    const float* bo   = (const float*)d_in[6];
    const float* ln_g = (const float*)d_in[7];
    const float* ln_b = (const float*)d_in[8];
    const float* hsc  = (const float*)d_in[9];
    const float* ls   = (const float*)d_in[10];
    float* out = (float*)d_out;

    __half *xh, *xl, *wqh, *wkh, *wvh, *woh;
    cudaGetSymbolAddress((void**)&xh,  g_xh);  cudaGetSymbolAddress((void**)&xl,  g_xl);
    cudaGetSymbolAddress((void**)&wqh, g_wqh); cudaGetSymbolAddress((void**)&wkh, g_wkh);
    cudaGetSymbolAddress((void**)&wvh, g_wvh); cudaGetSymbolAddress((void**)&woh, g_woh);

    static bool attr_done = false;
    if (!attr_done) {
        cudaFuncSetAttribute(qkv_mma,     cudaFuncAttributeMaxDynamicSharedMemorySize, 2*3*TS*2);
        cudaFuncSetAttribute(outproj_mma, cudaFuncAttributeMaxDynamicSharedMemorySize, 2*3*TS*2);
        cudaFuncSetAttribute(attn_mma,    cudaFuncAttributeMaxDynamicSharedMemorySize, 2*2*AS*2);
        attr_done = true;
    }

    const int XN4 = MROWS*DIM/4, WN4 = DIM*DIM/4;
    split_kernel<<<(XN4+255)/256, 256>>>(x,  xh,  xl,  XN4);
    tohalf_kernel<<<(WN4+255)/256, 256>>>(Wq, wqh, WN4);
    tohalf_kernel<<<(WN4+255)/256, 256>>>(Wk, wkh, WN4);
    tohalf_kernel<<<(WN4+255)/256, 256>>>(Wv, wvh, WN4);
    tohalf_kernel<<<(WN4+255)/256, 256>>>(Wo, woh, WN4);
    rope_table_kernel<<<(NB*NSEQ*DH + 255)/256, 256>>>(rope);

    qkv_mma<<<dim3(MROWS/128, 12), 256, 2*3*TS*2>>>();
    attn_mma<<<dim3(NB*HEADS, NSEQ/128), 256, 2*2*AS*2>>>(hsc);
    outproj_mma<<<dim3(MROWS/128, 4), 256, 2*3*TS*2>>>(bo);
    ln_kernel<<<MROWS, 128>>>(ln_g, ln_b, ls, out);
}

// round 15
// speedup vs baseline: 6.0621x; 1.2153x over previous
#include <cuda_runtime.h>
#include <cuda_fp16.h>
#include <cstdint>
#include <math.h>

#define HEADS   8
#define DH      64
#define DIM     512
#define NSEQ    2048
#define NB      4
#define MROWS   (NB*NSEQ)          // 8192
#define QSCALE  0.125f             // dh^-0.5
#define ASTRIDE 40                 // padded smem row stride (elems); 80B
#define KSTR    72                 // attention tile stride; 144B
#define TS      (128*ASTRIDE)      // GEMM tile elems (5120)
#define AS      (64*KSTR)          // attn tile elems (4608)

// -------- scratch (device globals; no allocation allowed) --------
__device__ __half g_xh[MROWS*DIM];
__device__ __half g_xl[MROWS*DIM];
__device__ __half g_wqh[DIM*DIM];
__device__ __half g_wkh[DIM*DIM];
__device__ __half g_wvh[DIM*DIM];
__device__ __half g_woh[DIM*DIM];
__device__ __half g_qh[NB*HEADS*NSEQ*DH];   // [b,h,n,d] hi only
__device__ __half g_kh[NB*HEADS*NSEQ*DH];   // hi only
__device__ __half g_vth[NB*HEADS*DH*NSEQ];  // [b,h,d,n], hi only
__device__ __half g_aoh[MROWS*DIM];
__device__ __half g_aol[MROWS*DIM];
__device__ float g_y[MROWS*DIM];
__device__ float g_cos[NB*NSEQ*DH];
__device__ float g_sin[NB*NSEQ*DH];

// ============================================================
// helpers
// ============================================================
__device__ __forceinline__ void mma16816(float* c, const uint32_t* a, const uint32_t* b) {
    asm volatile(
        "mma.sync.aligned.m16n8k16.row.col.f32.f16.f16.f32 "
        "{%0,%1,%2,%3}, {%4,%5,%6,%7}, {%8,%9}, {%0,%1,%2,%3};"
        : "+f"(c[0]), "+f"(c[1]), "+f"(c[2]), "+f"(c[3])
        : "r"(a[0]), "r"(a[1]), "r"(a[2]), "r"(a[3]), "r"(b[0]), "r"(b[1]));
}

__device__ __forceinline__ void ldsm4(uint32_t* r, uint32_t addr) {
    asm volatile("ldmatrix.sync.aligned.m8n8.x4.shared.b16 {%0,%1,%2,%3}, [%4];"
        : "=r"(r[0]), "=r"(r[1]), "=r"(r[2]), "=r"(r[3]) : "r"(addr));
}

__device__ __forceinline__ uint32_t su32(const void* p) {
    uint32_t a;
    asm("{ .reg .u64 t; cvta.to.shared.u64 t, %1; cvt.u32.u64 %0, t; }"
        : "=r"(a) : "l"(p));
    return a;
}
#define CPA(dst, src) asm volatile("cp.async.cg.shared.global [%0], [%1], 16;" :: "r"(dst), "l"(src))
#define CPC()         asm volatile("cp.async.commit_group;")
#define CPW(n)        asm volatile("cp.async.wait_group %0;" :: "n"(n))

// fp16 hi/lo split helpers
__device__ __forceinline__ void hsplit4(float4 v, uint2& h, uint2& l) {
    __half2 ha = __floats2half2_rn(v.x, v.y);
    __half2 hb = __floats2half2_rn(v.z, v.w);
    float rx = v.x - __half2float(ha.x);
    float ry = v.y - __half2float(ha.y);
    float rz = v.z - __half2float(hb.x);
    float rw = v.w - __half2float(hb.y);
    __half2 la = __floats2half2_rn(rx, ry);
    __half2 lb = __floats2half2_rn(rz, rw);
    h.x = *(uint32_t*)&ha; h.y = *(uint32_t*)&hb;
    l.x = *(uint32_t*)&la; l.y = *(uint32_t*)&lb;
}
__device__ __forceinline__ void hsplit2(float a, float b, uint32_t& h, uint32_t& l) {
    __half2 hh = __floats2half2_rn(a, b);
    float ra = a - __half2float(hh.x);
    float rb = b - __half2float(hh.y);
    __half2 ll = __floats2half2_rn(ra, rb);
    h = *(uint32_t*)&hh; l = *(uint32_t*)&ll;
}

// ============================================================
// Fused prep kernel: x split + 4 weight converts + rope table
// grid layout (blocks of 256):
//   [0, 4096)        x split (XN4 = 1048576 float4)
//   [4096, 4352)     Wq convert (WN4 = 65536)
//   [4352, 4608)     Wk
//   [4608, 4864)     Wv
//   [4864, 5120)     Wo
//   [5120, 7168)     rope table (524288 elems)
// ============================================================
__global__ void prep_kernel(const float* __restrict__ x,
                            const float* __restrict__ Wq,
                            const float* __restrict__ Wk,
                            const float* __restrict__ Wv,
                            const float* __restrict__ Wo,
                            const float* __restrict__ rope)
{
    const int bid = blockIdx.x, tid = threadIdx.x;
    if (bid < 4096) {
        int i = bid*256 + tid;
        float4 v = ((const float4*)x)[i];
        uint2 h, l; hsplit4(v, h, l);
        ((uint2*)g_xh)[i] = h;
        ((uint2*)g_xl)[i] = l;
    } else if (bid < 5120) {
        int wsel = (bid - 4096) >> 8;
        int i = ((bid - 4096) & 255)*256 + tid;
        const float* src = (wsel == 0) ? Wq : (wsel == 1) ? Wk : (wsel == 2) ? Wv : Wo;
        __half* dst = (wsel == 0) ? g_wqh : (wsel == 1) ? g_wkh : (wsel == 2) ? g_wvh : g_woh;
        float4 v = ((const float4*)src)[i];
        __half2 a = __floats2half2_rn(v.x, v.y);
        __half2 b = __floats2half2_rn(v.z, v.w);
        uint2 o; o.x = *(uint32_t*)&a; o.y = *(uint32_t*)&b;
        ((uint2*)dst)[i] = o;
    } else {
        int i = (bid - 5120)*256 + tid;
        float f = rope[i];
        g_cos[i] = cosf(f);
        g_sin[i] = sinf(f);
    }
}

// ============================================================
// Kernel 1: QKV projection, fp16 2-term (x exact, W hi only)
// grid: (64, 12), block 256; dyn smem 2*3*TS*2 = 61440 B
// ============================================================
__global__ void __launch_bounds__(256) qkv_mma()
{
    extern __shared__ __align__(16) __half dsm[];
    const uint32_t sbase = su32(dsm);

    const int tid = threadIdx.x, lid = tid & 31, wid = tid >> 5;
    const int wm = wid >> 2, wn = wid & 3;
    const int m0   = blockIdx.x * 128;
    const int by   = blockIdx.y;
    const int mat  = by >> 2;
    const int col0 = (by & 3) * 128;
    const __half* Wh = (mat == 0) ? g_wqh : ((mat == 1) ? g_wkh : g_wvh);

    const int g  = lid >> 2;
    const int t2 = (lid & 3) * 2;
    const uint32_t fofsG = (uint32_t)((lid & 15)*ASTRIDE + ((lid >> 4) & 1)*8) * 2;

    const int srow = tid >> 1;
    const int sseg = (tid & 1) * 16;
    const int sm  = m0 + srow, sn = sm & 2047, sb2 = sm >> 11;
    const size_t axo = (size_t)(sn*NB + sb2)*DIM + sseg;
    const size_t bwo = (size_t)(col0 + srow)*DIM + sseg;
    const uint32_t doff = (uint32_t)(srow*ASTRIDE + sseg) * 2;

    #define QKV_STAGE(kk, buf) do { \
        uint32_t b0 = sbase + (uint32_t)(buf)*(3*TS*2) + doff; \
        const __half* pa = g_xh + axo + (kk); \
        const __half* pb = g_xl + axo + (kk); \
        const __half* pc = Wh + bwo + (kk); \
        CPA(b0,          pa); CPA(b0 + 16,          pa + 8); \
        CPA(b0 + TS*2,   pb); CPA(b0 + TS*2 + 16,   pb + 8); \
        CPA(b0 + 2*TS*2, pc); CPA(b0 + 2*TS*2 + 16, pc + 8); \
    } while (0)

    float c[4][4][4];
    #pragma unroll
    for (int i = 0; i < 4; i++)
        #pragma unroll
        for (int j = 0; j < 4; j++)
            #pragma unroll
            for (int q = 0; q < 4; q++) c[i][j][q] = 0.f;

    QKV_STAGE(0, 0); CPC();

    for (int kc = 0; kc < 16; kc++) {
        if (kc + 1 < 16) { QKV_STAGE((kc+1)*32, (kc+1)&1); CPC(); CPW(1); }
        else             { CPW(0); }
        __syncthreads();

        const uint32_t bufb = sbase + (uint32_t)(kc&1)*(3*TS*2);

        #pragma unroll
        for (int ks = 0; ks < 2; ks++) {
            const uint32_t kB = (uint32_t)(ks*16)*2;
            uint32_t bh[4][2];
            #pragma unroll
            for (int np = 0; np < 2; np++) {
                uint32_t r[4];
                uint32_t ba = bufb + (uint32_t)(2*TS*2) +
                              (uint32_t)((wn*32 + np*16)*ASTRIDE)*2 + kB + fofsG;
                ldsm4(r, ba);
                bh[np*2][0]=r[0]; bh[np*2+1][0]=r[1]; bh[np*2][1]=r[2]; bh[np*2+1][1]=r[3];
            }
            #pragma unroll
            for (int mt = 0; mt < 4; mt++) {
                uint32_t aa = bufb + (uint32_t)((wm*64 + mt*16)*ASTRIDE)*2 + kB + fofsG;
                uint32_t ah[4], al[4];
                ldsm4(ah, aa);
                ldsm4(al, aa + (uint32_t)(TS*2));
                #pragma unroll
                for (int nt = 0; nt < 4; nt++) {
                    mma16816(c[mt][nt], ah, bh[nt]);
                    mma16816(c[mt][nt], al, bh[nt]);
                }
            }
        }
        __syncthreads();
    }

    // ---- epilogue: RoPE (+qscale), convert, scatter ----
    #pragma unroll
    for (int mt = 0; mt < 4; mt++) {
        #pragma unroll
        for (int half = 0; half < 2; half++) {
            int m = m0 + wm*64 + mt*16 + g + half*8;
            int n = m & 2047, b = m >> 11;
            #pragma unroll
            for (int nt = 0; nt < 4; nt++) {
                int gc = col0 + wn*32 + nt*8 + t2;
                int h = gc >> 6, d = gc & 63;
                float v0 = c[mt][nt][half*2 + 0];
                float v1 = c[mt][nt][half*2 + 1];
                if (mat < 2) {
                    size_t fo = ((size_t)(b*NSEQ + n))*DH + d;
                    float co0 = g_cos[fo], co1 = g_cos[fo+1];
                    float si0 = g_sin[fo], si1 = g_sin[fo+1];
                    float o0 = v0*co0 - v1*si0;
                    float o1 = v1*co1 + v0*si1;
                    size_t off = (((size_t)(b*HEADS + h))*NSEQ + n)*DH + d;
                    if (mat == 0) { o0 *= QSCALE; o1 *= QSCALE; }
                    __half2 h2 = __floats2half2_rn(o0, o1);
                    *(uint32_t*)&((mat == 0) ? g_qh : g_kh)[off] = *(uint32_t*)&h2;
                } else {
                    size_t base = ((size_t)(b*HEADS + h))*DH*NSEQ;
                    g_vth[base + (size_t)d*NSEQ + n]     = __float2half_rn(v0);
                    g_vth[base + (size_t)(d+1)*NSEQ + n] = __float2half_rn(v1);
                }
            }
        }
    }
}

// ============================================================
// Kernel 2: causal flash attention, fp16 1-term (S = Qh*Kh, O = Ph*Vh)
// grid: (32 bh, 16 qtiles DESC), block 256; dyn smem 2*2*AS*2 = 36864 B
// ============================================================
__global__ void __launch_bounds__(256) attn_mma(const float* __restrict__ head_scale)
{
    extern __shared__ __align__(16) __half dsm[];
    const uint32_t sbase = su32(dsm);

    const int tid = threadIdx.x, lid = tid & 31, wid = tid >> 5;
    const int bh = blockIdx.x;
    const int qt = (NSEQ/128 - 1) - blockIdx.y;    // longest first
    const int q0 = qt * 128;
    const int g  = lid >> 2;
    const int t2 = (lid & 3) * 2;
    const int kmax = 2*qt + 2;
    const uint32_t fofsA = (uint32_t)((lid & 15)*KSTR + ((lid >> 4) & 1)*8) * 2;

    const size_t hb_nd = (size_t)bh * NSEQ * DH;
    const size_t hb_dn = (size_t)bh * DH * NSEQ;

    const int srow = tid >> 2;
    const int sseg = (tid & 3) * 16;
    const uint32_t doff = (uint32_t)(srow*KSTR + sseg) * 2;
    const __half* kh_s = g_kh + hb_nd + (size_t)srow*DH + sseg;
    const __half* vh_s = g_vth + hb_dn + (size_t)srow*NSEQ + sseg;

    #define ATTN_STAGE(k0v, buf) do { \
        uint32_t b0 = sbase + (uint32_t)(buf)*(2*AS*2) + doff; \
        const __half* pa = kh_s + (size_t)(k0v)*DH; \
        const __half* pc = vh_s + (k0v); \
        CPA(b0,        pa); CPA(b0 + 16,        pa + 8); \
        CPA(b0 + AS*2, pc); CPA(b0 + AS*2 + 16, pc + 8); \
    } while (0)

    // ---- load Q fragments (hi only) ----
    uint32_t qh[4][4];
    {
        const __half* qhp = g_qh + hb_nd + (size_t)(q0 + wid*16)*DH;
        #pragma unroll
        for (int kt = 0; kt < 4; kt++) {
            int kc = kt*16 + t2;
            qh[kt][0] = *(const uint32_t*)&qhp[(size_t)g*DH + kc];
            qh[kt][1] = *(const uint32_t*)&qhp[(size_t)(g+8)*DH + kc];
            qh[kt][2] = *(const uint32_t*)&qhp[(size_t)g*DH + kc + 8];
            qh[kt][3] = *(const uint32_t*)&qhp[(size_t)(g+8)*DH + kc + 8];
        }
    }

    float m_i[2] = {-1e30f, -1e30f};
    float l_i[2] = {0.f, 0.f};
    float o[8][4];
    #pragma unroll
    for (int dt = 0; dt < 8; dt++)
        #pragma unroll
        for (int q = 0; q < 4; q++) o[dt][q] = 0.f;

    ATTN_STAGE(0, 0); CPC();

    for (int kb = 0; kb < kmax; kb++) {
        const int k0 = kb * 64;
        if (kb + 1 < kmax) { ATTN_STAGE((kb+1)*64, (kb+1)&1); CPC(); CPW(1); }
        else               { CPW(0); }
        __syncthreads();

        const uint32_t kbufb = sbase + (uint32_t)(kb&1)*(2*AS*2);

        if (k0 <= q0 + wid*16 + 15) {
            // ---- S = Q K^T (1-term) ----
            float sc[8][4];
            #pragma unroll
            for (int j = 0; j < 8; j++)
                #pragma unroll
                for (int q = 0; q < 4; q++) sc[j][q] = 0.f;

            #pragma unroll
            for (int jp = 0; jp < 4; jp++) {
                #pragma unroll
                for (int kt = 0; kt < 4; kt++) {
                    uint32_t ka = kbufb + (uint32_t)((jp*16)*KSTR + kt*16)*2 + fofsA;
                    uint32_t rh[4];
                    ldsm4(rh, ka);
                    uint32_t b0h[2] = {rh[0], rh[2]}, b1h[2] = {rh[1], rh[3]};
                    mma16816(sc[2*jp],   qh[kt], b0h);
                    mma16816(sc[2*jp+1], qh[kt], b1h);
                }
            }

            // ---- causal mask (near-diagonal blocks only) ----
            if (k0 + 63 > q0 + wid*16) {
                const int r0 = q0 + wid*16 + g;
                #pragma unroll
                for (int j = 0; j < 8; j++) {
                    int col = k0 + j*8 + t2;
                    if (col     > r0)   sc[j][0] = -1e30f;
                    if (col + 1 > r0)   sc[j][1] = -1e30f;
                    if (col     > r0+8) sc[j][2] = -1e30f;
                    if (col + 1 > r0+8) sc[j][3] = -1e30f;
                }
            }

            // ---- online softmax ----
            float alpha[2];
            #pragma unroll
            for (int r = 0; r < 2; r++) {
                float mx = -1e30f;
                #pragma unroll
                for (int j = 0; j < 8; j++)
                    mx = fmaxf(mx, fmaxf(sc[j][2*r], sc[j][2*r+1]));
                mx = fmaxf(mx, __shfl_xor_sync(0xffffffffu, mx, 1));
                mx = fmaxf(mx, __shfl_xor_sync(0xffffffffu, mx, 2));
                float mnew = fmaxf(m_i[r], mx);
                alpha[r] = __expf(m_i[r] - mnew);
                m_i[r] = mnew;
                float rs = 0.f;
                #pragma unroll
                for (int j = 0; j < 8; j++) {
                    float p0 = __expf(sc[j][2*r]   - mnew);
                    float p1 = __expf(sc[j][2*r+1] - mnew);
                    sc[j][2*r] = p0; sc[j][2*r+1] = p1;
                    rs += p0 + p1;
                }
                rs += __shfl_xor_sync(0xffffffffu, rs, 1);
                rs += __shfl_xor_sync(0xffffffffu, rs, 2);
                l_i[r] = l_i[r]*alpha[r] + rs;
            }

            #pragma unroll
            for (int dt = 0; dt < 8; dt++) {
                o[dt][0] *= alpha[0]; o[dt][1] *= alpha[0];
                o[dt][2] *= alpha[1]; o[dt][3] *= alpha[1];
            }

            // ---- P -> A-fragments (hi only) ----
            uint32_t ph[4][4];
            #pragma unroll
            for (int kt = 0; kt < 4; kt++) {
                __half2 p0 = __floats2half2_rn(sc[2*kt][0],   sc[2*kt][1]);
                __half2 p1 = __floats2half2_rn(sc[2*kt][2],   sc[2*kt][3]);
                __half2 p2 = __floats2half2_rn(sc[2*kt+1][0], sc[2*kt+1][1]);
                __half2 p3 = __floats2half2_rn(sc[2*kt+1][2], sc[2*kt+1][3]);
                ph[kt][0] = *(uint32_t*)&p0;
                ph[kt][1] = *(uint32_t*)&p1;
                ph[kt][2] = *(uint32_t*)&p2;
                ph[kt][3] = *(uint32_t*)&p3;
            }

            // ---- O += P V (1-term) ----
            #pragma unroll
            for (int dp = 0; dp < 4; dp++) {
                #pragma unroll
                for (int kt = 0; kt < 4; kt++) {
                    uint32_t va = kbufb + (uint32_t)(AS*2) +
                                  (uint32_t)((dp*16)*KSTR + kt*16)*2 + fofsA;
                    uint32_t rh[4];
                    ldsm4(rh, va);
                    uint32_t b0h[2] = {rh[0], rh[2]}, b1h[2] = {rh[1], rh[3]};
                    mma16816(o[2*dp],   ph[kt], b0h);
                    mma16816(o[2*dp+1], ph[kt], b1h);
                }
            }
        }
        __syncthreads();
    }

    // ---- epilogue: scale, split to hi/lo for outproj ----
    const int b = bh >> 3, h = bh & 7;
    const float hs = head_scale[h];
    #pragma unroll
    for (int r = 0; r < 2; r++) {
        const float inv = hs / l_i[r];
        const int n = q0 + wid*16 + g + r*8;
        __half* dsth = g_aoh + ((size_t)(b*NSEQ + n))*DIM + h*DH;
        __half* dstl = g_aol + ((size_t)(b*NSEQ + n))*DIM + h*DH;
        #pragma unroll
        for (int dt = 0; dt < 8; dt++) {
            int d = dt*8 + t2;
            uint32_t hh, ll;
            hsplit2(o[dt][2*r]*inv, o[dt][2*r+1]*inv, hh, ll);
            *(uint32_t*)&dsth[d] = hh;
            *(uint32_t*)&dstl[d] = ll;
        }
    }
}

// ============================================================
// Kernel 3: output projection, fp16 2-term (ao exact, Wo hi only)
// grid: (64, 4), block 256; dyn smem 61440 B
// ============================================================
__global__ void __launch_bounds__(256) outproj_mma(const float* __restrict__ bo)
{
    extern __shared__ __align__(16) __half dsm[];
    const uint32_t sbase = su32(dsm);

    const int tid = threadIdx.x, lid = tid & 31, wid = tid >> 5;
    const int wm = wid >> 2, wn = wid & 3;
    const int m0   = blockIdx.x * 128;
    const int col0 = blockIdx.y * 128;
    const int g  = lid >> 2;
    const int t2 = (lid & 3) * 2;
    const uint32_t fofsG = (uint32_t)((lid & 15)*ASTRIDE + ((lid >> 4) & 1)*8) * 2;

    const int srow = tid >> 1;
    const int sseg = (tid & 1) * 16;
    const size_t aoo = (size_t)(m0 + srow)*DIM + sseg;
    const size_t woo = (size_t)(col0 + srow)*DIM + sseg;
    const uint32_t doff = (uint32_t)(srow*ASTRIDE + sseg) * 2;

    #define OP_STAGE(kk, buf) do { \
        uint32_t b0 = sbase + (uint32_t)(buf)*(3*TS*2) + doff; \
        const __half* pa = g_aoh + aoo + (kk); \
        const __half* pb = g_aol + aoo + (kk); \
        const __half* pc = g_woh + woo + (kk); \
        CPA(b0,          pa); CPA(b0 + 16,          pa + 8); \
        CPA(b0 + TS*2,   pb); CPA(b0 + TS*2 + 16,   pb + 8); \
        CPA(b0 + 2*TS*2, pc); CPA(b0 + 2*TS*2 + 16, pc + 8); \
    } while (0)

    float c[4][4][4];
    #pragma unroll
    for (int i = 0; i < 4; i++)
        #pragma unroll
        for (int j = 0; j < 4; j++)
            #pragma unroll
            for (int q = 0; q < 4; q++) c[i][j][q] = 0.f;

    OP_STAGE(0, 0); CPC();

    for (int kc = 0; kc < 16; kc++) {
        if (kc + 1 < 16) { OP_STAGE((kc+1)*32, (kc+1)&1); CPC(); CPW(1); }
        else             { CPW(0); }
        __syncthreads();

        const uint32_t bufb = sbase + (uint32_t)(kc&1)*(3*TS*2);

        #pragma unroll
        for (int ks = 0; ks < 2; ks++) {
            const uint32_t kB = (uint32_t)(ks*16)*2;
            uint32_t bh[4][2];
            #pragma unroll
            for (int np = 0; np < 2; np++) {
                uint32_t r[4];
                uint32_t ba = bufb + (uint32_t)(2*TS*2) +
                              (uint32_t)((wn*32 + np*16)*ASTRIDE)*2 + kB + fofsG;
                ldsm4(r, ba);
                bh[np*2][0]=r[0]; bh[np*2+1][0]=r[1]; bh[np*2][1]=r[2]; bh[np*2+1][1]=r[3];
            }
            #pragma unroll
            for (int mt = 0; mt < 4; mt++) {
                uint32_t aa = bufb + (uint32_t)((wm*64 + mt*16)*ASTRIDE)*2 + kB + fofsG;
                uint32_t ah[4], al[4];
                ldsm4(ah, aa);
                ldsm4(al, aa + (uint32_t)(TS*2));
                #pragma unroll
                for (int nt = 0; nt < 4; nt++) {
                    mma16816(c[mt][nt], ah, bh[nt]);
                    mma16816(c[mt][nt], al, bh[nt]);
                }
            }
        }
        __syncthreads();
    }

    #pragma unroll
    for (int mt = 0; mt < 4; mt++) {
        #pragma unroll
        for (int half = 0; half < 2; half++) {
            int m = m0 + wm*64 + mt*16 + g + half*8;
            #pragma unroll
            for (int nt = 0; nt < 4; nt++) {
                int gc = col0 + wn*32 + nt*8 + t2;
                float* dst = g_y + (size_t)m*DIM + gc;
                dst[0] = c[mt][nt][half*2 + 0] + __ldg(bo + gc);
                dst[1] = c[mt][nt][half*2 + 1] + __ldg(bo + gc + 1);
            }
        }
    }
}

// ============================================================
// Kernel 4: LayerNorm + ls_scale + transpose
// ============================================================
__global__ void ln_kernel(const float* __restrict__ ln_g,
                          const float* __restrict__ ln_b,
                          const float* __restrict__ ls,
                          float* __restrict__ out)
{
    __shared__ float red[8];
    const int m = blockIdx.x;
    const int b = m >> 11, n = m & 2047;
    const int tid = threadIdx.x;
    float4 v = ((const float4*)(g_y + (size_t)m*DIM))[tid];
    float s  = v.x + v.y + v.z + v.w;
    float sq = v.x*v.x + v.y*v.y + v.z*v.z + v.w*v.w;
    #pragma unroll
    for (int off = 16; off > 0; off >>= 1) {
        s  += __shfl_xor_sync(0xffffffffu, s,  off);
        sq += __shfl_xor_sync(0xffffffffu, sq, off);
    }
    const int wid = tid >> 5;
    if ((tid & 31) == 0) { red[wid] = s; red[wid + 4] = sq; }
    __syncthreads();
    s  = red[0] + red[1] + red[2] + red[3];
    sq = red[4] + red[5] + red[6] + red[7];
    float mu  = s * (1.f/DIM);
    float var = sq * (1.f/DIM) - mu*mu;
    float r   = rsqrtf(var + 1e-5f);

    float* dst = out + (size_t)(n*NB + b)*DIM;
    const int d0 = tid * 4;
    float vv[4] = {v.x, v.y, v.z, v.w};
    #pragma unroll
    for (int q = 0; q < 4; q++) {
        int d = d0 + q;
        dst[d] = ls[d] * ((vv[q] - mu) * r * ln_g[d] + ln_b[d]);
    }
}

// ============================================================
extern "C" void kernel_launch(void* const* d_in, const int* in_sizes, int n_in,
                              void* d_out, int out_size)
{
    const float* x    = (const float*)d_in[0];
    const float* rope = (const float*)d_in[1];
    const float* Wq   = (const float*)d_in[2];
    const float* Wk   = (const float*)d_in[3];
    const float* Wv   = (const float*)d_in[4];
    const float* Wo   = (const float*)d_in[5];
    const float* bo   = (const float*)d_in[6];
    const float* ln_g = (const float*)d_in[7];
    const float* ln_b = (const float*)d_in[8];
    const float* hsc  = (const float*)d_in[9];
    const float* ls   = (const float*)d_in[10];
    float* out = (float*)d_out;

    static bool attr_done = false;
    if (!attr_done) {
        cudaFuncSetAttribute(qkv_mma,     cudaFuncAttributeMaxDynamicSharedMemorySize, 2*3*TS*2);
        cudaFuncSetAttribute(outproj_mma, cudaFuncAttributeMaxDynamicSharedMemorySize, 2*3*TS*2);
        cudaFuncSetAttribute(attn_mma,    cudaFuncAttributeMaxDynamicSharedMemorySize, 2*2*AS*2);
        attr_done = true;
    }

    prep_kernel<<<7168, 256>>>(x, Wq, Wk, Wv, Wo, rope);
    qkv_mma<<<dim3(MROWS/128, 12), 256, 2*3*TS*2>>>();
    attn_mma<<<dim3(NB*HEADS, NSEQ/128), 256, 2*2*AS*2>>>(hsc);
    outproj_mma<<<dim3(MROWS/128, 4), 256, 2*3*TS*2>>>(bo);
    ln_kernel<<<MROWS, 128>>>(ln_g, ln_b, ls, out);
}

// round 16
// speedup vs baseline: 7.9436x; 1.3104x over previous
#include <cuda_runtime.h>
#include <cuda_fp16.h>
#include <cstdint>
#include <math.h>

#define HEADS   8
#define DH      64
#define DIM     512
#define NSEQ    2048
#define NB      4
#define MROWS   (NB*NSEQ)          // 8192
#define QSCALE  0.125f             // dh^-0.5
#define ASTRIDE 40                 // padded smem row stride (elems); 80B
#define KSTR    72                 // attention tile stride; 144B
#define TS      (128*ASTRIDE)      // GEMM tile elems (5120)
#define AS      (64*KSTR)          // attn tile elems (4608)

// -------- scratch (device globals; no allocation allowed) --------
__device__ __half g_xh[MROWS*DIM];
__device__ __half g_wqh[DIM*DIM];
__device__ __half g_wkh[DIM*DIM];
__device__ __half g_wvh[DIM*DIM];
__device__ __half g_woh[DIM*DIM];
__device__ __half g_qh[NB*HEADS*NSEQ*DH];   // [b,h,n,d]
__device__ __half g_kh[NB*HEADS*NSEQ*DH];
__device__ __half g_vth[NB*HEADS*DH*NSEQ];  // [b,h,d,n]
__device__ __half g_aoh[MROWS*DIM];
__device__ float g_y[MROWS*DIM];
__device__ float g_cos[NB*NSEQ*DH];
__device__ float g_sin[NB*NSEQ*DH];

// ============================================================
// helpers
// ============================================================
__device__ __forceinline__ void mma16816(float* c, const uint32_t* a, const uint32_t* b) {
    asm volatile(
        "mma.sync.aligned.m16n8k16.row.col.f32.f16.f16.f32 "
        "{%0,%1,%2,%3}, {%4,%5,%6,%7}, {%8,%9}, {%0,%1,%2,%3};"
        : "+f"(c[0]), "+f"(c[1]), "+f"(c[2]), "+f"(c[3])
        : "r"(a[0]), "r"(a[1]), "r"(a[2]), "r"(a[3]), "r"(b[0]), "r"(b[1]));
}

__device__ __forceinline__ void ldsm4(uint32_t* r, uint32_t addr) {
    asm volatile("ldmatrix.sync.aligned.m8n8.x4.shared.b16 {%0,%1,%2,%3}, [%4];"
        : "=r"(r[0]), "=r"(r[1]), "=r"(r[2]), "=r"(r[3]) : "r"(addr));
}

__device__ __forceinline__ uint32_t su32(const void* p) {
    uint32_t a;
    asm("{ .reg .u64 t; cvta.to.shared.u64 t, %1; cvt.u32.u64 %0, t; }"
        : "=r"(a) : "l"(p));
    return a;
}
#define CPA(dst, src) asm volatile("cp.async.cg.shared.global [%0], [%1], 16;" :: "r"(dst), "l"(src))
#define CPC()         asm volatile("cp.async.commit_group;")
#define CPW(n)        asm volatile("cp.async.wait_group %0;" :: "n"(n))

// ============================================================
// Fused prep kernel: x convert + 4 weight converts + rope table
// grid (blocks of 256):
//   [0, 4096)     x convert (1048576 float4)
//   [4096, 5120)  Wq/Wk/Wv/Wo converts (65536 float4 each)
//   [5120, 7168)  rope table (524288 elems)
// ============================================================
__global__ void prep_kernel(const float* __restrict__ x,
                            const float* __restrict__ Wq,
                            const float* __restrict__ Wk,
                            const float* __restrict__ Wv,
                            const float* __restrict__ Wo,
                            const float* __restrict__ rope)
{
    const int bid = blockIdx.x, tid = threadIdx.x;
    if (bid < 4096) {
        int i = bid*256 + tid;
        float4 v = ((const float4*)x)[i];
        __half2 a = __floats2half2_rn(v.x, v.y);
        __half2 b = __floats2half2_rn(v.z, v.w);
        uint2 o; o.x = *(uint32_t*)&a; o.y = *(uint32_t*)&b;
        ((uint2*)g_xh)[i] = o;
    } else if (bid < 5120) {
        int wsel = (bid - 4096) >> 8;
        int i = ((bid - 4096) & 255)*256 + tid;
        const float* src = (wsel == 0) ? Wq : (wsel == 1) ? Wk : (wsel == 2) ? Wv : Wo;
        __half* dst = (wsel == 0) ? g_wqh : (wsel == 1) ? g_wkh : (wsel == 2) ? g_wvh : g_woh;
        float4 v = ((const float4*)src)[i];
        __half2 a = __floats2half2_rn(v.x, v.y);
        __half2 b = __floats2half2_rn(v.z, v.w);
        uint2 o; o.x = *(uint32_t*)&a; o.y = *(uint32_t*)&b;
        ((uint2*)dst)[i] = o;
    } else {
        int i = (bid - 5120)*256 + tid;
        float f = rope[i];
        g_cos[i] = cosf(f);
        g_sin[i] = sinf(f);
    }
}

// ============================================================
// Kernel 1: QKV projection, fp16 1-term
// grid: (64, 12), block 256; dyn smem 2*2*TS*2 = 40960 B
// ============================================================
__global__ void __launch_bounds__(256) qkv_mma()
{
    extern __shared__ __align__(16) __half dsm[];
    const uint32_t sbase = su32(dsm);

    const int tid = threadIdx.x, lid = tid & 31, wid = tid >> 5;
    const int wm = wid >> 2, wn = wid & 3;
    const int m0   = blockIdx.x * 128;
    const int by   = blockIdx.y;
    const int mat  = by >> 2;
    const int col0 = (by & 3) * 128;
    const __half* Wh = (mat == 0) ? g_wqh : ((mat == 1) ? g_wkh : g_wvh);

    const int g  = lid >> 2;
    const int t2 = (lid & 3) * 2;
    const uint32_t fofsG = (uint32_t)((lid & 15)*ASTRIDE + ((lid >> 4) & 1)*8) * 2;

    const int srow = tid >> 1;
    const int sseg = (tid & 1) * 16;
    const int sm  = m0 + srow, sn = sm & 2047, sb2 = sm >> 11;
    const size_t axo = (size_t)(sn*NB + sb2)*DIM + sseg;
    const size_t bwo = (size_t)(col0 + srow)*DIM + sseg;
    const uint32_t doff = (uint32_t)(srow*ASTRIDE + sseg) * 2;

    #define QKV_STAGE(kk, buf) do { \
        uint32_t b0 = sbase + (uint32_t)(buf)*(2*TS*2) + doff; \
        const __half* pa = g_xh + axo + (kk); \
        const __half* pc = Wh + bwo + (kk); \
        CPA(b0,        pa); CPA(b0 + 16,        pa + 8); \
        CPA(b0 + TS*2, pc); CPA(b0 + TS*2 + 16, pc + 8); \
    } while (0)

    float c[4][4][4];
    #pragma unroll
    for (int i = 0; i < 4; i++)
        #pragma unroll
        for (int j = 0; j < 4; j++)
            #pragma unroll
            for (int q = 0; q < 4; q++) c[i][j][q] = 0.f;

    QKV_STAGE(0, 0); CPC();

    for (int kc = 0; kc < 16; kc++) {
        if (kc + 1 < 16) { QKV_STAGE((kc+1)*32, (kc+1)&1); CPC(); CPW(1); }
        else             { CPW(0); }
        __syncthreads();

        const uint32_t bufb = sbase + (uint32_t)(kc&1)*(2*TS*2);

        #pragma unroll
        for (int ks = 0; ks < 2; ks++) {
            const uint32_t kB = (uint32_t)(ks*16)*2;
            uint32_t bh[4][2];
            #pragma unroll
            for (int np = 0; np < 2; np++) {
                uint32_t r[4];
                uint32_t ba = bufb + (uint32_t)(TS*2) +
                              (uint32_t)((wn*32 + np*16)*ASTRIDE)*2 + kB + fofsG;
                ldsm4(r, ba);
                bh[np*2][0]=r[0]; bh[np*2+1][0]=r[1]; bh[np*2][1]=r[2]; bh[np*2+1][1]=r[3];
            }
            #pragma unroll
            for (int mt = 0; mt < 4; mt++) {
                uint32_t aa = bufb + (uint32_t)((wm*64 + mt*16)*ASTRIDE)*2 + kB + fofsG;
                uint32_t ah[4];
                ldsm4(ah, aa);
                #pragma unroll
                for (int nt = 0; nt < 4; nt++)
                    mma16816(c[mt][nt], ah, bh[nt]);
            }
        }
        __syncthreads();
    }

    // ---- epilogue: RoPE (+qscale), convert, scatter ----
    #pragma unroll
    for (int mt = 0; mt < 4; mt++) {
        #pragma unroll
        for (int half = 0; half < 2; half++) {
            int m = m0 + wm*64 + mt*16 + g + half*8;
            int n = m & 2047, b = m >> 11;
            #pragma unroll
            for (int nt = 0; nt < 4; nt++) {
                int gc = col0 + wn*32 + nt*8 + t2;
                int h = gc >> 6, d = gc & 63;
                float v0 = c[mt][nt][half*2 + 0];
                float v1 = c[mt][nt][half*2 + 1];
                if (mat < 2) {
                    size_t fo = ((size_t)(b*NSEQ + n))*DH + d;
                    float co0 = g_cos[fo], co1 = g_cos[fo+1];
                    float si0 = g_sin[fo], si1 = g_sin[fo+1];
                    float o0 = v0*co0 - v1*si0;
                    float o1 = v1*co1 + v0*si1;
                    size_t off = (((size_t)(b*HEADS + h))*NSEQ + n)*DH + d;
                    if (mat == 0) { o0 *= QSCALE; o1 *= QSCALE; }
                    __half2 h2 = __floats2half2_rn(o0, o1);
                    *(uint32_t*)&((mat == 0) ? g_qh : g_kh)[off] = *(uint32_t*)&h2;
                } else {
                    size_t base = ((size_t)(b*HEADS + h))*DH*NSEQ;
                    g_vth[base + (size_t)d*NSEQ + n]     = __float2half_rn(v0);
                    g_vth[base + (size_t)(d+1)*NSEQ + n] = __float2half_rn(v1);
                }
            }
        }
    }
}

// ============================================================
// Kernel 2: causal flash attention, fp16 1-term
// grid: (32 bh, 16 qtiles DESC), block 256; dyn smem 36864 B
// ============================================================
__global__ void __launch_bounds__(256) attn_mma(const float* __restrict__ head_scale)
{
    extern __shared__ __align__(16) __half dsm[];
    const uint32_t sbase = su32(dsm);

    const int tid = threadIdx.x, lid = tid & 31, wid = tid >> 5;
    const int bh = blockIdx.x;
    const int qt = (NSEQ/128 - 1) - blockIdx.y;    // longest first
    const int q0 = qt * 128;
    const int g  = lid >> 2;
    const int t2 = (lid & 3) * 2;
    const int kmax = 2*qt + 2;
    const uint32_t fofsA = (uint32_t)((lid & 15)*KSTR + ((lid >> 4) & 1)*8) * 2;

    const size_t hb_nd = (size_t)bh * NSEQ * DH;
    const size_t hb_dn = (size_t)bh * DH * NSEQ;

    const int srow = tid >> 2;
    const int sseg = (tid & 3) * 16;
    const uint32_t doff = (uint32_t)(srow*KSTR + sseg) * 2;
    const __half* kh_s = g_kh + hb_nd + (size_t)srow*DH + sseg;
    const __half* vh_s = g_vth + hb_dn + (size_t)srow*NSEQ + sseg;

    #define ATTN_STAGE(k0v, buf) do { \
        uint32_t b0 = sbase + (uint32_t)(buf)*(2*AS*2) + doff; \
        const __half* pa = kh_s + (size_t)(k0v)*DH; \
        const __half* pc = vh_s + (k0v); \
        CPA(b0,        pa); CPA(b0 + 16,        pa + 8); \
        CPA(b0 + AS*2, pc); CPA(b0 + AS*2 + 16, pc + 8); \
    } while (0)

    // ---- load Q fragments ----
    uint32_t qh[4][4];
    {
        const __half* qhp = g_qh + hb_nd + (size_t)(q0 + wid*16)*DH;
        #pragma unroll
        for (int kt = 0; kt < 4; kt++) {
            int kc = kt*16 + t2;
            qh[kt][0] = *(const uint32_t*)&qhp[(size_t)g*DH + kc];
            qh[kt][1] = *(const uint32_t*)&qhp[(size_t)(g+8)*DH + kc];
            qh[kt][2] = *(const uint32_t*)&qhp[(size_t)g*DH + kc + 8];
            qh[kt][3] = *(const uint32_t*)&qhp[(size_t)(g+8)*DH + kc + 8];
        }
    }

    float m_i[2] = {-1e30f, -1e30f};
    float l_i[2] = {0.f, 0.f};
    float o[8][4];
    #pragma unroll
    for (int dt = 0; dt < 8; dt++)
        #pragma unroll
        for (int q = 0; q < 4; q++) o[dt][q] = 0.f;

    ATTN_STAGE(0, 0); CPC();

    for (int kb = 0; kb < kmax; kb++) {
        const int k0 = kb * 64;
        if (kb + 1 < kmax) { ATTN_STAGE((kb+1)*64, (kb+1)&1); CPC(); CPW(1); }
        else               { CPW(0); }
        __syncthreads();

        const uint32_t kbufb = sbase + (uint32_t)(kb&1)*(2*AS*2);

        if (k0 <= q0 + wid*16 + 15) {
            // ---- S = Q K^T ----
            float sc[8][4];
            #pragma unroll
            for (int j = 0; j < 8; j++)
                #pragma unroll
                for (int q = 0; q < 4; q++) sc[j][q] = 0.f;

            #pragma unroll
            for (int jp = 0; jp < 4; jp++) {
                #pragma unroll
                for (int kt = 0; kt < 4; kt++) {
                    uint32_t ka = kbufb + (uint32_t)((jp*16)*KSTR + kt*16)*2 + fofsA;
                    uint32_t rh[4];
                    ldsm4(rh, ka);
                    uint32_t b0h[2] = {rh[0], rh[2]}, b1h[2] = {rh[1], rh[3]};
                    mma16816(sc[2*jp],   qh[kt], b0h);
                    mma16816(sc[2*jp+1], qh[kt], b1h);
                }
            }

            // ---- causal mask ----
            if (k0 + 63 > q0 + wid*16) {
                const int r0 = q0 + wid*16 + g;
                #pragma unroll
                for (int j = 0; j < 8; j++) {
                    int col = k0 + j*8 + t2;
                    if (col     > r0)   sc[j][0] = -1e30f;
                    if (col + 1 > r0)   sc[j][1] = -1e30f;
                    if (col     > r0+8) sc[j][2] = -1e30f;
                    if (col + 1 > r0+8) sc[j][3] = -1e30f;
                }
            }

            // ---- online softmax ----
            float alpha[2];
            #pragma unroll
            for (int r = 0; r < 2; r++) {
                float mx = -1e30f;
                #pragma unroll
                for (int j = 0; j < 8; j++)
                    mx = fmaxf(mx, fmaxf(sc[j][2*r], sc[j][2*r+1]));
                mx = fmaxf(mx, __shfl_xor_sync(0xffffffffu, mx, 1));
                mx = fmaxf(mx, __shfl_xor_sync(0xffffffffu, mx, 2));
                float mnew = fmaxf(m_i[r], mx);
                alpha[r] = __expf(m_i[r] - mnew);
                m_i[r] = mnew;
                float rs = 0.f;
                #pragma unroll
                for (int j = 0; j < 8; j++) {
                    float p0 = __expf(sc[j][2*r]   - mnew);
                    float p1 = __expf(sc[j][2*r+1] - mnew);
                    sc[j][2*r] = p0; sc[j][2*r+1] = p1;
                    rs += p0 + p1;
                }
                rs += __shfl_xor_sync(0xffffffffu, rs, 1);
                rs += __shfl_xor_sync(0xffffffffu, rs, 2);
                l_i[r] = l_i[r]*alpha[r] + rs;
            }

            #pragma unroll
            for (int dt = 0; dt < 8; dt++) {
                o[dt][0] *= alpha[0]; o[dt][1] *= alpha[0];
                o[dt][2] *= alpha[1]; o[dt][3] *= alpha[1];
            }

            // ---- P -> A-fragments ----
            uint32_t ph[4][4];
            #pragma unroll
            for (int kt = 0; kt < 4; kt++) {
                __half2 p0 = __floats2half2_rn(sc[2*kt][0],   sc[2*kt][1]);
                __half2 p1 = __floats2half2_rn(sc[2*kt][2],   sc[2*kt][3]);
                __half2 p2 = __floats2half2_rn(sc[2*kt+1][0], sc[2*kt+1][1]);
                __half2 p3 = __floats2half2_rn(sc[2*kt+1][2], sc[2*kt+1][3]);
                ph[kt][0] = *(uint32_t*)&p0;
                ph[kt][1] = *(uint32_t*)&p1;
                ph[kt][2] = *(uint32_t*)&p2;
                ph[kt][3] = *(uint32_t*)&p3;
            }

            // ---- O += P V ----
            #pragma unroll
            for (int dp = 0; dp < 4; dp++) {
                #pragma unroll
                for (int kt = 0; kt < 4; kt++) {
                    uint32_t va = kbufb + (uint32_t)(AS*2) +
                                  (uint32_t)((dp*16)*KSTR + kt*16)*2 + fofsA;
                    uint32_t rh[4];
                    ldsm4(rh, va);
                    uint32_t b0h[2] = {rh[0], rh[2]}, b1h[2] = {rh[1], rh[3]};
                    mma16816(o[2*dp],   ph[kt], b0h);
                    mma16816(o[2*dp+1], ph[kt], b1h);
                }
            }
        }
        __syncthreads();
    }

    // ---- epilogue ----
    const int b = bh >> 3, h = bh & 7;
    const float hs = head_scale[h];
    #pragma unroll
    for (int r = 0; r < 2; r++) {
        const float inv = hs / l_i[r];
        const int n = q0 + wid*16 + g + r*8;
        __half* dsth = g_aoh + ((size_t)(b*NSEQ + n))*DIM + h*DH;
        #pragma unroll
        for (int dt = 0; dt < 8; dt++) {
            int d = dt*8 + t2;
            __half2 h2 = __floats2half2_rn(o[dt][2*r]*inv, o[dt][2*r+1]*inv);
            *(uint32_t*)&dsth[d] = *(uint32_t*)&h2;
        }
    }
}

// ============================================================
// Kernel 3: output projection, fp16 1-term (+bias)
// grid: (64, 4), block 256; dyn smem 40960 B
// ============================================================
__global__ void __launch_bounds__(256) outproj_mma(const float* __restrict__ bo)
{
    extern __shared__ __align__(16) __half dsm[];
    const uint32_t sbase = su32(dsm);

    const int tid = threadIdx.x, lid = tid & 31, wid = tid >> 5;
    const int wm = wid >> 2, wn = wid & 3;
    const int m0   = blockIdx.x * 128;
    const int col0 = blockIdx.y * 128;
    const int g  = lid >> 2;
    const int t2 = (lid & 3) * 2;
    const uint32_t fofsG = (uint32_t)((lid & 15)*ASTRIDE + ((lid >> 4) & 1)*8) * 2;

    const int srow = tid >> 1;
    const int sseg = (tid & 1) * 16;
    const size_t aoo = (size_t)(m0 + srow)*DIM + sseg;
    const size_t woo = (size_t)(col0 + srow)*DIM + sseg;
    const uint32_t doff = (uint32_t)(srow*ASTRIDE + sseg) * 2;

    #define OP_STAGE(kk, buf) do { \
        uint32_t b0 = sbase + (uint32_t)(buf)*(2*TS*2) + doff; \
        const __half* pa = g_aoh + aoo + (kk); \
        const __half* pc = g_woh + woo + (kk); \
        CPA(b0,        pa); CPA(b0 + 16,        pa + 8); \
        CPA(b0 + TS*2, pc); CPA(b0 + TS*2 + 16, pc + 8); \
    } while (0)

    float c[4][4][4];
    #pragma unroll
    for (int i = 0; i < 4; i++)
        #pragma unroll
        for (int j = 0; j < 4; j++)
            #pragma unroll
            for (int q = 0; q < 4; q++) c[i][j][q] = 0.f;

    OP_STAGE(0, 0); CPC();

    for (int kc = 0; kc < 16; kc++) {
        if (kc + 1 < 16) { OP_STAGE((kc+1)*32, (kc+1)&1); CPC(); CPW(1); }
        else             { CPW(0); }
        __syncthreads();

        const uint32_t bufb = sbase + (uint32_t)(kc&1)*(2*TS*2);

        #pragma unroll
        for (int ks = 0; ks < 2; ks++) {
            const uint32_t kB = (uint32_t)(ks*16)*2;
            uint32_t bh[4][2];
            #pragma unroll
            for (int np = 0; np < 2; np++) {
                uint32_t r[4];
                uint32_t ba = bufb + (uint32_t)(TS*2) +
                              (uint32_t)((wn*32 + np*16)*ASTRIDE)*2 + kB + fofsG;
                ldsm4(r, ba);
                bh[np*2][0]=r[0]; bh[np*2+1][0]=r[1]; bh[np*2][1]=r[2]; bh[np*2+1][1]=r[3];
            }
            #pragma unroll
            for (int mt = 0; mt < 4; mt++) {
                uint32_t aa = bufb + (uint32_t)((wm*64 + mt*16)*ASTRIDE)*2 + kB + fofsG;
                uint32_t ah[4];
                ldsm4(ah, aa);
                #pragma unroll
                for (int nt = 0; nt < 4; nt++)
                    mma16816(c[mt][nt], ah, bh[nt]);
            }
        }
        __syncthreads();
    }

    #pragma unroll
    for (int mt = 0; mt < 4; mt++) {
        #pragma unroll
        for (int half = 0; half < 2; half++) {
            int m = m0 + wm*64 + mt*16 + g + half*8;
            #pragma unroll
            for (int nt = 0; nt < 4; nt++) {
                int gc = col0 + wn*32 + nt*8 + t2;
                float* dst = g_y + (size_t)m*DIM + gc;
                dst[0] = c[mt][nt][half*2 + 0] + __ldg(bo + gc);
                dst[1] = c[mt][nt][half*2 + 1] + __ldg(bo + gc + 1);
            }
        }
    }
}

// ============================================================
// Kernel 4: LayerNorm + ls_scale + transpose
// ============================================================
__global__ void ln_kernel(const float* __restrict__ ln_g,
                          const float* __restrict__ ln_b,
                          const float* __restrict__ ls,
                          float* __restrict__ out)
{
    __shared__ float red[8];
    const int m = blockIdx.x;
    const int b = m >> 11, n = m & 2047;
    const int tid = threadIdx.x;
    float4 v = ((const float4*)(g_y + (size_t)m*DIM))[tid];
    float s  = v.x + v.y + v.z + v.w;
    float sq = v.x*v.x + v.y*v.y + v.z*v.z + v.w*v.w;
    #pragma unroll
    for (int off = 16; off > 0; off >>= 1) {
        s  += __shfl_xor_sync(0xffffffffu, s,  off);
        sq += __shfl_xor_sync(0xffffffffu, sq, off);
    }
    const int wid = tid >> 5;
    if ((tid & 31) == 0) { red[wid] = s; red[wid + 4] = sq; }
    __syncthreads();
    s  = red[0] + red[1] + red[2] + red[3];
    sq = red[4] + red[5] + red[6] + red[7];
    float mu  = s * (1.f/DIM);
    float var = sq * (1.f/DIM) - mu*mu;
    float r   = rsqrtf(var + 1e-5f);

    float* dst = out + (size_t)(n*NB + b)*DIM;
    const int d0 = tid * 4;
    float vv[4] = {v.x, v.y, v.z, v.w};
    #pragma unroll
    for (int q = 0; q < 4; q++) {
        int d = d0 + q;
        dst[d] = ls[d] * ((vv[q] - mu) * r * ln_g[d] + ln_b[d]);
    }
}

// ============================================================
extern "C" void kernel_launch(void* const* d_in, const int* in_sizes, int n_in,
                              void* d_out, int out_size)
{
    const float* x    = (const float*)d_in[0];
    const float* rope = (const float*)d_in[1];
    const float* Wq   = (const float*)d_in[2];
    const float* Wk   = (const float*)d_in[3];
    const float* Wv   = (const float*)d_in[4];
    const float* Wo   = (const float*)d_in[5];
    const float* bo   = (const float*)d_in[6];
    const float* ln_g = (const float*)d_in[7];
    const float* ln_b = (const float*)d_in[8];
    const float* hsc  = (const float*)d_in[9];
    const float* ls   = (const float*)d_in[10];
    float* out = (float*)d_out;

    static bool attr_done = false;
    if (!attr_done) {
        cudaFuncSetAttribute(qkv_mma,     cudaFuncAttributeMaxDynamicSharedMemorySize, 2*2*TS*2);
        cudaFuncSetAttribute(outproj_mma, cudaFuncAttributeMaxDynamicSharedMemorySize, 2*2*TS*2);
        cudaFuncSetAttribute(attn_mma,    cudaFuncAttributeMaxDynamicSharedMemorySize, 2*2*AS*2);
        attr_done = true;
    }

    prep_kernel<<<7168, 256>>>(x, Wq, Wk, Wv, Wo, rope);
    qkv_mma<<<dim3(MROWS/128, 12), 256, 2*2*TS*2>>>();
    attn_mma<<<dim3(NB*HEADS, NSEQ/128), 256, 2*2*AS*2>>>(hsc);
    outproj_mma<<<dim3(MROWS/128, 4), 256, 2*2*TS*2>>>(bo);
    ln_kernel<<<MROWS, 128>>>(ln_g, ln_b, ls, out);
}